// round 1
// baseline (speedup 1.0000x reference)
#include <cuda_runtime.h>

#define Nn 50000
#define Ee 800000
#define ET (Ee + Nn)   // 850000 edges incl. self loops
#define INC 256
#define HC 256         // H*C layer1 output width
#define NH 4
#define OC 40

// ---------------- scratch (device globals; no allocation allowed) ----------
__device__ float g_h1[Nn * HC];        // x @ W1
__device__ float g_als1[Nn * NH];
__device__ float g_ald1[Nn * NH];
__device__ float g_m1[Nn * NH];
__device__ float g_den1[Nn * NH];
__device__ float g_ee1[ET * NH];       // edge logits -> exp(e - m)
__device__ float g_agg1[Nn * HC];      // layer-1 aggregation (then relu'ed in place)
__device__ float g_h2[Nn * OC];        // relu(agg1+b1) @ W2
__device__ float g_als2[Nn];
__device__ float g_ald2[Nn];
__device__ float g_m2[Nn];
__device__ float g_den2[Nn];
__device__ float g_ee2[ET];
__device__ float g_agg2[Nn * OC];

// ---------------- helpers ---------------------------------------------------
__device__ __forceinline__ void atomicMaxF(float* addr, float v) {
    // works because init is -FLT_MAX (negative bit pattern)
    if (v >= 0.f) atomicMax((int*)addr, __float_as_int(v));
    else          atomicMin((unsigned int*)addr, (unsigned int)__float_as_int(v));
}

__device__ __forceinline__ void edge_sd(const int* __restrict__ ei, int e, int& s, int& d) {
    if (e < Ee) { s = ei[e]; d = ei[Ee + e]; }
    else        { s = e - Ee; d = s; }
}

// ---------------- init ------------------------------------------------------
__global__ void init_kernel() {
    int i = blockIdx.x * blockDim.x + threadIdx.x;
    int stride = gridDim.x * blockDim.x;
    for (int j = i; j < Nn * HC; j += stride) g_agg1[j] = 0.f;
    for (int j = i; j < Nn * OC; j += stride) g_agg2[j] = 0.f;
    for (int j = i; j < Nn * NH; j += stride) { g_den1[j] = 0.f; g_m1[j] = -3.402823466e38f; }
    for (int j = i; j < Nn;      j += stride) { g_den2[j] = 0.f; g_m2[j] = -3.402823466e38f; }
}

// ---------------- GEMM1: h1 = x @ W1   [50000,256] x [256,256] --------------
// 64x64 tile, 256 threads, 4x4 per thread, BK=16, float4 smem reads.
__global__ __launch_bounds__(256) void gemm1_kernel(const float* __restrict__ X,
                                                    const float* __restrict__ W) {
    __shared__ float As[16][68];  // [k][m], pad 4 keeps float4 alignment
    __shared__ float Bs[16][68];  // [k][n]
    const int bm = blockIdx.y * 64;
    const int bn = blockIdx.x * 64;
    const int tid = threadIdx.x;
    const int tx = tid & 15;       // 0..15 -> n groups of 4
    const int ty = tid >> 4;       // 0..15 -> m groups of 4
    float acc[4][4] = {};

    for (int k0 = 0; k0 < INC; k0 += 16) {
        #pragma unroll
        for (int i = 0; i < 4; i++) {
            int r = (tid >> 4) + i * 16;      // 0..63
            int c = tid & 15;                 // 0..15
            int row = bm + r;
            As[c][r] = (row < Nn) ? X[row * INC + k0 + c] : 0.f;
        }
        #pragma unroll
        for (int i = 0; i < 4; i++) {
            int r = (tid >> 6) + i * 4;       // 0..15
            int c = tid & 63;                 // 0..63
            Bs[r][c] = W[(k0 + r) * HC + bn + c];
        }
        __syncthreads();
        #pragma unroll
        for (int k = 0; k < 16; k++) {
            float4 a = *(const float4*)&As[k][ty * 4];
            float4 b = *(const float4*)&Bs[k][tx * 4];
            acc[0][0] += a.x * b.x; acc[0][1] += a.x * b.y; acc[0][2] += a.x * b.z; acc[0][3] += a.x * b.w;
            acc[1][0] += a.y * b.x; acc[1][1] += a.y * b.y; acc[1][2] += a.y * b.z; acc[1][3] += a.y * b.w;
            acc[2][0] += a.z * b.x; acc[2][1] += a.z * b.y; acc[2][2] += a.z * b.z; acc[2][3] += a.z * b.w;
            acc[3][0] += a.w * b.x; acc[3][1] += a.w * b.y; acc[3][2] += a.w * b.z; acc[3][3] += a.w * b.w;
        }
        __syncthreads();
    }
    #pragma unroll
    for (int i = 0; i < 4; i++) {
        int row = bm + ty * 4 + i;
        if (row < Nn) {
            float4 v = make_float4(acc[i][0], acc[i][1], acc[i][2], acc[i][3]);
            *(float4*)&g_h1[row * HC + bn + tx * 4] = v;
        }
    }
}

// ---------------- attention coefficients layer 1 -----------------------------
// warp per node; lane l handles channels [8l, 8l+8) -> head = l/8
__global__ void attn_coef1(const float* __restrict__ a_src, const float* __restrict__ a_dst) {
    int n = blockIdx.x * 8 + (threadIdx.x >> 5);
    if (n >= Nn) return;
    int lane = threadIdx.x & 31;
    const float4* hp = (const float4*)(g_h1 + n * HC);
    float4 v0 = hp[lane * 2], v1 = hp[lane * 2 + 1];
    const float4* sp = (const float4*)a_src;
    const float4* dp = (const float4*)a_dst;
    float4 s0 = sp[lane * 2], s1 = sp[lane * 2 + 1];
    float4 d0 = dp[lane * 2], d1 = dp[lane * 2 + 1];
    float ps = v0.x*s0.x + v0.y*s0.y + v0.z*s0.z + v0.w*s0.w
             + v1.x*s1.x + v1.y*s1.y + v1.z*s1.z + v1.w*s1.w;
    float pd = v0.x*d0.x + v0.y*d0.y + v0.z*d0.z + v0.w*d0.w
             + v1.x*d1.x + v1.y*d1.y + v1.z*d1.z + v1.w*d1.w;
    #pragma unroll
    for (int off = 4; off; off >>= 1) {
        ps += __shfl_down_sync(0xffffffffu, ps, off);
        pd += __shfl_down_sync(0xffffffffu, pd, off);
    }
    if ((lane & 7) == 0) {
        int h = lane >> 3;
        g_als1[n * NH + h] = ps;
        g_ald1[n * NH + h] = pd;
    }
}

// ---------------- edge logits + segment max, layer 1 -------------------------
__global__ void edge_logits1(const int* __restrict__ ei) {
    int e = blockIdx.x * blockDim.x + threadIdx.x;
    if (e >= ET) return;
    int s, d; edge_sd(ei, e, s, d);
    #pragma unroll
    for (int h = 0; h < NH; h++) {
        float v = g_als1[s * NH + h] + g_ald1[d * NH + h];
        v = (v > 0.f) ? v : 0.2f * v;
        g_ee1[e * NH + h] = v;
        atomicMaxF(&g_m1[d * NH + h], v);
    }
}

__global__ void edge_exp1(const int* __restrict__ ei) {
    int e = blockIdx.x * blockDim.x + threadIdx.x;
    if (e >= ET) return;
    int s, d; edge_sd(ei, e, s, d);
    (void)s;
    #pragma unroll
    for (int h = 0; h < NH; h++) {
        float ee = expf(g_ee1[e * NH + h] - g_m1[d * NH + h]);
        g_ee1[e * NH + h] = ee;
        atomicAdd(&g_den1[d * NH + h], ee);
    }
}

// ---------------- scatter layer 1: agg1[dst] += alpha * h1[src] -------------
// one block (256 threads) per edge; 256 channels
__global__ __launch_bounds__(256) void scatter1(const int* __restrict__ ei) {
    int e = blockIdx.x;
    __shared__ int ss, sd;
    __shared__ float sal[NH];
    if (threadIdx.x < NH) {
        int s, d; edge_sd(ei, e, s, d);
        if (threadIdx.x == 0) { ss = s; sd = d; }
        sal[threadIdx.x] = g_ee1[e * NH + threadIdx.x] /
                           (g_den1[d * NH + threadIdx.x] + 1e-16f);
    }
    __syncthreads();
    int ch = threadIdx.x;
    float val = sal[ch >> 6] * g_h1[ss * HC + ch];
    atomicAdd(&g_agg1[sd * HC + ch], val);
}

// ---------------- relu(agg1 + b1) in place -----------------------------------
__global__ void relu_bias(const float* __restrict__ b1) {
    int i = blockIdx.x * blockDim.x + threadIdx.x;
    if (i >= Nn * HC) return;
    float v = g_agg1[i] + b1[i & (HC - 1)];
    g_agg1[i] = (v > 0.f) ? v : 0.f;
}

// ---------------- GEMM2: h2 = relu(agg1) @ W2   [50000,256] x [256,40] -------
__global__ __launch_bounds__(320) void gemm2_kernel(const float* __restrict__ W2) {
    __shared__ float W2s[INC * OC];  // 40 KB
    int tid = threadIdx.y * 40 + threadIdx.x;
    for (int i = tid; i < INC * OC; i += 320) W2s[i] = W2[i];
    __syncthreads();
    int o = threadIdx.x;
    #pragma unroll
    for (int r = 0; r < 8; r++) {
        int row = blockIdx.x * 64 + r * 8 + threadIdx.y;
        if (row >= Nn) continue;
        const float4* xp = (const float4*)(g_agg1 + row * INC);
        float acc = 0.f;
        #pragma unroll 8
        for (int k4 = 0; k4 < 64; k4++) {
            float4 xv = xp[k4];
            int kb = k4 * 4 * OC;
            acc = fmaf(xv.x, W2s[kb + o], acc);
            acc = fmaf(xv.y, W2s[kb + OC + o], acc);
            acc = fmaf(xv.z, W2s[kb + 2 * OC + o], acc);
            acc = fmaf(xv.w, W2s[kb + 3 * OC + o], acc);
        }
        g_h2[row * OC + o] = acc;
    }
}

// ---------------- attention coefficients layer 2 (H=1, C=40) -----------------
__global__ void attn_coef2(const float* __restrict__ a_src, const float* __restrict__ a_dst) {
    int n = blockIdx.x * 8 + (threadIdx.x >> 5);
    if (n >= Nn) return;
    int lane = threadIdx.x & 31;
    float v0 = g_h2[n * OC + lane];
    float s = v0 * a_src[lane];
    float d = v0 * a_dst[lane];
    if (lane < 8) {
        float v1 = g_h2[n * OC + 32 + lane];
        s += v1 * a_src[32 + lane];
        d += v1 * a_dst[32 + lane];
    }
    #pragma unroll
    for (int off = 16; off; off >>= 1) {
        s += __shfl_down_sync(0xffffffffu, s, off);
        d += __shfl_down_sync(0xffffffffu, d, off);
    }
    if (lane == 0) { g_als2[n] = s; g_ald2[n] = d; }
}

__global__ void edge_logits2(const int* __restrict__ ei) {
    int e = blockIdx.x * blockDim.x + threadIdx.x;
    if (e >= ET) return;
    int s, d; edge_sd(ei, e, s, d);
    float v = g_als2[s] + g_ald2[d];
    v = (v > 0.f) ? v : 0.2f * v;
    g_ee2[e] = v;
    atomicMaxF(&g_m2[d], v);
}

__global__ void edge_exp2(const int* __restrict__ ei) {
    int e = blockIdx.x * blockDim.x + threadIdx.x;
    if (e >= ET) return;
    int s, d; edge_sd(ei, e, s, d);
    (void)s;
    float ee = expf(g_ee2[e] - g_m2[d]);
    g_ee2[e] = ee;
    atomicAdd(&g_den2[d], ee);
}

__global__ void scatter2(const int* __restrict__ ei) {
    long long idx = (long long)blockIdx.x * blockDim.x + threadIdx.x;
    if (idx >= (long long)ET * OC) return;
    int e = (int)(idx / OC);
    int ch = (int)(idx - (long long)e * OC);
    int s, d; edge_sd(ei, e, s, d);
    float alpha = g_ee2[e] / (g_den2[d] + 1e-16f);
    atomicAdd(&g_agg2[d * OC + ch], alpha * g_h2[s * OC + ch]);
}

// ---------------- finalize: out = log_softmax(agg2 + b2) ---------------------
__global__ void finalize(const float* __restrict__ b2, float* __restrict__ out) {
    int n = blockIdx.x * 8 + (threadIdx.x >> 5);
    if (n >= Nn) return;
    int lane = threadIdx.x & 31;
    float v0 = g_agg2[n * OC + lane] + b2[lane];
    float v1 = (lane < 8) ? (g_agg2[n * OC + 32 + lane] + b2[32 + lane])
                          : -3.402823466e38f;
    float mx = fmaxf(v0, v1);
    #pragma unroll
    for (int off = 16; off; off >>= 1)
        mx = fmaxf(mx, __shfl_xor_sync(0xffffffffu, mx, off));
    float se = expf(v0 - mx) + ((lane < 8) ? expf(v1 - mx) : 0.f);
    #pragma unroll
    for (int off = 16; off; off >>= 1)
        se += __shfl_xor_sync(0xffffffffu, se, off);
    float lse = mx + logf(se);
    out[n * OC + lane] = v0 - lse;
    if (lane < 8) out[n * OC + 32 + lane] = v1 - lse;
}

// ---------------- launch -----------------------------------------------------
extern "C" void kernel_launch(void* const* d_in, const int* in_sizes, int n_in,
                              void* d_out, int out_size) {
    const float* x      = (const float*)d_in[0];
    const int*   ei     = (const int*)d_in[1];
    const float* W1     = (const float*)d_in[2];
    const float* a_src1 = (const float*)d_in[3];
    const float* a_dst1 = (const float*)d_in[4];
    const float* b1     = (const float*)d_in[5];
    const float* W2     = (const float*)d_in[6];
    const float* a_src2 = (const float*)d_in[7];
    const float* a_dst2 = (const float*)d_in[8];
    const float* b2     = (const float*)d_in[9];
    float* out = (float*)d_out;

    init_kernel<<<2048, 256>>>();

    dim3 g1grid(HC / 64, (Nn + 63) / 64);
    gemm1_kernel<<<g1grid, 256>>>(x, W1);

    attn_coef1<<<(Nn + 7) / 8, 256>>>(a_src1, a_dst1);

    int eblocks = (ET + 255) / 256;
    edge_logits1<<<eblocks, 256>>>(ei);
    edge_exp1<<<eblocks, 256>>>(ei);
    scatter1<<<ET, 256>>>(ei);

    relu_bias<<<(Nn * HC + 255) / 256, 256>>>(b1);

    gemm2_kernel<<<(Nn + 63) / 64, dim3(40, 8)>>>(W2);

    attn_coef2<<<(Nn + 7) / 8, 256>>>(a_src2, a_dst2);
    edge_logits2<<<eblocks, 256>>>(ei);
    edge_exp2<<<eblocks, 256>>>(ei);

    long long s2total = (long long)ET * OC;
    int s2blocks = (int)((s2total + 255) / 256);
    scatter2<<<s2blocks, 256>>>(ei);

    finalize<<<(Nn + 7) / 8, 256>>>(b2, out);
}

// round 2
// speedup vs baseline: 2.2215x; 2.2215x over previous
#include <cuda_runtime.h>

#define Nn 50000
#define Ee 800000
#define ET (Ee + Nn)   // 850000 edges incl. self loops
#define INC 256
#define HC 256         // H*C layer1 output width
#define NH 4
#define OC 40

// ---------------- scratch (device globals; no allocation allowed) ----------
__device__ float g_h1[Nn * HC];        // x @ W1
__device__ float g_als1[Nn * NH];
__device__ float g_ald1[Nn * NH];
__device__ float g_agg1[Nn * HC];      // layer-1 aggregation
__device__ float g_h2[Nn * OC];        // relu(agg1+b1) @ W2
__device__ float g_als2[Nn];
__device__ float g_ald2[Nn];
__device__ float g_agg2[Nn * OC];
// CSR scratch
__device__ int g_counts[Nn];
__device__ int g_fill[Nn];
__device__ int g_rowptr[Nn + 1];
__device__ int g_srcl[ET];

// ---------------- helpers ---------------------------------------------------
__device__ __forceinline__ void edge_sd(const int* __restrict__ ei, int e, int& s, int& d) {
    if (e < Ee) { s = ei[e]; d = ei[Ee + e]; }
    else        { s = e - Ee; d = s; }
}

__device__ __forceinline__ float lrelu(float v) { return (v > 0.f) ? v : 0.2f * v; }

// ---------------- init: zero CSR counters ------------------------------------
__global__ void init_kernel() {
    int i = blockIdx.x * blockDim.x + threadIdx.x;
    if (i < Nn) { g_counts[i] = 0; g_fill[i] = 0; }
}

// ---------------- CSR build ---------------------------------------------------
__global__ void hist_kernel(const int* __restrict__ ei) {
    int e = blockIdx.x * blockDim.x + threadIdx.x;
    if (e >= ET) return;
    int d = (e < Ee) ? ei[Ee + e] : (e - Ee);
    atomicAdd(&g_counts[d], 1);
}

__global__ void scan_kernel() {   // single block, 1024 threads
    __shared__ int sm[1024];
    __shared__ int s_off;
    int t = threadIdx.x;
    if (t == 0) { s_off = 0; g_rowptr[0] = 0; }
    __syncthreads();
    const int CH = (Nn + 1023) / 1024;
    for (int c = 0; c < CH; c++) {
        int idx = c * 1024 + t;
        int v = (idx < Nn) ? g_counts[idx] : 0;
        sm[t] = v;
        __syncthreads();
        #pragma unroll
        for (int s = 1; s < 1024; s <<= 1) {
            int add = (t >= s) ? sm[t - s] : 0;
            __syncthreads();
            sm[t] += add;
            __syncthreads();
        }
        int incl = sm[t] + s_off;
        if (idx < Nn) g_rowptr[idx + 1] = incl;
        __syncthreads();
        if (t == 1023) s_off = incl;
        __syncthreads();
    }
}

__global__ void fill_kernel(const int* __restrict__ ei) {
    int e = blockIdx.x * blockDim.x + threadIdx.x;
    if (e >= ET) return;
    int s, d; edge_sd(ei, e, s, d);
    int pos = g_rowptr[d] + atomicAdd(&g_fill[d], 1);
    g_srcl[pos] = s;
}

// ---------------- GEMM1: h1 = x @ W1   [50000,256] x [256,256] --------------
__global__ __launch_bounds__(256) void gemm1_kernel(const float* __restrict__ X,
                                                    const float* __restrict__ W) {
    __shared__ float As[16][68];
    __shared__ float Bs[16][68];
    const int bm = blockIdx.y * 64;
    const int bn = blockIdx.x * 64;
    const int tid = threadIdx.x;
    const int tx = tid & 15;
    const int ty = tid >> 4;
    float acc[4][4] = {};

    for (int k0 = 0; k0 < INC; k0 += 16) {
        #pragma unroll
        for (int i = 0; i < 4; i++) {
            int r = (tid >> 4) + i * 16;
            int c = tid & 15;
            int row = bm + r;
            As[c][r] = (row < Nn) ? X[row * INC + k0 + c] : 0.f;
        }
        #pragma unroll
        for (int i = 0; i < 4; i++) {
            int r = (tid >> 6) + i * 4;
            int c = tid & 63;
            Bs[r][c] = W[(k0 + r) * HC + bn + c];
        }
        __syncthreads();
        #pragma unroll
        for (int k = 0; k < 16; k++) {
            float4 a = *(const float4*)&As[k][ty * 4];
            float4 b = *(const float4*)&Bs[k][tx * 4];
            acc[0][0] += a.x * b.x; acc[0][1] += a.x * b.y; acc[0][2] += a.x * b.z; acc[0][3] += a.x * b.w;
            acc[1][0] += a.y * b.x; acc[1][1] += a.y * b.y; acc[1][2] += a.y * b.z; acc[1][3] += a.y * b.w;
            acc[2][0] += a.z * b.x; acc[2][1] += a.z * b.y; acc[2][2] += a.z * b.z; acc[2][3] += a.z * b.w;
            acc[3][0] += a.w * b.x; acc[3][1] += a.w * b.y; acc[3][2] += a.w * b.z; acc[3][3] += a.w * b.w;
        }
        __syncthreads();
    }
    #pragma unroll
    for (int i = 0; i < 4; i++) {
        int row = bm + ty * 4 + i;
        if (row < Nn) {
            float4 v = make_float4(acc[i][0], acc[i][1], acc[i][2], acc[i][3]);
            *(float4*)&g_h1[row * HC + bn + tx * 4] = v;
        }
    }
}

// ---------------- attention coefficients layer 1 -----------------------------
__global__ void attn_coef1(const float* __restrict__ a_src, const float* __restrict__ a_dst) {
    int n = blockIdx.x * 8 + (threadIdx.x >> 5);
    if (n >= Nn) return;
    int lane = threadIdx.x & 31;
    const float4* hp = (const float4*)(g_h1 + n * HC);
    float4 v0 = hp[lane * 2], v1 = hp[lane * 2 + 1];
    const float4* sp = (const float4*)a_src;
    const float4* dp = (const float4*)a_dst;
    float4 s0 = sp[lane * 2], s1 = sp[lane * 2 + 1];
    float4 d0 = dp[lane * 2], d1 = dp[lane * 2 + 1];
    float ps = v0.x*s0.x + v0.y*s0.y + v0.z*s0.z + v0.w*s0.w
             + v1.x*s1.x + v1.y*s1.y + v1.z*s1.z + v1.w*s1.w;
    float pd = v0.x*d0.x + v0.y*d0.y + v0.z*d0.z + v0.w*d0.w
             + v1.x*d1.x + v1.y*d1.y + v1.z*d1.z + v1.w*d1.w;
    #pragma unroll
    for (int off = 4; off; off >>= 1) {
        ps += __shfl_down_sync(0xffffffffu, ps, off);
        pd += __shfl_down_sync(0xffffffffu, pd, off);
    }
    if ((lane & 7) == 0) {
        int h = lane >> 3;
        g_als1[n * NH + h] = ps;
        g_ald1[n * NH + h] = pd;
    }
}

// ---------------- layer 1 fused softmax + aggregation ------------------------
// one 256-thread block per destination node; channels = threads
__global__ __launch_bounds__(256) void agg1_kernel() {
    int d = blockIdx.x;
    int start = g_rowptr[d], end = g_rowptr[d + 1];
    int tid = threadIdx.x;
    __shared__ float sden[NH];
    __shared__ int ssrc[128];
    __shared__ float salpha[128 * NH];

    float4 aldv = *(const float4*)&g_ald1[d * NH];

    // phase A: denominators per head (no max: logits are O(1))
    float p0 = 0.f, p1 = 0.f, p2 = 0.f, p3 = 0.f;
    for (int i = start + tid; i < end; i += 256) {
        int s = g_srcl[i];
        float4 als = *(const float4*)&g_als1[s * NH];
        p0 += __expf(lrelu(als.x + aldv.x));
        p1 += __expf(lrelu(als.y + aldv.y));
        p2 += __expf(lrelu(als.z + aldv.z));
        p3 += __expf(lrelu(als.w + aldv.w));
    }
    #pragma unroll
    for (int off = 16; off; off >>= 1) {
        p0 += __shfl_down_sync(0xffffffffu, p0, off);
        p1 += __shfl_down_sync(0xffffffffu, p1, off);
        p2 += __shfl_down_sync(0xffffffffu, p2, off);
        p3 += __shfl_down_sync(0xffffffffu, p3, off);
    }
    if (tid < NH) sden[tid] = 1e-16f;
    __syncthreads();
    if ((tid & 31) == 0) {
        atomicAdd(&sden[0], p0);
        atomicAdd(&sden[1], p1);
        atomicAdd(&sden[2], p2);
        atomicAdd(&sden[3], p3);
    }
    __syncthreads();
    float rd0 = 1.f / sden[0], rd1 = 1.f / sden[1], rd2 = 1.f / sden[2], rd3 = 1.f / sden[3];

    // phase B: accumulate alpha * h1[src]
    int ch = tid, head = tid >> 6;
    float acc = 0.f;
    for (int base = start; base < end; base += 128) {
        int cnt = min(128, end - base);
        if (tid < cnt) {
            int s = g_srcl[base + tid];
            ssrc[tid] = s;
            float4 als = *(const float4*)&g_als1[s * NH];
            salpha[tid * 4 + 0] = __expf(lrelu(als.x + aldv.x)) * rd0;
            salpha[tid * 4 + 1] = __expf(lrelu(als.y + aldv.y)) * rd1;
            salpha[tid * 4 + 2] = __expf(lrelu(als.z + aldv.z)) * rd2;
            salpha[tid * 4 + 3] = __expf(lrelu(als.w + aldv.w)) * rd3;
        }
        __syncthreads();
        int j = 0;
        for (; j + 4 <= cnt; j += 4) {
            float a0 = salpha[(j + 0) * 4 + head];
            float a1 = salpha[(j + 1) * 4 + head];
            float a2 = salpha[(j + 2) * 4 + head];
            float a3 = salpha[(j + 3) * 4 + head];
            int s0 = ssrc[j], s1 = ssrc[j + 1], s2 = ssrc[j + 2], s3 = ssrc[j + 3];
            float h0 = g_h1[s0 * HC + ch];
            float h1v = g_h1[s1 * HC + ch];
            float h2v = g_h1[s2 * HC + ch];
            float h3 = g_h1[s3 * HC + ch];
            acc = fmaf(a0, h0, acc);
            acc = fmaf(a1, h1v, acc);
            acc = fmaf(a2, h2v, acc);
            acc = fmaf(a3, h3, acc);
        }
        for (; j < cnt; j++)
            acc = fmaf(salpha[j * 4 + head], g_h1[ssrc[j] * HC + ch], acc);
        __syncthreads();
    }
    g_agg1[d * HC + ch] = acc;
}

// ---------------- relu(agg1 + b1) in place -----------------------------------
__global__ void relu_bias(const float* __restrict__ b1) {
    int i = blockIdx.x * blockDim.x + threadIdx.x;
    if (i >= Nn * HC) return;
    float v = g_agg1[i] + b1[i & (HC - 1)];
    g_agg1[i] = (v > 0.f) ? v : 0.f;
}

// ---------------- GEMM2: h2 = relu(agg1) @ W2   [50000,256] x [256,40] -------
__global__ __launch_bounds__(320) void gemm2_kernel(const float* __restrict__ W2) {
    __shared__ float W2s[INC * OC];  // 40 KB
    int tid = threadIdx.y * 40 + threadIdx.x;
    for (int i = tid; i < INC * OC; i += 320) W2s[i] = W2[i];
    __syncthreads();
    int o = threadIdx.x;
    #pragma unroll
    for (int r = 0; r < 8; r++) {
        int row = blockIdx.x * 64 + r * 8 + threadIdx.y;
        if (row >= Nn) continue;
        const float4* xp = (const float4*)(g_agg1 + row * INC);
        float acc = 0.f;
        #pragma unroll 8
        for (int k4 = 0; k4 < 64; k4++) {
            float4 xv = xp[k4];
            int kb = k4 * 4 * OC;
            acc = fmaf(xv.x, W2s[kb + o], acc);
            acc = fmaf(xv.y, W2s[kb + OC + o], acc);
            acc = fmaf(xv.z, W2s[kb + 2 * OC + o], acc);
            acc = fmaf(xv.w, W2s[kb + 3 * OC + o], acc);
        }
        g_h2[row * OC + o] = acc;
    }
}

// ---------------- attention coefficients layer 2 (H=1, C=40) -----------------
__global__ void attn_coef2(const float* __restrict__ a_src, const float* __restrict__ a_dst) {
    int n = blockIdx.x * 8 + (threadIdx.x >> 5);
    if (n >= Nn) return;
    int lane = threadIdx.x & 31;
    float v0 = g_h2[n * OC + lane];
    float s = v0 * a_src[lane];
    float d = v0 * a_dst[lane];
    if (lane < 8) {
        float v1 = g_h2[n * OC + 32 + lane];
        s += v1 * a_src[32 + lane];
        d += v1 * a_dst[32 + lane];
    }
    #pragma unroll
    for (int off = 16; off; off >>= 1) {
        s += __shfl_down_sync(0xffffffffu, s, off);
        d += __shfl_down_sync(0xffffffffu, d, off);
    }
    if (lane == 0) { g_als2[n] = s; g_ald2[n] = d; }
}

// ---------------- layer 2 fused softmax + aggregation ------------------------
// one warp per destination node
__global__ void agg2_kernel() {
    int n = blockIdx.x * 8 + (threadIdx.x >> 5);
    if (n >= Nn) return;
    int lane = threadIdx.x & 31;
    int start = g_rowptr[n], end = g_rowptr[n + 1];
    float ald = g_ald2[n];

    float den = 0.f;
    for (int i = start + lane; i < end; i += 32)
        den += __expf(lrelu(g_als2[g_srcl[i]] + ald));
    #pragma unroll
    for (int off = 16; off; off >>= 1)
        den += __shfl_xor_sync(0xffffffffu, den, off);
    float rden = 1.f / (den + 1e-16f);

    float acc0 = 0.f, acc1 = 0.f;
    for (int base = start; base < end; base += 32) {
        int i = base + lane;
        int s = 0; float a = 0.f;
        if (i < end) {
            s = g_srcl[i];
            a = __expf(lrelu(g_als2[s] + ald)) * rden;
        }
        int cnt = min(32, end - base);
        for (int j = 0; j < cnt; j++) {
            int   sj = __shfl_sync(0xffffffffu, s, j);
            float aj = __shfl_sync(0xffffffffu, a, j);
            acc0 = fmaf(aj, g_h2[sj * OC + lane], acc0);
            if (lane < 8) acc1 = fmaf(aj, g_h2[sj * OC + 32 + lane], acc1);
        }
    }
    g_agg2[n * OC + lane] = acc0;
    if (lane < 8) g_agg2[n * OC + 32 + lane] = acc1;
}

// ---------------- finalize: out = log_softmax(agg2 + b2) ---------------------
__global__ void finalize(const float* __restrict__ b2, float* __restrict__ out) {
    int n = blockIdx.x * 8 + (threadIdx.x >> 5);
    if (n >= Nn) return;
    int lane = threadIdx.x & 31;
    float v0 = g_agg2[n * OC + lane] + b2[lane];
    float v1 = (lane < 8) ? (g_agg2[n * OC + 32 + lane] + b2[32 + lane])
                          : -3.402823466e38f;
    float mx = fmaxf(v0, v1);
    #pragma unroll
    for (int off = 16; off; off >>= 1)
        mx = fmaxf(mx, __shfl_xor_sync(0xffffffffu, mx, off));
    float se = expf(v0 - mx) + ((lane < 8) ? expf(v1 - mx) : 0.f);
    #pragma unroll
    for (int off = 16; off; off >>= 1)
        se += __shfl_xor_sync(0xffffffffu, se, off);
    float lse = mx + logf(se);
    out[n * OC + lane] = v0 - lse;
    if (lane < 8) out[n * OC + 32 + lane] = v1 - lse;
}

// ---------------- launch -----------------------------------------------------
extern "C" void kernel_launch(void* const* d_in, const int* in_sizes, int n_in,
                              void* d_out, int out_size) {
    const float* x      = (const float*)d_in[0];
    const int*   ei     = (const int*)d_in[1];
    const float* W1     = (const float*)d_in[2];
    const float* a_src1 = (const float*)d_in[3];
    const float* a_dst1 = (const float*)d_in[4];
    const float* b1     = (const float*)d_in[5];
    const float* W2     = (const float*)d_in[6];
    const float* a_src2 = (const float*)d_in[7];
    const float* a_dst2 = (const float*)d_in[8];
    const float* b2     = (const float*)d_in[9];
    float* out = (float*)d_out;

    int eblocks = (ET + 255) / 256;

    init_kernel<<<(Nn + 255) / 256, 256>>>();
    hist_kernel<<<eblocks, 256>>>(ei);
    scan_kernel<<<1, 1024>>>();
    fill_kernel<<<eblocks, 256>>>(ei);

    dim3 g1grid(HC / 64, (Nn + 63) / 64);
    gemm1_kernel<<<g1grid, 256>>>(x, W1);
    attn_coef1<<<(Nn + 7) / 8, 256>>>(a_src1, a_dst1);

    agg1_kernel<<<Nn, 256>>>();

    relu_bias<<<(Nn * HC + 255) / 256, 256>>>(b1);
    gemm2_kernel<<<(Nn + 63) / 64, dim3(40, 8)>>>(W2);

    attn_coef2<<<(Nn + 7) / 8, 256>>>(a_src2, a_dst2);
    agg2_kernel<<<(Nn + 7) / 8, 256>>>();

    finalize<<<(Nn + 7) / 8, 256>>>(b2, out);
}

// round 4
// speedup vs baseline: 2.6337x; 1.1856x over previous
#include <cuda_runtime.h>
#include <cuda_bf16.h>
#include <cstdint>

#define Nn 50000
#define Ee 800000
#define ET (Ee + Nn)   // 850000 edges incl. self loops
#define INC 256
#define HC 256         // H*C layer1 output width
#define NH 4
#define OC 40

#define MT 128
#define MTILES ((Nn + MT - 1) / MT)    // 391
#define PADN (MTILES * MT)             // 50048

// ---------------- scratch (device globals; no allocation allowed) ----------
__device__ float g_h1[Nn * HC];        // x @ W1
__device__ float g_als1[Nn * NH];
__device__ float g_ald1[Nn * NH];
__device__ float g_agg1[Nn * HC];      // layer-1 aggregation (bias+relu fused)
__device__ float g_h2[Nn * OC];
__device__ float g_als2[Nn];
__device__ float g_ald2[Nn];
__device__ float g_agg2[Nn * OC];
// CSR scratch
__device__ int g_counts[Nn];
__device__ int g_fill[Nn];
__device__ int g_rowptr[Nn + 1];
__device__ int g_srcl[ET];
// split-bf16 operands for tensor-core GEMM1
__device__ __align__(16) __nv_bfloat16 g_xh[(size_t)PADN * INC];
__device__ __align__(16) __nv_bfloat16 g_xl[(size_t)PADN * INC];
__device__ __align__(16) __nv_bfloat16 g_w1h[INC * HC];   // [n][k] K-major
__device__ __align__(16) __nv_bfloat16 g_w1l[INC * HC];

// ---------------- misc helpers -----------------------------------------------
__device__ __forceinline__ void edge_sd(const int* __restrict__ ei, int e, int& s, int& d) {
    if (e < Ee) { s = ei[e]; d = ei[Ee + e]; }
    else        { s = e - Ee; d = s; }
}
__device__ __forceinline__ float lrelu(float v) { return (v > 0.f) ? v : 0.2f * v; }

// ---------------- init / CSR build -------------------------------------------
__global__ void init_kernel() {
    int i = blockIdx.x * blockDim.x + threadIdx.x;
    if (i < Nn) { g_counts[i] = 0; g_fill[i] = 0; }
}
__global__ void hist_kernel(const int* __restrict__ ei) {
    int e = blockIdx.x * blockDim.x + threadIdx.x;
    if (e >= ET) return;
    int d = (e < Ee) ? ei[Ee + e] : (e - Ee);
    atomicAdd(&g_counts[d], 1);
}
__global__ void scan_kernel() {
    __shared__ int sm[1024];
    __shared__ int s_off;
    int t = threadIdx.x;
    if (t == 0) { s_off = 0; g_rowptr[0] = 0; }
    __syncthreads();
    const int CH = (Nn + 1023) / 1024;
    for (int c = 0; c < CH; c++) {
        int idx = c * 1024 + t;
        int v = (idx < Nn) ? g_counts[idx] : 0;
        sm[t] = v;
        __syncthreads();
        #pragma unroll
        for (int s = 1; s < 1024; s <<= 1) {
            int add = (t >= s) ? sm[t - s] : 0;
            __syncthreads();
            sm[t] += add;
            __syncthreads();
        }
        int incl = sm[t] + s_off;
        if (idx < Nn) g_rowptr[idx + 1] = incl;
        __syncthreads();
        if (t == 1023) s_off = incl;
        __syncthreads();
    }
}
__global__ void fill_kernel(const int* __restrict__ ei) {
    int e = blockIdx.x * blockDim.x + threadIdx.x;
    if (e >= ET) return;
    int s, d; edge_sd(ei, e, s, d);
    int pos = g_rowptr[d] + atomicAdd(&g_fill[d], 1);
    g_srcl[pos] = s;
}

// ---------------- convert: x -> (hi,lo) bf16, padded -------------------------
__global__ void convert_x(const float* __restrict__ X) {
    long i = (long)blockIdx.x * blockDim.x + threadIdx.x;      // vec-of-8 index
    const long NV = (long)PADN * INC / 8;
    if (i >= NV) return;
    long base = i * 8;
    __nv_bfloat16 h[8], l[8];
    if (base < (long)Nn * INC) {
        float4 f0 = ((const float4*)X)[i * 2];
        float4 f1 = ((const float4*)X)[i * 2 + 1];
        float v[8] = {f0.x, f0.y, f0.z, f0.w, f1.x, f1.y, f1.z, f1.w};
        #pragma unroll
        for (int j = 0; j < 8; j++) {
            h[j] = __float2bfloat16(v[j]);
            l[j] = __float2bfloat16(v[j] - __bfloat162float(h[j]));
        }
    } else {
        #pragma unroll
        for (int j = 0; j < 8; j++) { h[j] = __float2bfloat16(0.f); l[j] = h[j]; }
    }
    *(uint4*)(g_xh + base) = *(const uint4*)h;
    *(uint4*)(g_xl + base) = *(const uint4*)l;
}

// ---------------- convert: W1 [K][N] -> transposed split [N][K] ---------------
__global__ void convert_w(const float* __restrict__ W1) {
    int t = blockIdx.x * blockDim.x + threadIdx.x;
    if (t >= INC * HC) return;
    int k = t >> 8, n = t & 255;
    float v = W1[t];
    __nv_bfloat16 h = __float2bfloat16(v);
    __nv_bfloat16 l = __float2bfloat16(v - __bfloat162float(h));
    g_w1h[n * INC + k] = h;
    g_w1l[n * INC + k] = l;
}

// ---------------- GEMM1 via mma.sync (HMMA bf16, split hi/lo) -----------------
// CTA: 128(M) x 128(N), BK=64, 8 warps (2x4), warp tile 64x32.
// smem rows padded to 144B (72 bf16 / 36 words): word-stride % 32 == 4 ->
// fragment LDS pattern (4g + t) is bank-conflict-free.
#define LDW 36                     // smem row stride in 32-bit words
#define LDB 144                    // smem row stride in bytes
#define ATILE (128 * LDB)          // 18432 bytes per tile
#define GSM_TOTAL (4 * ATILE)      // Ah, Al, Bh, Bl = 73728 bytes

__device__ __forceinline__ void mma_bf16(float* c, const uint32_t* a, const uint32_t* b) {
    asm volatile(
        "mma.sync.aligned.m16n8k16.row.col.f32.bf16.bf16.f32 "
        "{%0,%1,%2,%3}, {%4,%5,%6,%7}, {%8,%9}, {%0,%1,%2,%3};"
        : "+f"(c[0]), "+f"(c[1]), "+f"(c[2]), "+f"(c[3])
        : "r"(a[0]), "r"(a[1]), "r"(a[2]), "r"(a[3]), "r"(b[0]), "r"(b[1]));
}

__global__ void __launch_bounds__(256, 1) gemm1_mma() {
    extern __shared__ char smem[];
    char* sAh = smem;
    char* sAl = smem + ATILE;
    char* sBh = smem + 2 * ATILE;
    char* sBl = smem + 3 * ATILE;

    const int tid = threadIdx.x;
    const int wid = tid >> 5;
    const int lane = tid & 31;
    const int wm = wid >> 2;       // 0..1
    const int wn = wid & 3;        // 0..3
    const int g = lane >> 2;       // 0..7
    const int t = lane & 3;        // 0..3

    const int bm = (blockIdx.x >> 1) * MT;
    const int bn = (blockIdx.x & 1) * 128;

    float acc[4][4][4] = {};       // [mt][nt][4]

    const uint32_t* Ahw = (const uint32_t*)sAh;
    const uint32_t* Alw = (const uint32_t*)sAl;
    const uint32_t* Bhw = (const uint32_t*)sBh;
    const uint32_t* Blw = (const uint32_t*)sBl;

    for (int c = 0; c < 4; c++) {          // K chunks of 64
        // ---- global -> smem: 128 rows x 64 bf16 per tile; 4 uint4/thread/tile
        #pragma unroll
        for (int i = 0; i < 4; i++) {
            int idx = i * 256 + tid;       // 0..1023
            int row = idx >> 3;
            int col8 = (idx & 7) * 8;
            size_t ga = (size_t)(bm + row) * INC + c * 64 + col8;
            size_t gb = (size_t)(bn + row) * INC + c * 64 + col8;
            int so = row * LDB + col8 * 2;
            *(uint4*)(sAh + so) = *(const uint4*)(g_xh + ga);
            *(uint4*)(sAl + so) = *(const uint4*)(g_xl + ga);
            *(uint4*)(sBh + so) = *(const uint4*)(g_w1h + gb);
            *(uint4*)(sBl + so) = *(const uint4*)(g_w1l + gb);
        }
        __syncthreads();

        #pragma unroll
        for (int kk = 0; kk < 4; kk++) {   // k-steps of 16
            const int kw = kk * 8;         // word offset of k-step

            // B fragments: [nt][2] hi and lo
            uint32_t bh[4][2], bl[4][2];
            #pragma unroll
            for (int nt = 0; nt < 4; nt++) {
                int brow = wn * 32 + nt * 8 + g;
                int w0 = brow * LDW + kw + t;
                bh[nt][0] = Bhw[w0];
                bh[nt][1] = Bhw[w0 + 4];
                bl[nt][0] = Blw[w0];
                bl[nt][1] = Blw[w0 + 4];
            }
            #pragma unroll
            for (int mt = 0; mt < 4; mt++) {
                int arow = wm * 64 + mt * 16 + g;
                int w0 = arow * LDW + kw + t;
                uint32_t ah[4], al[4];
                ah[0] = Ahw[w0];
                ah[1] = Ahw[w0 + 8 * LDW];
                ah[2] = Ahw[w0 + 4];
                ah[3] = Ahw[w0 + 8 * LDW + 4];
                al[0] = Alw[w0];
                al[1] = Alw[w0 + 8 * LDW];
                al[2] = Alw[w0 + 4];
                al[3] = Alw[w0 + 8 * LDW + 4];
                #pragma unroll
                for (int nt = 0; nt < 4; nt++) {
                    mma_bf16(acc[mt][nt], ah, bh[nt]);
                    mma_bf16(acc[mt][nt], ah, bl[nt]);
                    mma_bf16(acc[mt][nt], al, bh[nt]);
                }
            }
        }
        __syncthreads();
    }

    // ---- epilogue ----
    #pragma unroll
    for (int mt = 0; mt < 4; mt++) {
        int row0 = bm + wm * 64 + mt * 16 + g;
        int row1 = row0 + 8;
        #pragma unroll
        for (int nt = 0; nt < 4; nt++) {
            int col = bn + wn * 32 + nt * 8 + 2 * t;
            if (row0 < Nn)
                *(float2*)(g_h1 + (size_t)row0 * HC + col) = make_float2(acc[mt][nt][0], acc[mt][nt][1]);
            if (row1 < Nn)
                *(float2*)(g_h1 + (size_t)row1 * HC + col) = make_float2(acc[mt][nt][2], acc[mt][nt][3]);
        }
    }
}

// ---------------- attention coefficients layer 1 -----------------------------
__global__ void attn_coef1(const float* __restrict__ a_src, const float* __restrict__ a_dst) {
    int n = blockIdx.x * 8 + (threadIdx.x >> 5);
    if (n >= Nn) return;
    int lane = threadIdx.x & 31;
    const float4* hp = (const float4*)(g_h1 + (size_t)n * HC);
    float4 v0 = hp[lane * 2], v1 = hp[lane * 2 + 1];
    const float4* sp = (const float4*)a_src;
    const float4* dp = (const float4*)a_dst;
    float4 s0 = sp[lane * 2], s1 = sp[lane * 2 + 1];
    float4 d0 = dp[lane * 2], d1 = dp[lane * 2 + 1];
    float ps = v0.x*s0.x + v0.y*s0.y + v0.z*s0.z + v0.w*s0.w
             + v1.x*s1.x + v1.y*s1.y + v1.z*s1.z + v1.w*s1.w;
    float pd = v0.x*d0.x + v0.y*d0.y + v0.z*d0.z + v0.w*d0.w
             + v1.x*d1.x + v1.y*d1.y + v1.z*d1.z + v1.w*d1.w;
    #pragma unroll
    for (int off = 4; off; off >>= 1) {
        ps += __shfl_down_sync(0xffffffffu, ps, off);
        pd += __shfl_down_sync(0xffffffffu, pd, off);
    }
    if ((lane & 7) == 0) {
        int h = lane >> 3;
        g_als1[n * NH + h] = ps;
        g_ald1[n * NH + h] = pd;
    }
}

// ---------------- layer 1 fused softmax + aggregation + bias + relu ----------
__global__ __launch_bounds__(256) void agg1_kernel(const float* __restrict__ b1) {
    int d = blockIdx.x;
    int start = g_rowptr[d], end = g_rowptr[d + 1];
    int tid = threadIdx.x;
    __shared__ float sden[NH];
    __shared__ int ssrc[128];
    __shared__ float salpha[128 * NH];

    float4 aldv = *(const float4*)&g_ald1[d * NH];

    float p0 = 0.f, p1 = 0.f, p2 = 0.f, p3 = 0.f;
    for (int i = start + tid; i < end; i += 256) {
        int s = g_srcl[i];
        float4 als = *(const float4*)&g_als1[s * NH];
        p0 += __expf(lrelu(als.x + aldv.x));
        p1 += __expf(lrelu(als.y + aldv.y));
        p2 += __expf(lrelu(als.z + aldv.z));
        p3 += __expf(lrelu(als.w + aldv.w));
    }
    #pragma unroll
    for (int off = 16; off; off >>= 1) {
        p0 += __shfl_down_sync(0xffffffffu, p0, off);
        p1 += __shfl_down_sync(0xffffffffu, p1, off);
        p2 += __shfl_down_sync(0xffffffffu, p2, off);
        p3 += __shfl_down_sync(0xffffffffu, p3, off);
    }
    if (tid < NH) sden[tid] = 1e-16f;
    __syncthreads();
    if ((tid & 31) == 0) {
        atomicAdd(&sden[0], p0);
        atomicAdd(&sden[1], p1);
        atomicAdd(&sden[2], p2);
        atomicAdd(&sden[3], p3);
    }
    __syncthreads();
    float rd0 = 1.f / sden[0], rd1 = 1.f / sden[1], rd2 = 1.f / sden[2], rd3 = 1.f / sden[3];

    int ch = tid, head = tid >> 6;
    float acc = 0.f;
    for (int base = start; base < end; base += 128) {
        int cnt = min(128, end - base);
        if (tid < cnt) {
            int s = g_srcl[base + tid];
            ssrc[tid] = s;
            float4 als = *(const float4*)&g_als1[s * NH];
            salpha[tid * 4 + 0] = __expf(lrelu(als.x + aldv.x)) * rd0;
            salpha[tid * 4 + 1] = __expf(lrelu(als.y + aldv.y)) * rd1;
            salpha[tid * 4 + 2] = __expf(lrelu(als.z + aldv.z)) * rd2;
            salpha[tid * 4 + 3] = __expf(lrelu(als.w + aldv.w)) * rd3;
        }
        __syncthreads();
        int j = 0;
        for (; j + 4 <= cnt; j += 4) {
            float a0 = salpha[(j + 0) * 4 + head];
            float a1 = salpha[(j + 1) * 4 + head];
            float a2 = salpha[(j + 2) * 4 + head];
            float a3 = salpha[(j + 3) * 4 + head];
            int s0 = ssrc[j], s1 = ssrc[j + 1], s2 = ssrc[j + 2], s3 = ssrc[j + 3];
            float h0 = g_h1[(size_t)s0 * HC + ch];
            float h1v = g_h1[(size_t)s1 * HC + ch];
            float h2v = g_h1[(size_t)s2 * HC + ch];
            float h3 = g_h1[(size_t)s3 * HC + ch];
            acc = fmaf(a0, h0, acc);
            acc = fmaf(a1, h1v, acc);
            acc = fmaf(a2, h2v, acc);
            acc = fmaf(a3, h3, acc);
        }
        for (; j < cnt; j++)
            acc = fmaf(salpha[j * 4 + head], g_h1[(size_t)ssrc[j] * HC + ch], acc);
        __syncthreads();
    }
    float v = acc + b1[ch];
    g_agg1[(size_t)d * HC + ch] = (v > 0.f) ? v : 0.f;
}

// ---------------- GEMM2: h2 = agg1 @ W2   [50000,256] x [256,40] -------------
__global__ __launch_bounds__(320) void gemm2_kernel(const float* __restrict__ W2) {
    __shared__ float W2s[INC * OC];  // 40 KB
    int tid = threadIdx.y * 40 + threadIdx.x;
    for (int i = tid; i < INC * OC; i += 320) W2s[i] = W2[i];
    __syncthreads();
    int o = threadIdx.x;
    #pragma unroll
    for (int r = 0; r < 8; r++) {
        int row = blockIdx.x * 64 + r * 8 + threadIdx.y;
        if (row >= Nn) continue;
        const float4* xp = (const float4*)(g_agg1 + (size_t)row * INC);
        float acc = 0.f;
        #pragma unroll 8
        for (int k4 = 0; k4 < 64; k4++) {
            float4 xv = xp[k4];
            int kb = k4 * 4 * OC;
            acc = fmaf(xv.x, W2s[kb + o], acc);
            acc = fmaf(xv.y, W2s[kb + OC + o], acc);
            acc = fmaf(xv.z, W2s[kb + 2 * OC + o], acc);
            acc = fmaf(xv.w, W2s[kb + 3 * OC + o], acc);
        }
        g_h2[row * OC + o] = acc;
    }
}

// ---------------- attention coefficients layer 2 ------------------------------
__global__ void attn_coef2(const float* __restrict__ a_src, const float* __restrict__ a_dst) {
    int n = blockIdx.x * 8 + (threadIdx.x >> 5);
    if (n >= Nn) return;
    int lane = threadIdx.x & 31;
    float v0 = g_h2[n * OC + lane];
    float s = v0 * a_src[lane];
    float d = v0 * a_dst[lane];
    if (lane < 8) {
        float v1 = g_h2[n * OC + 32 + lane];
        s += v1 * a_src[32 + lane];
        d += v1 * a_dst[32 + lane];
    }
    #pragma unroll
    for (int off = 16; off; off >>= 1) {
        s += __shfl_down_sync(0xffffffffu, s, off);
        d += __shfl_down_sync(0xffffffffu, d, off);
    }
    if (lane == 0) { g_als2[n] = s; g_ald2[n] = d; }
}

// ---------------- layer 2 fused softmax + aggregation ------------------------
__global__ void agg2_kernel() {
    int n = blockIdx.x * 8 + (threadIdx.x >> 5);
    if (n >= Nn) return;
    int lane = threadIdx.x & 31;
    int start = g_rowptr[n], end = g_rowptr[n + 1];
    float ald = g_ald2[n];

    float den = 0.f;
    for (int i = start + lane; i < end; i += 32)
        den += __expf(lrelu(g_als2[g_srcl[i]] + ald));
    #pragma unroll
    for (int off = 16; off; off >>= 1)
        den += __shfl_xor_sync(0xffffffffu, den, off);
    float rden = 1.f / (den + 1e-16f);

    float acc0 = 0.f, acc1 = 0.f;
    for (int base = start; base < end; base += 32) {
        int i = base + lane;
        int s = 0; float a = 0.f;
        if (i < end) {
            s = g_srcl[i];
            a = __expf(lrelu(g_als2[s] + ald)) * rden;
        }
        int cnt = min(32, end - base);
        for (int j = 0; j < cnt; j++) {
            int   sj = __shfl_sync(0xffffffffu, s, j);
            float aj = __shfl_sync(0xffffffffu, a, j);
            acc0 = fmaf(aj, g_h2[sj * OC + lane], acc0);
            if (lane < 8) acc1 = fmaf(aj, g_h2[sj * OC + 32 + lane], acc1);
        }
    }
    g_agg2[n * OC + lane] = acc0;
    if (lane < 8) g_agg2[n * OC + 32 + lane] = acc1;
}

// ---------------- finalize: out = log_softmax(agg2 + b2) ---------------------
__global__ void finalize(const float* __restrict__ b2, float* __restrict__ out) {
    int n = blockIdx.x * 8 + (threadIdx.x >> 5);
    if (n >= Nn) return;
    int lane = threadIdx.x & 31;
    float v0 = g_agg2[n * OC + lane] + b2[lane];
    float v1 = (lane < 8) ? (g_agg2[n * OC + 32 + lane] + b2[32 + lane])
                          : -3.402823466e38f;
    float mx = fmaxf(v0, v1);
    #pragma unroll
    for (int off = 16; off; off >>= 1)
        mx = fmaxf(mx, __shfl_xor_sync(0xffffffffu, mx, off));
    float se = expf(v0 - mx) + ((lane < 8) ? expf(v1 - mx) : 0.f);
    #pragma unroll
    for (int off = 16; off; off >>= 1)
        se += __shfl_xor_sync(0xffffffffu, se, off);
    float lse = mx + logf(se);
    out[n * OC + lane] = v0 - lse;
    if (lane < 8) out[n * OC + 32 + lane] = v1 - lse;
}

// ---------------- launch -----------------------------------------------------
extern "C" void kernel_launch(void* const* d_in, const int* in_sizes, int n_in,
                              void* d_out, int out_size) {
    const float* x      = (const float*)d_in[0];
    const int*   ei     = (const int*)d_in[1];
    const float* W1     = (const float*)d_in[2];
    const float* a_src1 = (const float*)d_in[3];
    const float* a_dst1 = (const float*)d_in[4];
    const float* b1     = (const float*)d_in[5];
    const float* W2     = (const float*)d_in[6];
    const float* a_src2 = (const float*)d_in[7];
    const float* a_dst2 = (const float*)d_in[8];
    const float* b2     = (const float*)d_in[9];
    float* out = (float*)d_out;

    cudaFuncSetAttribute(gemm1_mma, cudaFuncAttributeMaxDynamicSharedMemorySize, GSM_TOTAL);

    int eblocks = (ET + 255) / 256;

    init_kernel<<<(Nn + 255) / 256, 256>>>();
    hist_kernel<<<eblocks, 256>>>(ei);
    scan_kernel<<<1, 1024>>>();
    fill_kernel<<<eblocks, 256>>>(ei);

    long nv = (long)PADN * INC / 8;
    convert_x<<<(int)((nv + 255) / 256), 256>>>(x);
    convert_w<<<(INC * HC + 255) / 256, 256>>>(W1);

    gemm1_mma<<<MTILES * 2, 256, GSM_TOTAL>>>();

    attn_coef1<<<(Nn + 7) / 8, 256>>>(a_src1, a_dst1);
    agg1_kernel<<<Nn, 256>>>(b1);

    gemm2_kernel<<<(Nn + 63) / 64, dim3(40, 8)>>>(W2);

    attn_coef2<<<(Nn + 7) / 8, 256>>>(a_src2, a_dst2);
    agg2_kernel<<<(Nn + 7) / 8, 256>>>();

    finalize<<<(Nn + 7) / 8, 256>>>(b2, out);
}

// round 5
// speedup vs baseline: 4.2762x; 1.6236x over previous
#include <cuda_runtime.h>
#include <cuda_bf16.h>
#include <cstdint>

#define Nn 50000
#define Ee 800000
#define ET (Ee + Nn)   // 850000 edges incl. self loops
#define INC 256
#define HC 256         // H*C layer1 output width
#define NH 4
#define OC 40
#define NB ((Nn + 255) / 256)          // 196 scan blocks

#define MT 128
#define MTILES ((Nn + MT - 1) / MT)    // 391
#define PADN (MTILES * MT)             // 50048

// ---------------- scratch (device globals; no allocation allowed) ----------
__device__ float g_h1[(size_t)Nn * HC];   // x @ W1 (fp32, for attn + gather)
__device__ float g_als1[Nn * NH];
__device__ float g_ald1[Nn * NH];
__device__ float g_h2[Nn * OC];
__device__ float g_als2[Nn];
__device__ float g_ald2[Nn];
__device__ float g_agg2[Nn * OC];
// CSR scratch
__device__ int g_counts[Nn];
__device__ int g_fill[Nn];
__device__ int g_rowptr[Nn + 1];
__device__ int g_srcl[ET];
__device__ int g_bsum[NB];
__device__ int g_boff[NB];
// split-bf16 weights (K-major [n][k]) for tensor-core GEMMs
__device__ __align__(16) __nv_bfloat16 g_w1h[INC * HC];
__device__ __align__(16) __nv_bfloat16 g_w1l[INC * HC];
__device__ __align__(16) __nv_bfloat16 g_w2h[64 * INC];
__device__ __align__(16) __nv_bfloat16 g_w2l[64 * INC];
// layer-1 aggregation output, split bf16 (input to GEMM2)
__device__ __align__(16) __nv_bfloat16 g_a1h[(size_t)PADN * HC];
__device__ __align__(16) __nv_bfloat16 g_a1l[(size_t)PADN * HC];

// ---------------- misc helpers -----------------------------------------------
__device__ __forceinline__ void edge_sd(const int* __restrict__ ei, int e, int& s, int& d) {
    if (e < Ee) { s = ei[e]; d = ei[Ee + e]; }
    else        { s = e - Ee; d = s; }
}
__device__ __forceinline__ float lrelu(float v) { return (v > 0.f) ? v : 0.2f * v; }
__device__ __forceinline__ uint32_t pack2(__nv_bfloat16 a, __nv_bfloat16 b) {
    __nv_bfloat162 t; t.x = a; t.y = b;
    return *reinterpret_cast<uint32_t*>(&t);
}
__device__ __forceinline__ void split4(float4 v, uint2& hh, uint2& ll) {
    __nv_bfloat16 h0 = __float2bfloat16(v.x), h1 = __float2bfloat16(v.y);
    __nv_bfloat16 h2 = __float2bfloat16(v.z), h3 = __float2bfloat16(v.w);
    __nv_bfloat16 l0 = __float2bfloat16(v.x - __bfloat162float(h0));
    __nv_bfloat16 l1 = __float2bfloat16(v.y - __bfloat162float(h1));
    __nv_bfloat16 l2 = __float2bfloat16(v.z - __bfloat162float(h2));
    __nv_bfloat16 l3 = __float2bfloat16(v.w - __bfloat162float(h3));
    hh.x = pack2(h0, h1); hh.y = pack2(h2, h3);
    ll.x = pack2(l0, l1); ll.y = pack2(l2, l3);
}

// ---------------- init / CSR build -------------------------------------------
__global__ void init_kernel() {
    int i = blockIdx.x * blockDim.x + threadIdx.x;
    if (i < Nn) { g_counts[i] = 0; g_fill[i] = 0; }
}
__global__ void hist_kernel(const int* __restrict__ ei) {
    int e = blockIdx.x * blockDim.x + threadIdx.x;
    if (e >= ET) return;
    int d = (e < Ee) ? ei[Ee + e] : (e - Ee);
    atomicAdd(&g_counts[d], 1);
}

__device__ __forceinline__ int block_incl_scan(int v, int* ws) {
    int lane = threadIdx.x & 31, warp = threadIdx.x >> 5;
    #pragma unroll
    for (int o = 1; o < 32; o <<= 1) {
        int u = __shfl_up_sync(0xffffffffu, v, o);
        if (lane >= o) v += u;
    }
    if (lane == 31) ws[warp] = v;
    __syncthreads();
    if (warp == 0 && lane < 8) {
        int w = ws[lane];
        #pragma unroll
        for (int o = 1; o < 8; o <<= 1) {
            int u = __shfl_up_sync(0xffu, w, o);
            if (lane >= o) w += u;
        }
        ws[lane] = w;
    }
    __syncthreads();
    if (warp > 0) v += ws[warp - 1];
    return v;
}

__global__ void scan_part() {
    __shared__ int ws[8];
    int idx = blockIdx.x * 256 + threadIdx.x;
    int v = (idx < Nn) ? g_counts[idx] : 0;
    int incl = block_incl_scan(v, ws);
    if (idx < Nn) g_rowptr[idx + 1] = incl;
    if (threadIdx.x == 255) g_bsum[blockIdx.x] = incl;
}
__global__ void scan_top() {
    __shared__ int ws[8];
    int t = threadIdx.x;
    int v = (t < NB) ? g_bsum[t] : 0;
    int incl = block_incl_scan(v, ws);
    if (t < NB) g_boff[t] = incl - v;     // exclusive
    if (t == 0) g_rowptr[0] = 0;
}
__global__ void scan_add() {
    int idx = blockIdx.x * 256 + threadIdx.x;
    if (idx < Nn) g_rowptr[idx + 1] += g_boff[blockIdx.x];
}
__global__ void fill_kernel(const int* __restrict__ ei) {
    int e = blockIdx.x * blockDim.x + threadIdx.x;
    if (e >= ET) return;
    int s, d; edge_sd(ei, e, s, d);
    int pos = g_rowptr[d] + atomicAdd(&g_fill[d], 1);
    g_srcl[pos] = s;
}

// ---------------- weight converts ---------------------------------------------
__global__ void convert_w1(const float* __restrict__ W1) {
    int t = blockIdx.x * blockDim.x + threadIdx.x;
    if (t >= INC * HC) return;
    int k = t >> 8, n = t & 255;
    float v = W1[t];
    __nv_bfloat16 h = __float2bfloat16(v);
    g_w1h[n * INC + k] = h;
    g_w1l[n * INC + k] = __float2bfloat16(v - __bfloat162float(h));
}
__global__ void convert_w2(const float* __restrict__ W2) {
    int t = blockIdx.x * blockDim.x + threadIdx.x;
    if (t >= 64 * INC) return;
    int n = t >> 8, k = t & 255;
    float v = (n < OC) ? W2[k * OC + n] : 0.f;
    __nv_bfloat16 h = __float2bfloat16(v);
    g_w2h[n * INC + k] = h;
    g_w2l[n * INC + k] = __float2bfloat16(v - __bfloat162float(h));
}

// ---------------- GEMM common ---------------------------------------------------
#define LDW 36                     // smem row stride in 32-bit words
#define LDB 144                    // smem row stride in bytes (pad: %32 words == 4)
#define ATILE (128 * LDB)          // 18432 bytes

__device__ __forceinline__ void mma_bf16(float* c, const uint32_t* a, const uint32_t* b) {
    asm volatile(
        "mma.sync.aligned.m16n8k16.row.col.f32.bf16.bf16.f32 "
        "{%0,%1,%2,%3}, {%4,%5,%6,%7}, {%8,%9}, {%0,%1,%2,%3};"
        : "+f"(c[0]), "+f"(c[1]), "+f"(c[2]), "+f"(c[3])
        : "r"(a[0]), "r"(a[1]), "r"(a[2]), "r"(a[3]), "r"(b[0]), "r"(b[1]));
}

// ---------------- GEMM1: h1 = x @ W1 (fused fp32->split conversion) ----------
// CTA: 128(M) x 128(N), BK=64, 8 warps (2x4), warp tile 64x32.
#define G1_SMEM (4 * ATILE)        // Ah, Al, Bh, Bl

__global__ void __launch_bounds__(256, 1) gemm1_mma(const float* __restrict__ X) {
    extern __shared__ char smem[];
    char* sAh = smem;
    char* sAl = smem + ATILE;
    char* sBh = smem + 2 * ATILE;
    char* sBl = smem + 3 * ATILE;

    const int tid = threadIdx.x;
    const int wid = tid >> 5;
    const int lane = tid & 31;
    const int wm = wid >> 2;       // 0..1
    const int wn = wid & 3;        // 0..3
    const int g = lane >> 2;       // 0..7
    const int t = lane & 3;        // 0..3

    const int bm = (blockIdx.x >> 1) * MT;
    const int bn = (blockIdx.x & 1) * 128;

    float acc[4][4][4] = {};

    const uint32_t* Ahw = (const uint32_t*)sAh;
    const uint32_t* Alw = (const uint32_t*)sAl;
    const uint32_t* Bhw = (const uint32_t*)sBh;
    const uint32_t* Blw = (const uint32_t*)sBl;

    for (int c = 0; c < 4; c++) {          // K chunks of 64
        // ---- A: load fp32 x directly, split into smem (128 rows x 64 cols)
        #pragma unroll
        for (int i = 0; i < 8; i++) {
            int idx = i * 256 + tid;       // 0..2047
            int row = idx >> 4;
            int col4 = (idx & 15) * 4;
            int grow = bm + row;
            float4 v = (grow < Nn)
                ? *(const float4*)(X + (size_t)grow * INC + c * 64 + col4)
                : make_float4(0.f, 0.f, 0.f, 0.f);
            uint2 hh, ll;
            split4(v, hh, ll);
            int so = row * LDB + col4 * 2;
            *(uint2*)(sAh + so) = hh;
            *(uint2*)(sAl + so) = ll;
        }
        // ---- B: pre-split bf16 weights (128 rows x 64 cols)
        #pragma unroll
        for (int i = 0; i < 4; i++) {
            int idx = i * 256 + tid;       // 0..1023
            int row = idx >> 3;
            int col8 = (idx & 7) * 8;
            size_t gb = (size_t)(bn + row) * INC + c * 64 + col8;
            int so = row * LDB + col8 * 2;
            *(uint4*)(sBh + so) = *(const uint4*)(g_w1h + gb);
            *(uint4*)(sBl + so) = *(const uint4*)(g_w1l + gb);
        }
        __syncthreads();

        #pragma unroll
        for (int kk = 0; kk < 4; kk++) {   // k-steps of 16
            const int kw = kk * 8;
            uint32_t bh[4][2], bl[4][2];
            #pragma unroll
            for (int nt = 0; nt < 4; nt++) {
                int w0 = (wn * 32 + nt * 8 + g) * LDW + kw + t;
                bh[nt][0] = Bhw[w0]; bh[nt][1] = Bhw[w0 + 4];
                bl[nt][0] = Blw[w0]; bl[nt][1] = Blw[w0 + 4];
            }
            #pragma unroll
            for (int mt = 0; mt < 4; mt++) {
                int w0 = (wm * 64 + mt * 16 + g) * LDW + kw + t;
                uint32_t ah[4], al[4];
                ah[0] = Ahw[w0]; ah[1] = Ahw[w0 + 8 * LDW];
                ah[2] = Ahw[w0 + 4]; ah[3] = Ahw[w0 + 8 * LDW + 4];
                al[0] = Alw[w0]; al[1] = Alw[w0 + 8 * LDW];
                al[2] = Alw[w0 + 4]; al[3] = Alw[w0 + 8 * LDW + 4];
                #pragma unroll
                for (int nt = 0; nt < 4; nt++) {
                    mma_bf16(acc[mt][nt], ah, bh[nt]);
                    mma_bf16(acc[mt][nt], ah, bl[nt]);
                    mma_bf16(acc[mt][nt], al, bh[nt]);
                }
            }
        }
        __syncthreads();
    }

    #pragma unroll
    for (int mt = 0; mt < 4; mt++) {
        int row0 = bm + wm * 64 + mt * 16 + g;
        int row1 = row0 + 8;
        #pragma unroll
        for (int nt = 0; nt < 4; nt++) {
            int col = bn + wn * 32 + nt * 8 + 2 * t;
            if (row0 < Nn)
                *(float2*)(g_h1 + (size_t)row0 * HC + col) = make_float2(acc[mt][nt][0], acc[mt][nt][1]);
            if (row1 < Nn)
                *(float2*)(g_h1 + (size_t)row1 * HC + col) = make_float2(acc[mt][nt][2], acc[mt][nt][3]);
        }
    }
}

// ---------------- GEMM2: h2 = agg1 @ W2 (split bf16, N=64 padded) -------------
// CTA: 128(M) x 64(N), BK=64, 8 warps (4x2), warp tile 32x32.
#define BTILE2 (64 * LDB)          // 9216 bytes
#define G2_SMEM (2 * ATILE + 2 * BTILE2)   // 55296

__global__ void __launch_bounds__(256, 1) gemm2_mma() {
    extern __shared__ char smem[];
    char* sAh = smem;
    char* sAl = smem + ATILE;
    char* sBh = smem + 2 * ATILE;
    char* sBl = smem + 2 * ATILE + BTILE2;

    const int tid = threadIdx.x;
    const int wid = tid >> 5;
    const int lane = tid & 31;
    const int wm = wid >> 1;       // 0..3
    const int wn = wid & 1;        // 0..1
    const int g = lane >> 2;
    const int t = lane & 3;

    const int bm = blockIdx.x * MT;

    float acc[2][4][4] = {};

    const uint32_t* Ahw = (const uint32_t*)sAh;
    const uint32_t* Alw = (const uint32_t*)sAl;
    const uint32_t* Bhw = (const uint32_t*)sBh;
    const uint32_t* Blw = (const uint32_t*)sBl;

    for (int c = 0; c < 4; c++) {
        #pragma unroll
        for (int i = 0; i < 4; i++) {
            int idx = i * 256 + tid;       // 0..1023
            int row = idx >> 3;
            int col8 = (idx & 7) * 8;
            size_t ga = (size_t)(bm + row) * HC + c * 64 + col8;
            int so = row * LDB + col8 * 2;
            *(uint4*)(sAh + so) = *(const uint4*)(g_a1h + ga);
            *(uint4*)(sAl + so) = *(const uint4*)(g_a1l + ga);
        }
        #pragma unroll
        for (int i = 0; i < 2; i++) {
            int idx = i * 256 + tid;       // 0..511
            int row = idx >> 3;            // 0..63
            int col8 = (idx & 7) * 8;
            size_t gb = (size_t)row * INC + c * 64 + col8;
            int so = row * LDB + col8 * 2;
            *(uint4*)(sBh + so) = *(const uint4*)(g_w2h + gb);
            *(uint4*)(sBl + so) = *(const uint4*)(g_w2l + gb);
        }
        __syncthreads();

        #pragma unroll
        for (int kk = 0; kk < 4; kk++) {
            const int kw = kk * 8;
            uint32_t bh[4][2], bl[4][2];
            #pragma unroll
            for (int nt = 0; nt < 4; nt++) {
                int w0 = (wn * 32 + nt * 8 + g) * LDW + kw + t;
                bh[nt][0] = Bhw[w0]; bh[nt][1] = Bhw[w0 + 4];
                bl[nt][0] = Blw[w0]; bl[nt][1] = Blw[w0 + 4];
            }
            #pragma unroll
            for (int mt = 0; mt < 2; mt++) {
                int w0 = (wm * 32 + mt * 16 + g) * LDW + kw + t;
                uint32_t ah[4], al[4];
                ah[0] = Ahw[w0]; ah[1] = Ahw[w0 + 8 * LDW];
                ah[2] = Ahw[w0 + 4]; ah[3] = Ahw[w0 + 8 * LDW + 4];
                al[0] = Alw[w0]; al[1] = Alw[w0 + 8 * LDW];
                al[2] = Alw[w0 + 4]; al[3] = Alw[w0 + 8 * LDW + 4];
                #pragma unroll
                for (int nt = 0; nt < 4; nt++) {
                    mma_bf16(acc[mt][nt], ah, bh[nt]);
                    mma_bf16(acc[mt][nt], ah, bl[nt]);
                    mma_bf16(acc[mt][nt], al, bh[nt]);
                }
            }
        }
        __syncthreads();
    }

    #pragma unroll
    for (int mt = 0; mt < 2; mt++) {
        int row0 = bm + wm * 32 + mt * 16 + g;
        int row1 = row0 + 8;
        #pragma unroll
        for (int nt = 0; nt < 4; nt++) {
            int col = wn * 32 + nt * 8 + 2 * t;
            if (col < OC) {
                if (row0 < Nn)
                    *(float2*)(g_h2 + (size_t)row0 * OC + col) = make_float2(acc[mt][nt][0], acc[mt][nt][1]);
                if (row1 < Nn)
                    *(float2*)(g_h2 + (size_t)row1 * OC + col) = make_float2(acc[mt][nt][2], acc[mt][nt][3]);
            }
        }
    }
}

// ---------------- attention coefficients layer 1 -----------------------------
__global__ void attn_coef1(const float* __restrict__ a_src, const float* __restrict__ a_dst) {
    int n = blockIdx.x * 8 + (threadIdx.x >> 5);
    if (n >= Nn) return;
    int lane = threadIdx.x & 31;
    const float4* hp = (const float4*)(g_h1 + (size_t)n * HC);
    float4 v0 = hp[lane * 2], v1 = hp[lane * 2 + 1];
    const float4* sp = (const float4*)a_src;
    const float4* dp = (const float4*)a_dst;
    float4 s0 = sp[lane * 2], s1 = sp[lane * 2 + 1];
    float4 d0 = dp[lane * 2], d1 = dp[lane * 2 + 1];
    float ps = v0.x*s0.x + v0.y*s0.y + v0.z*s0.z + v0.w*s0.w
             + v1.x*s1.x + v1.y*s1.y + v1.z*s1.z + v1.w*s1.w;
    float pd = v0.x*d0.x + v0.y*d0.y + v0.z*d0.z + v0.w*d0.w
             + v1.x*d1.x + v1.y*d1.y + v1.z*d1.z + v1.w*d1.w;
    #pragma unroll
    for (int off = 4; off; off >>= 1) {
        ps += __shfl_down_sync(0xffffffffu, ps, off);
        pd += __shfl_down_sync(0xffffffffu, pd, off);
    }
    if ((lane & 7) == 0) {
        int h = lane >> 3;
        g_als1[n * NH + h] = ps;
        g_ald1[n * NH + h] = pd;
    }
}

// ---------------- layer 1 fused softmax + aggregation + bias + relu + split --
// 256 threads: slot = tid>>6 picks 1 of 4 parallel edges, ch4 = tid&63 float4 lane
__global__ __launch_bounds__(256) void agg1_kernel(const float* __restrict__ b1) {
    int d = blockIdx.x;
    int start = g_rowptr[d], end = g_rowptr[d + 1];
    int tid = threadIdx.x;
    __shared__ float sden[NH];
    __shared__ int ssrc[128];
    __shared__ float salpha[128 * NH];
    __shared__ float4 sacc[4 * 64];

    float4 aldv = *(const float4*)&g_ald1[d * NH];

    // phase A: denominators per head
    float p0 = 0.f, p1 = 0.f, p2 = 0.f, p3 = 0.f;
    for (int i = start + tid; i < end; i += 256) {
        int s = g_srcl[i];
        float4 als = *(const float4*)&g_als1[s * NH];
        p0 += __expf(lrelu(als.x + aldv.x));
        p1 += __expf(lrelu(als.y + aldv.y));
        p2 += __expf(lrelu(als.z + aldv.z));
        p3 += __expf(lrelu(als.w + aldv.w));
    }
    #pragma unroll
    for (int off = 16; off; off >>= 1) {
        p0 += __shfl_down_sync(0xffffffffu, p0, off);
        p1 += __shfl_down_sync(0xffffffffu, p1, off);
        p2 += __shfl_down_sync(0xffffffffu, p2, off);
        p3 += __shfl_down_sync(0xffffffffu, p3, off);
    }
    if (tid < NH) sden[tid] = 1e-16f;
    __syncthreads();
    if ((tid & 31) == 0) {
        atomicAdd(&sden[0], p0);
        atomicAdd(&sden[1], p1);
        atomicAdd(&sden[2], p2);
        atomicAdd(&sden[3], p3);
    }
    __syncthreads();
    float rd0 = 1.f / sden[0], rd1 = 1.f / sden[1], rd2 = 1.f / sden[2], rd3 = 1.f / sden[3];

    const int ch4 = tid & 63;
    const int slot = tid >> 6;
    const int head = ch4 >> 4;
    float4 acc = make_float4(0.f, 0.f, 0.f, 0.f);

    for (int base = start; base < end; base += 128) {
        int cnt = min(128, end - base);
        if (tid < cnt) {
            int s = g_srcl[base + tid];
            ssrc[tid] = s;
            float4 als = *(const float4*)&g_als1[s * NH];
            salpha[tid * 4 + 0] = __expf(lrelu(als.x + aldv.x)) * rd0;
            salpha[tid * 4 + 1] = __expf(lrelu(als.y + aldv.y)) * rd1;
            salpha[tid * 4 + 2] = __expf(lrelu(als.z + aldv.z)) * rd2;
            salpha[tid * 4 + 3] = __expf(lrelu(als.w + aldv.w)) * rd3;
        }
        __syncthreads();
        for (int j = slot; j < cnt; j += 4) {
            float a = salpha[j * 4 + head];
            int s = ssrc[j];
            float4 h = *((const float4*)(g_h1 + (size_t)s * HC) + ch4);
            acc.x = fmaf(a, h.x, acc.x);
            acc.y = fmaf(a, h.y, acc.y);
            acc.z = fmaf(a, h.z, acc.z);
            acc.w = fmaf(a, h.w, acc.w);
        }
        __syncthreads();
    }
    sacc[slot * 64 + ch4] = acc;
    __syncthreads();
    if (tid < 64) {
        float4 a0 = sacc[tid], a1 = sacc[64 + tid], a2 = sacc[128 + tid], a3 = sacc[192 + tid];
        int ch = tid * 4;
        float4 bb = *(const float4*)(b1 + ch);
        float4 r;
        r.x = fmaxf(a0.x + a1.x + a2.x + a3.x + bb.x, 0.f);
        r.y = fmaxf(a0.y + a1.y + a2.y + a3.y + bb.y, 0.f);
        r.z = fmaxf(a0.z + a1.z + a2.z + a3.z + bb.z, 0.f);
        r.w = fmaxf(a0.w + a1.w + a2.w + a3.w + bb.w, 0.f);
        uint2 hh, ll;
        split4(r, hh, ll);
        *(uint2*)(g_a1h + (size_t)d * HC + ch) = hh;
        *(uint2*)(g_a1l + (size_t)d * HC + ch) = ll;
    }
}

// ---------------- attention coefficients layer 2 ------------------------------
__global__ void attn_coef2(const float* __restrict__ a_src, const float* __restrict__ a_dst) {
    int n = blockIdx.x * 8 + (threadIdx.x >> 5);
    if (n >= Nn) return;
    int lane = threadIdx.x & 31;
    float v0 = g_h2[n * OC + lane];
    float s = v0 * a_src[lane];
    float d = v0 * a_dst[lane];
    if (lane < 8) {
        float v1 = g_h2[n * OC + 32 + lane];
        s += v1 * a_src[32 + lane];
        d += v1 * a_dst[32 + lane];
    }
    #pragma unroll
    for (int off = 16; off; off >>= 1) {
        s += __shfl_down_sync(0xffffffffu, s, off);
        d += __shfl_down_sync(0xffffffffu, d, off);
    }
    if (lane == 0) { g_als2[n] = s; g_ald2[n] = d; }
}

// ---------------- layer 2 fused softmax + aggregation ------------------------
__global__ void agg2_kernel() {
    int n = blockIdx.x * 8 + (threadIdx.x >> 5);
    if (n >= Nn) return;
    int lane = threadIdx.x & 31;
    int start = g_rowptr[n], end = g_rowptr[n + 1];
    float ald = g_ald2[n];

    float den = 0.f;
    for (int i = start + lane; i < end; i += 32)
        den += __expf(lrelu(g_als2[g_srcl[i]] + ald));
    #pragma unroll
    for (int off = 16; off; off >>= 1)
        den += __shfl_xor_sync(0xffffffffu, den, off);
    float rden = 1.f / (den + 1e-16f);

    float acc0 = 0.f, acc1 = 0.f;
    for (int base = start; base < end; base += 32) {
        int i = base + lane;
        int s = 0; float a = 0.f;
        if (i < end) {
            s = g_srcl[i];
            a = __expf(lrelu(g_als2[s] + ald)) * rden;
        }
        int cnt = min(32, end - base);
        for (int j = 0; j < cnt; j++) {
            int   sj = __shfl_sync(0xffffffffu, s, j);
            float aj = __shfl_sync(0xffffffffu, a, j);
            acc0 = fmaf(aj, g_h2[sj * OC + lane], acc0);
            if (lane < 8) acc1 = fmaf(aj, g_h2[sj * OC + 32 + lane], acc1);
        }
    }
    g_agg2[n * OC + lane] = acc0;
    if (lane < 8) g_agg2[n * OC + 32 + lane] = acc1;
}

// ---------------- finalize: out = log_softmax(agg2 + b2) ---------------------
__global__ void finalize(const float* __restrict__ b2, float* __restrict__ out) {
    int n = blockIdx.x * 8 + (threadIdx.x >> 5);
    if (n >= Nn) return;
    int lane = threadIdx.x & 31;
    float v0 = g_agg2[n * OC + lane] + b2[lane];
    float v1 = (lane < 8) ? (g_agg2[n * OC + 32 + lane] + b2[32 + lane])
                          : -3.402823466e38f;
    float mx = fmaxf(v0, v1);
    #pragma unroll
    for (int off = 16; off; off >>= 1)
        mx = fmaxf(mx, __shfl_xor_sync(0xffffffffu, mx, off));
    float se = expf(v0 - mx) + ((lane < 8) ? expf(v1 - mx) : 0.f);
    #pragma unroll
    for (int off = 16; off; off >>= 1)
        se += __shfl_xor_sync(0xffffffffu, se, off);
    float lse = mx + logf(se);
    out[n * OC + lane] = v0 - lse;
    if (lane < 8) out[n * OC + 32 + lane] = v1 - lse;
}

// ---------------- launch -----------------------------------------------------
extern "C" void kernel_launch(void* const* d_in, const int* in_sizes, int n_in,
                              void* d_out, int out_size) {
    const float* x      = (const float*)d_in[0];
    const int*   ei     = (const int*)d_in[1];
    const float* W1     = (const float*)d_in[2];
    const float* a_src1 = (const float*)d_in[3];
    const float* a_dst1 = (const float*)d_in[4];
    const float* b1     = (const float*)d_in[5];
    const float* W2     = (const float*)d_in[6];
    const float* a_src2 = (const float*)d_in[7];
    const float* a_dst2 = (const float*)d_in[8];
    const float* b2     = (const float*)d_in[9];
    float* out = (float*)d_out;

    cudaFuncSetAttribute(gemm1_mma, cudaFuncAttributeMaxDynamicSharedMemorySize, G1_SMEM);
    cudaFuncSetAttribute(gemm2_mma, cudaFuncAttributeMaxDynamicSharedMemorySize, G2_SMEM);

    int eblocks = (ET + 255) / 256;

    init_kernel<<<NB, 256>>>();
    hist_kernel<<<eblocks, 256>>>(ei);
    scan_part<<<NB, 256>>>();
    scan_top<<<1, 256>>>();
    scan_add<<<NB, 256>>>();
    fill_kernel<<<eblocks, 256>>>(ei);

    convert_w1<<<(INC * HC + 255) / 256, 256>>>(W1);
    convert_w2<<<(64 * INC + 255) / 256, 256>>>(W2);

    gemm1_mma<<<MTILES * 2, 256, G1_SMEM>>>(x);

    attn_coef1<<<(Nn + 7) / 8, 256>>>(a_src1, a_dst1);
    agg1_kernel<<<Nn, 256>>>(b1);

    gemm2_mma<<<MTILES, 256, G2_SMEM>>>();

    attn_coef2<<<(Nn + 7) / 8, 256>>>(a_src2, a_dst2);
    agg2_kernel<<<(Nn + 7) / 8, 256>>>();

    finalize<<<(Nn + 7) / 8, 256>>>(b2, out);
}

// round 6
// speedup vs baseline: 4.3006x; 1.0057x over previous
#include <cuda_runtime.h>
#include <cuda_bf16.h>
#include <cstdint>

#define Nn 50000
#define Ee 800000
#define ET (Ee + Nn)   // 850000 edges incl. self loops
#define INC 256
#define HC 256
#define NH 4
#define OC 40
#define NB ((Nn + 255) / 256)          // 196 scan blocks

#define MT 128
#define MTILES ((Nn + MT - 1) / MT)    // 391
#define PADN (MTILES * MT)             // 50048

// ---------------- scratch ----------------------------------------------------
__device__ float g_h1[(size_t)Nn * HC];
__device__ float g_als1[Nn * NH];
__device__ float g_ald1[Nn * NH];
__device__ float g_h2[Nn * OC];
__device__ float g_als2[Nn];
__device__ float g_ald2[Nn];
__device__ int g_counts[Nn];
__device__ int g_fill[Nn];
__device__ int g_rowptr[Nn + 1];
__device__ int g_srcl[ET];
__device__ int g_bsum[NB];
__device__ int g_boff[NB];
__device__ __align__(16) __nv_bfloat16 g_w1h[INC * HC];
__device__ __align__(16) __nv_bfloat16 g_w1l[INC * HC];
__device__ __align__(16) __nv_bfloat16 g_w2h[64 * INC];
__device__ __align__(16) __nv_bfloat16 g_w2l[64 * INC];
__device__ __align__(16) __nv_bfloat16 g_a1h[(size_t)PADN * HC];
__device__ __align__(16) __nv_bfloat16 g_a1l[(size_t)PADN * HC];

// ---------------- helpers ----------------------------------------------------
__device__ __forceinline__ void edge_sd(const int* __restrict__ ei, int e, int& s, int& d) {
    if (e < Ee) { s = ei[e]; d = ei[Ee + e]; }
    else        { s = e - Ee; d = s; }
}
__device__ __forceinline__ float lrelu(float v) { return (v > 0.f) ? v : 0.2f * v; }
__device__ __forceinline__ uint32_t pack2(__nv_bfloat16 a, __nv_bfloat16 b) {
    __nv_bfloat162 t; t.x = a; t.y = b;
    return *reinterpret_cast<uint32_t*>(&t);
}
__device__ __forceinline__ void split4(float4 v, uint2& hh, uint2& ll) {
    __nv_bfloat16 h0 = __float2bfloat16(v.x), h1 = __float2bfloat16(v.y);
    __nv_bfloat16 h2 = __float2bfloat16(v.z), h3 = __float2bfloat16(v.w);
    __nv_bfloat16 l0 = __float2bfloat16(v.x - __bfloat162float(h0));
    __nv_bfloat16 l1 = __float2bfloat16(v.y - __bfloat162float(h1));
    __nv_bfloat16 l2 = __float2bfloat16(v.z - __bfloat162float(h2));
    __nv_bfloat16 l3 = __float2bfloat16(v.w - __bfloat162float(h3));
    hh.x = pack2(h0, h1); hh.y = pack2(h2, h3);
    ll.x = pack2(l0, l1); ll.y = pack2(l2, l3);
}
__device__ __forceinline__ uint32_t smem_u32(const void* p) {
    uint32_t a;
    asm("{ .reg .u64 t; cvta.to.shared.u64 t, %1; cvt.u32.u64 %0, t; }" : "=r"(a) : "l"(p));
    return a;
}
__device__ __forceinline__ void cp16(uint32_t dst, const void* src) {
    asm volatile("cp.async.ca.shared.global [%0], [%1], 16;" :: "r"(dst), "l"(src));
}
#define CP_COMMIT() asm volatile("cp.async.commit_group;" ::: "memory")
#define CP_WAIT0()  asm volatile("cp.async.wait_group 0;" ::: "memory")

// ---------------- init / CSR build -------------------------------------------
__global__ void init_kernel() {
    int i = blockIdx.x * blockDim.x + threadIdx.x;
    if (i < Nn) { g_counts[i] = 0; g_fill[i] = 0; }
}
__global__ void hist_kernel(const int* __restrict__ ei) {
    int e = blockIdx.x * blockDim.x + threadIdx.x;
    if (e >= ET) return;
    int d = (e < Ee) ? ei[Ee + e] : (e - Ee);
    atomicAdd(&g_counts[d], 1);
}
__device__ __forceinline__ int block_incl_scan(int v, int* ws) {
    int lane = threadIdx.x & 31, warp = threadIdx.x >> 5;
    #pragma unroll
    for (int o = 1; o < 32; o <<= 1) {
        int u = __shfl_up_sync(0xffffffffu, v, o);
        if (lane >= o) v += u;
    }
    if (lane == 31) ws[warp] = v;
    __syncthreads();
    if (warp == 0 && lane < 8) {
        int w = ws[lane];
        #pragma unroll
        for (int o = 1; o < 8; o <<= 1) {
            int u = __shfl_up_sync(0xffu, w, o);
            if (lane >= o) w += u;
        }
        ws[lane] = w;
    }
    __syncthreads();
    if (warp > 0) v += ws[warp - 1];
    return v;
}
__global__ void scan_part() {
    __shared__ int ws[8];
    int idx = blockIdx.x * 256 + threadIdx.x;
    int v = (idx < Nn) ? g_counts[idx] : 0;
    int incl = block_incl_scan(v, ws);
    if (idx < Nn) g_rowptr[idx + 1] = incl;
    if (threadIdx.x == 255) g_bsum[blockIdx.x] = incl;
}
__global__ void scan_top() {
    __shared__ int ws[8];
    int t = threadIdx.x;
    int v = (t < NB) ? g_bsum[t] : 0;
    int incl = block_incl_scan(v, ws);
    if (t < NB) g_boff[t] = incl - v;
    if (t == 0) g_rowptr[0] = 0;
}
__global__ void scan_add() {
    int idx = blockIdx.x * 256 + threadIdx.x;
    if (idx < Nn) g_rowptr[idx + 1] += g_boff[blockIdx.x];
}
__global__ void fill_kernel(const int* __restrict__ ei) {
    int e = blockIdx.x * blockDim.x + threadIdx.x;
    if (e >= ET) return;
    int s, d; edge_sd(ei, e, s, d);
    int pos = g_rowptr[d] + atomicAdd(&g_fill[d], 1);
    g_srcl[pos] = s;
}

// ---------------- weight converts ---------------------------------------------
__global__ void convert_w1(const float* __restrict__ W1) {
    int t = blockIdx.x * blockDim.x + threadIdx.x;
    if (t >= INC * HC) return;
    int k = t >> 8, n = t & 255;
    float v = W1[t];
    __nv_bfloat16 h = __float2bfloat16(v);
    g_w1h[n * INC + k] = h;
    g_w1l[n * INC + k] = __float2bfloat16(v - __bfloat162float(h));
}
__global__ void convert_w2(const float* __restrict__ W2) {
    int t = blockIdx.x * blockDim.x + threadIdx.x;
    if (t >= 64 * INC) return;
    int n = t >> 8, k = t & 255;
    float v = (n < OC) ? W2[k * OC + n] : 0.f;
    __nv_bfloat16 h = __float2bfloat16(v);
    g_w2h[n * INC + k] = h;
    g_w2l[n * INC + k] = __float2bfloat16(v - __bfloat162float(h));
}

// ---------------- GEMM common ---------------------------------------------------
#define LDW 36
#define LDB 144
#define ATILE (128 * LDB)          // 18432 bytes

__device__ __forceinline__ void mma_bf16(float* c, const uint32_t* a, const uint32_t* b) {
    asm volatile(
        "mma.sync.aligned.m16n8k16.row.col.f32.bf16.bf16.f32 "
        "{%0,%1,%2,%3}, {%4,%5,%6,%7}, {%8,%9}, {%0,%1,%2,%3};"
        : "+f"(c[0]), "+f"(c[1]), "+f"(c[2]), "+f"(c[3])
        : "r"(a[0]), "r"(a[1]), "r"(a[2]), "r"(a[3]), "r"(b[0]), "r"(b[1]));
}

// ---------------- GEMM1: h1 = x @ W1, fused attn coef epilogue ----------------
// double buffered: [Ah Al Bh Bl] x2
#define G1_BUF (4 * ATILE)
#define G1_SMEM (2 * G1_BUF)       // 147456

__global__ void __launch_bounds__(256, 1)
gemm1_mma(const float* __restrict__ X,
          const float* __restrict__ a_src, const float* __restrict__ a_dst) {
    extern __shared__ char smem[];
    __shared__ float sAs[256], sAd[256];
    __shared__ float red[2][2][2][64];   // [wm][hl][s/d][row]

    const int tid = threadIdx.x;
    const int wid = tid >> 5;
    const int lane = tid & 31;
    const int wm = wid >> 2;
    const int wn = wid & 3;
    const int g = lane >> 2;
    const int t = lane & 3;
    const int hl = wn >> 1;

    const int bm = (blockIdx.x >> 1) * MT;
    const int bn = (blockIdx.x & 1) * 128;

    const uint32_t sb = smem_u32(smem);

    // prologue: stage attn vectors + zero reduction buffer
    if (tid < 128) { sAs[tid] = a_src[bn + tid]; sAd[tid] = a_dst[bn + tid]; }
    else { sAs[tid] = 0.f; sAd[tid] = 0.f; }
    {
        float* rp = &red[0][0][0][0];
        #pragma unroll
        for (int i = 0; i < 4; i++) rp[i * 256 + tid] = 0.f;
    }

    float acc[4][4][4] = {};
    float4 aregs[8];

    // ---- A global loads into regs for chunk c ----
    auto loadA = [&](int c) {
        #pragma unroll
        for (int i = 0; i < 8; i++) {
            int idx = i * 256 + tid;
            int row = idx >> 4;
            int col4 = (idx & 15) * 4;
            int grow = bm + row;
            aregs[i] = (grow < Nn)
                ? *(const float4*)(X + (size_t)grow * INC + c * 64 + col4)
                : make_float4(0.f, 0.f, 0.f, 0.f);
        }
    };
    auto storeA = [&](int buf) {
        char* sAh = smem + buf * G1_BUF;
        char* sAl = sAh + ATILE;
        #pragma unroll
        for (int i = 0; i < 8; i++) {
            int idx = i * 256 + tid;
            int row = idx >> 4;
            int col4 = (idx & 15) * 4;
            uint2 hh, ll;
            split4(aregs[i], hh, ll);
            int so = row * LDB + col4 * 2;
            *(uint2*)(sAh + so) = hh;
            *(uint2*)(sAl + so) = ll;
        }
    };
    auto cpB = [&](int c, int buf) {
        uint32_t dBh = sb + buf * G1_BUF + 2 * ATILE;
        uint32_t dBl = dBh + ATILE;
        #pragma unroll
        for (int i = 0; i < 4; i++) {
            int idx = i * 256 + tid;
            int row = idx >> 3;
            int col8 = (idx & 7) * 8;
            size_t gb = (size_t)(bn + row) * INC + c * 64 + col8;
            uint32_t so = row * LDB + col8 * 2;
            cp16(dBh + so, g_w1h + gb);
            cp16(dBl + so, g_w1l + gb);
        }
    };
    auto compute = [&](int buf) {
        const uint32_t* Ahw = (const uint32_t*)(smem + buf * G1_BUF);
        const uint32_t* Alw = (const uint32_t*)(smem + buf * G1_BUF + ATILE);
        const uint32_t* Bhw = (const uint32_t*)(smem + buf * G1_BUF + 2 * ATILE);
        const uint32_t* Blw = (const uint32_t*)(smem + buf * G1_BUF + 3 * ATILE);
        #pragma unroll
        for (int kk = 0; kk < 4; kk++) {
            const int kw = kk * 8;
            uint32_t bh[4][2], bl[4][2];
            #pragma unroll
            for (int nt = 0; nt < 4; nt++) {
                int w0 = (wn * 32 + nt * 8 + g) * LDW + kw + t;
                bh[nt][0] = Bhw[w0]; bh[nt][1] = Bhw[w0 + 4];
                bl[nt][0] = Blw[w0]; bl[nt][1] = Blw[w0 + 4];
            }
            #pragma unroll
            for (int mt = 0; mt < 4; mt++) {
                int w0 = (wm * 64 + mt * 16 + g) * LDW + kw + t;
                uint32_t ah[4], al[4];
                ah[0] = Ahw[w0]; ah[1] = Ahw[w0 + 8 * LDW];
                ah[2] = Ahw[w0 + 4]; ah[3] = Ahw[w0 + 8 * LDW + 4];
                al[0] = Alw[w0]; al[1] = Alw[w0 + 8 * LDW];
                al[2] = Alw[w0 + 4]; al[3] = Alw[w0 + 8 * LDW + 4];
                #pragma unroll
                for (int nt = 0; nt < 4; nt++) {
                    mma_bf16(acc[mt][nt], ah, bh[nt]);
                    mma_bf16(acc[mt][nt], ah, bl[nt]);
                    mma_bf16(acc[mt][nt], al, bh[nt]);
                }
            }
        }
    };

    // pipeline
    loadA(0); cpB(0, 0); CP_COMMIT(); storeA(0);
    CP_WAIT0(); __syncthreads();
    #pragma unroll
    for (int c = 0; c < 4; c++) {
        int buf = c & 1;
        if (c < 3) { loadA(c + 1); cpB(c + 1, buf ^ 1); CP_COMMIT(); }
        compute(buf);
        if (c < 3) { storeA(buf ^ 1); CP_WAIT0(); __syncthreads(); }
    }

    // ---- epilogue: h1 stores + attn dot-products ----
    #pragma unroll
    for (int mt = 0; mt < 4; mt++) {
        int row0 = bm + wm * 64 + mt * 16 + g;
        int row1 = row0 + 8;
        float s0 = 0.f, s1 = 0.f, d0 = 0.f, d1 = 0.f;
        #pragma unroll
        for (int nt = 0; nt < 4; nt++) {
            int lcol = wn * 32 + nt * 8 + 2 * t;
            int col = bn + lcol;
            float as0 = sAs[lcol], as1 = sAs[lcol + 1];
            float ad0 = sAd[lcol], ad1 = sAd[lcol + 1];
            s0 += acc[mt][nt][0] * as0 + acc[mt][nt][1] * as1;
            s1 += acc[mt][nt][2] * as0 + acc[mt][nt][3] * as1;
            d0 += acc[mt][nt][0] * ad0 + acc[mt][nt][1] * ad1;
            d1 += acc[mt][nt][2] * ad0 + acc[mt][nt][3] * ad1;
            if (row0 < Nn)
                *(float2*)(g_h1 + (size_t)row0 * HC + col) = make_float2(acc[mt][nt][0], acc[mt][nt][1]);
            if (row1 < Nn)
                *(float2*)(g_h1 + (size_t)row1 * HC + col) = make_float2(acc[mt][nt][2], acc[mt][nt][3]);
        }
        s0 += __shfl_down_sync(0xffffffffu, s0, 2); s0 += __shfl_down_sync(0xffffffffu, s0, 1);
        s1 += __shfl_down_sync(0xffffffffu, s1, 2); s1 += __shfl_down_sync(0xffffffffu, s1, 1);
        d0 += __shfl_down_sync(0xffffffffu, d0, 2); d0 += __shfl_down_sync(0xffffffffu, d0, 1);
        d1 += __shfl_down_sync(0xffffffffu, d1, 2); d1 += __shfl_down_sync(0xffffffffu, d1, 1);
        if (t == 0) {
            int r0 = mt * 16 + g, r1 = r0 + 8;
            atomicAdd(&red[wm][hl][0][r0], s0);
            atomicAdd(&red[wm][hl][0][r1], s1);
            atomicAdd(&red[wm][hl][1][r0], d0);
            atomicAdd(&red[wm][hl][1][r1], d1);
        }
    }
    __syncthreads();
    if (tid < 128) {
        int n = bm + tid;
        if (n < Nn) {
            int w = tid >> 6, r = tid & 63;
            #pragma unroll
            for (int h = 0; h < 2; h++) {
                int head = (bn >> 6) + h;
                g_als1[n * NH + head] = red[w][h][0][r];
                g_ald1[n * NH + head] = red[w][h][1][r];
            }
        }
    }
}

// ---------------- GEMM2: h2 = agg1 @ W2, fused attn coef epilogue -------------
#define BTILE2 (64 * LDB)
#define G2_BUF (2 * ATILE + 2 * BTILE2)
#define G2_SMEM (2 * G2_BUF)       // 110592

__global__ void __launch_bounds__(256, 1)
gemm2_mma(const float* __restrict__ a_src, const float* __restrict__ a_dst) {
    extern __shared__ char smem[];
    __shared__ float sAs[64], sAd[64];
    __shared__ float red2[2][128];

    const int tid = threadIdx.x;
    const int wid = tid >> 5;
    const int lane = tid & 31;
    const int wm = wid >> 1;
    const int wn = wid & 1;
    const int g = lane >> 2;
    const int t = lane & 3;

    const int bm = blockIdx.x * MT;
    const uint32_t sb = smem_u32(smem);

    if (tid < 64) { sAs[tid] = (tid < OC) ? a_src[tid] : 0.f;
                    sAd[tid] = (tid < OC) ? a_dst[tid] : 0.f; }
    if (tid < 128) { red2[0][tid] = 0.f; red2[1][tid] = 0.f; }

    float acc[2][4][4] = {};

    auto stage = [&](int c, int buf) {
        uint32_t dAh = sb + buf * G2_BUF;
        uint32_t dAl = dAh + ATILE;
        uint32_t dBh = dAl + ATILE;
        uint32_t dBl = dBh + BTILE2;
        #pragma unroll
        for (int i = 0; i < 4; i++) {
            int idx = i * 256 + tid;
            int row = idx >> 3;
            int col8 = (idx & 7) * 8;
            size_t ga = (size_t)(bm + row) * HC + c * 64 + col8;
            uint32_t so = row * LDB + col8 * 2;
            cp16(dAh + so, g_a1h + ga);
            cp16(dAl + so, g_a1l + ga);
        }
        #pragma unroll
        for (int i = 0; i < 2; i++) {
            int idx = i * 256 + tid;
            int row = idx >> 3;
            int col8 = (idx & 7) * 8;
            size_t gb = (size_t)row * INC + c * 64 + col8;
            uint32_t so = row * LDB + col8 * 2;
            cp16(dBh + so, g_w2h + gb);
            cp16(dBl + so, g_w2l + gb);
        }
    };
    auto compute = [&](int buf) {
        const uint32_t* Ahw = (const uint32_t*)(smem + buf * G2_BUF);
        const uint32_t* Alw = (const uint32_t*)(smem + buf * G2_BUF + ATILE);
        const uint32_t* Bhw = (const uint32_t*)(smem + buf * G2_BUF + 2 * ATILE);
        const uint32_t* Blw = (const uint32_t*)(smem + buf * G2_BUF + 2 * ATILE + BTILE2);
        #pragma unroll
        for (int kk = 0; kk < 4; kk++) {
            const int kw = kk * 8;
            uint32_t bh[4][2], bl[4][2];
            #pragma unroll
            for (int nt = 0; nt < 4; nt++) {
                int w0 = (wn * 32 + nt * 8 + g) * LDW + kw + t;
                bh[nt][0] = Bhw[w0]; bh[nt][1] = Bhw[w0 + 4];
                bl[nt][0] = Blw[w0]; bl[nt][1] = Blw[w0 + 4];
            }
            #pragma unroll
            for (int mt = 0; mt < 2; mt++) {
                int w0 = (wm * 32 + mt * 16 + g) * LDW + kw + t;
                uint32_t ah[4], al[4];
                ah[0] = Ahw[w0]; ah[1] = Ahw[w0 + 8 * LDW];
                ah[2] = Ahw[w0 + 4]; ah[3] = Ahw[w0 + 8 * LDW + 4];
                al[0] = Alw[w0]; al[1] = Alw[w0 + 8 * LDW];
                al[2] = Alw[w0 + 4]; al[3] = Alw[w0 + 8 * LDW + 4];
                #pragma unroll
                for (int nt = 0; nt < 4; nt++) {
                    mma_bf16(acc[mt][nt], ah, bh[nt]);
                    mma_bf16(acc[mt][nt], ah, bl[nt]);
                    mma_bf16(acc[mt][nt], al, bh[nt]);
                }
            }
        }
    };

    stage(0, 0); CP_COMMIT();
    CP_WAIT0(); __syncthreads();
    #pragma unroll
    for (int c = 0; c < 4; c++) {
        int buf = c & 1;
        if (c < 3) { stage(c + 1, buf ^ 1); CP_COMMIT(); }
        compute(buf);
        if (c < 3) { CP_WAIT0(); __syncthreads(); }
    }

    #pragma unroll
    for (int mt = 0; mt < 2; mt++) {
        int row0 = bm + wm * 32 + mt * 16 + g;
        int row1 = row0 + 8;
        float s0 = 0.f, s1 = 0.f, d0 = 0.f, d1 = 0.f;
        #pragma unroll
        for (int nt = 0; nt < 4; nt++) {
            int lcol = wn * 32 + nt * 8 + 2 * t;
            float as0 = sAs[lcol], as1 = sAs[lcol + 1];
            float ad0 = sAd[lcol], ad1 = sAd[lcol + 1];
            s0 += acc[mt][nt][0] * as0 + acc[mt][nt][1] * as1;
            s1 += acc[mt][nt][2] * as0 + acc[mt][nt][3] * as1;
            d0 += acc[mt][nt][0] * ad0 + acc[mt][nt][1] * ad1;
            d1 += acc[mt][nt][2] * ad0 + acc[mt][nt][3] * ad1;
            if (lcol < OC) {
                if (row0 < Nn)
                    *(float2*)(g_h2 + (size_t)row0 * OC + lcol) = make_float2(acc[mt][nt][0], acc[mt][nt][1]);
                if (row1 < Nn)
                    *(float2*)(g_h2 + (size_t)row1 * OC + lcol) = make_float2(acc[mt][nt][2], acc[mt][nt][3]);
            }
        }
        s0 += __shfl_down_sync(0xffffffffu, s0, 2); s0 += __shfl_down_sync(0xffffffffu, s0, 1);
        s1 += __shfl_down_sync(0xffffffffu, s1, 2); s1 += __shfl_down_sync(0xffffffffu, s1, 1);
        d0 += __shfl_down_sync(0xffffffffu, d0, 2); d0 += __shfl_down_sync(0xffffffffu, d0, 1);
        d1 += __shfl_down_sync(0xffffffffu, d1, 2); d1 += __shfl_down_sync(0xffffffffu, d1, 1);
        if (t == 0) {
            int r0 = wm * 32 + mt * 16 + g, r1 = r0 + 8;
            atomicAdd(&red2[0][r0], s0);
            atomicAdd(&red2[0][r1], s1);
            atomicAdd(&red2[1][r0], d0);
            atomicAdd(&red2[1][r1], d1);
        }
    }
    __syncthreads();
    if (tid < 128) {
        int n = bm + tid;
        if (n < Nn) {
            g_als2[n] = red2[0][tid];
            g_ald2[n] = red2[1][tid];
        }
    }
}

// ---------------- layer 1 single-pass softmax+agg+bias+relu+split -------------
__global__ __launch_bounds__(256) void agg1_kernel(const float* __restrict__ b1) {
    int d = blockIdx.x;
    int start = g_rowptr[d], end = g_rowptr[d + 1];
    int tid = threadIdx.x;
    __shared__ float sden[NH];
    __shared__ int ssrc[128];
    __shared__ float salpha[128 * NH];
    __shared__ float4 sacc[4 * 64];

    if (tid < NH) sden[tid] = 1e-16f;
    float4 aldv = *(const float4*)&g_ald1[d * NH];

    const int ch4 = tid & 63;
    const int slot = tid >> 6;
    const int head = ch4 >> 4;
    float4 acc = make_float4(0.f, 0.f, 0.f, 0.f);
    float p0 = 0.f, p1 = 0.f, p2 = 0.f, p3 = 0.f;

    for (int base = start; base < end; base += 128) {
        int cnt = min(128, end - base);
        __syncthreads();
        if (tid < cnt) {
            int s = g_srcl[base + tid];
            ssrc[tid] = s;
            float4 als = *(const float4*)&g_als1[s * NH];
            float e0 = __expf(lrelu(als.x + aldv.x));
            float e1 = __expf(lrelu(als.y + aldv.y));
            float e2 = __expf(lrelu(als.z + aldv.z));
            float e3 = __expf(lrelu(als.w + aldv.w));
            salpha[tid * 4 + 0] = e0; salpha[tid * 4 + 1] = e1;
            salpha[tid * 4 + 2] = e2; salpha[tid * 4 + 3] = e3;
            p0 += e0; p1 += e1; p2 += e2; p3 += e3;
        }
        __syncthreads();
        for (int j = slot; j < cnt; j += 4) {
            float a = salpha[j * 4 + head];
            int s = ssrc[j];
            float4 h = *((const float4*)(g_h1 + (size_t)s * HC) + ch4);
            acc.x = fmaf(a, h.x, acc.x);
            acc.y = fmaf(a, h.y, acc.y);
            acc.z = fmaf(a, h.z, acc.z);
            acc.w = fmaf(a, h.w, acc.w);
        }
    }
    #pragma unroll
    for (int off = 16; off; off >>= 1) {
        p0 += __shfl_down_sync(0xffffffffu, p0, off);
        p1 += __shfl_down_sync(0xffffffffu, p1, off);
        p2 += __shfl_down_sync(0xffffffffu, p2, off);
        p3 += __shfl_down_sync(0xffffffffu, p3, off);
    }
    if ((tid & 31) == 0) {
        atomicAdd(&sden[0], p0);
        atomicAdd(&sden[1], p1);
        atomicAdd(&sden[2], p2);
        atomicAdd(&sden[3], p3);
    }
    sacc[slot * 64 + ch4] = acc;
    __syncthreads();
    if (tid < 64) {
        float4 a0 = sacc[tid], a1 = sacc[64 + tid], a2 = sacc[128 + tid], a3 = sacc[192 + tid];
        float rd = 1.f / sden[tid >> 4];
        int ch = tid * 4;
        float4 bb = *(const float4*)(b1 + ch);
        float4 r;
        r.x = fmaxf((a0.x + a1.x + a2.x + a3.x) * rd + bb.x, 0.f);
        r.y = fmaxf((a0.y + a1.y + a2.y + a3.y) * rd + bb.y, 0.f);
        r.z = fmaxf((a0.z + a1.z + a2.z + a3.z) * rd + bb.z, 0.f);
        r.w = fmaxf((a0.w + a1.w + a2.w + a3.w) * rd + bb.w, 0.f);
        uint2 hh, ll;
        split4(r, hh, ll);
        *(uint2*)(g_a1h + (size_t)d * HC + ch) = hh;
        *(uint2*)(g_a1l + (size_t)d * HC + ch) = ll;
    }
}

// ---------------- layer 2 single-pass agg + log_softmax ----------------------
__global__ void agg2_final(const float* __restrict__ b2, float* __restrict__ out) {
    int n = blockIdx.x * 8 + (threadIdx.x >> 5);
    if (n >= Nn) return;
    int lane = threadIdx.x & 31;
    int start = g_rowptr[n], end = g_rowptr[n + 1];
    float ald = g_ald2[n];

    float den = 0.f, acc0 = 0.f, acc1 = 0.f;
    for (int base = start; base < end; base += 32) {
        int i = base + lane;
        int s = 0; float e = 0.f;
        if (i < end) {
            s = g_srcl[i];
            e = __expf(lrelu(g_als2[s] + ald));
        }
        den += e;
        int cnt = min(32, end - base);
        for (int j = 0; j < cnt; j++) {
            int   sj = __shfl_sync(0xffffffffu, s, j);
            float ej = __shfl_sync(0xffffffffu, e, j);
            acc0 = fmaf(ej, g_h2[sj * OC + lane], acc0);
            if (lane < 8) acc1 = fmaf(ej, g_h2[sj * OC + 32 + lane], acc1);
        }
    }
    #pragma unroll
    for (int off = 16; off; off >>= 1)
        den += __shfl_xor_sync(0xffffffffu, den, off);
    float rden = 1.f / (den + 1e-16f);

    float v0 = acc0 * rden + b2[lane];
    float v1 = (lane < 8) ? (acc1 * rden + b2[32 + lane]) : -3.402823466e38f;
    float mx = fmaxf(v0, v1);
    #pragma unroll
    for (int off = 16; off; off >>= 1)
        mx = fmaxf(mx, __shfl_xor_sync(0xffffffffu, mx, off));
    float se = expf(v0 - mx) + ((lane < 8) ? expf(v1 - mx) : 0.f);
    #pragma unroll
    for (int off = 16; off; off >>= 1)
        se += __shfl_xor_sync(0xffffffffu, se, off);
    float lse = mx + logf(se);
    out[n * OC + lane] = v0 - lse;
    if (lane < 8) out[n * OC + 32 + lane] = v1 - lse;
}

// ---------------- launch -----------------------------------------------------
extern "C" void kernel_launch(void* const* d_in, const int* in_sizes, int n_in,
                              void* d_out, int out_size) {
    const float* x      = (const float*)d_in[0];
    const int*   ei     = (const int*)d_in[1];
    const float* W1     = (const float*)d_in[2];
    const float* a_src1 = (const float*)d_in[3];
    const float* a_dst1 = (const float*)d_in[4];
    const float* b1     = (const float*)d_in[5];
    const float* W2     = (const float*)d_in[6];
    const float* a_src2 = (const float*)d_in[7];
    const float* a_dst2 = (const float*)d_in[8];
    const float* b2     = (const float*)d_in[9];
    float* out = (float*)d_out;

    cudaFuncSetAttribute(gemm1_mma, cudaFuncAttributeMaxDynamicSharedMemorySize, G1_SMEM);
    cudaFuncSetAttribute(gemm2_mma, cudaFuncAttributeMaxDynamicSharedMemorySize, G2_SMEM);

    int eblocks = (ET + 255) / 256;

    init_kernel<<<NB, 256>>>();
    hist_kernel<<<eblocks, 256>>>(ei);
    scan_part<<<NB, 256>>>();
    scan_top<<<1, 256>>>();
    scan_add<<<NB, 256>>>();
    fill_kernel<<<eblocks, 256>>>(ei);

    convert_w1<<<(INC * HC + 255) / 256, 256>>>(W1);
    convert_w2<<<(64 * INC + 255) / 256, 256>>>(W2);

    gemm1_mma<<<MTILES * 2, 256, G1_SMEM>>>(x, a_src1, a_dst1);
    agg1_kernel<<<Nn, 256>>>(b1);

    gemm2_mma<<<MTILES, 256, G2_SMEM>>>(a_src2, a_dst2);
    agg2_final<<<(Nn + 7) / 8, 256>>>(b2, out);
}

// round 7
// speedup vs baseline: 4.3803x; 1.0185x over previous
#include <cuda_runtime.h>
#include <cuda_bf16.h>
#include <cstdint>

#define Nn 50000
#define Ee 800000
#define ET (Ee + Nn)
#define INC 256
#define HC 256
#define NH 4
#define OC 40
#define NB ((Nn + 255) / 256)

#define MT 128
#define MTILES ((Nn + MT - 1) / MT)
#define PADN (MTILES * MT)

// ---------------- scratch ----------------------------------------------------
__device__ float g_h1[(size_t)Nn * HC];
__device__ float g_als1[Nn * NH];
__device__ float g_ald1[Nn * NH];
__device__ float g_h2[Nn * OC];
__device__ float g_als2[Nn];
__device__ float g_ald2[Nn];
__device__ int g_counts[Nn];
__device__ int g_fill[Nn];
__device__ int g_rowptr[Nn + 1];
__device__ int g_srcl[ET];
__device__ int g_bsum[NB];
__device__ int g_boff[NB];
__device__ __align__(16) __nv_bfloat16 g_w1h[INC * HC];
__device__ __align__(16) __nv_bfloat16 g_w1l[INC * HC];
__device__ __align__(16) __nv_bfloat16 g_w2h[64 * INC];
__device__ __align__(16) __nv_bfloat16 g_w2l[64 * INC];
__device__ __align__(16) __nv_bfloat16 g_a1h[(size_t)PADN * HC];
__device__ __align__(16) __nv_bfloat16 g_a1l[(size_t)PADN * HC];

// ---------------- helpers ----------------------------------------------------
__device__ __forceinline__ float lrelu(float v) { return (v > 0.f) ? v : 0.2f * v; }
__device__ __forceinline__ uint32_t pack2(__nv_bfloat16 a, __nv_bfloat16 b) {
    __nv_bfloat162 t; t.x = a; t.y = b;
    return *reinterpret_cast<uint32_t*>(&t);
}
__device__ __forceinline__ void split4(float4 v, uint2& hh, uint2& ll) {
    __nv_bfloat16 h0 = __float2bfloat16(v.x), h1 = __float2bfloat16(v.y);
    __nv_bfloat16 h2 = __float2bfloat16(v.z), h3 = __float2bfloat16(v.w);
    __nv_bfloat16 l0 = __float2bfloat16(v.x - __bfloat162float(h0));
    __nv_bfloat16 l1 = __float2bfloat16(v.y - __bfloat162float(h1));
    __nv_bfloat16 l2 = __float2bfloat16(v.z - __bfloat162float(h2));
    __nv_bfloat16 l3 = __float2bfloat16(v.w - __bfloat162float(h3));
    hh.x = pack2(h0, h1); hh.y = pack2(h2, h3);
    ll.x = pack2(l0, l1); ll.y = pack2(l2, l3);
}
__device__ __forceinline__ uint32_t smem_u32(const void* p) {
    uint32_t a;
    asm("{ .reg .u64 t; cvta.to.shared.u64 t, %1; cvt.u32.u64 %0, t; }" : "=r"(a) : "l"(p));
    return a;
}
__device__ __forceinline__ void cp16(uint32_t dst, const void* src) {
    asm volatile("cp.async.ca.shared.global [%0], [%1], 16;" :: "r"(dst), "l"(src));
}
#define CP_COMMIT() asm volatile("cp.async.commit_group;" ::: "memory")
#define CP_WAIT0()  asm volatile("cp.async.wait_group 0;" ::: "memory")

// ---------------- init / CSR build -------------------------------------------
__global__ void init_kernel() {
    int i = blockIdx.x * blockDim.x + threadIdx.x;
    if (i < Nn) { g_counts[i] = 1; g_fill[i] = 0; }   // 1 = self loop baked in
}
__global__ void hist_kernel(const int* __restrict__ ei) {
    int i = blockIdx.x * blockDim.x + threadIdx.x;
    if (i >= Ee / 4) return;
    int4 d = ((const int4*)(ei + Ee))[i];
    atomicAdd(&g_counts[d.x], 1);
    atomicAdd(&g_counts[d.y], 1);
    atomicAdd(&g_counts[d.z], 1);
    atomicAdd(&g_counts[d.w], 1);
}
__device__ __forceinline__ int block_incl_scan(int v, int* ws) {
    int lane = threadIdx.x & 31, warp = threadIdx.x >> 5;
    #pragma unroll
    for (int o = 1; o < 32; o <<= 1) {
        int u = __shfl_up_sync(0xffffffffu, v, o);
        if (lane >= o) v += u;
    }
    if (lane == 31) ws[warp] = v;
    __syncthreads();
    if (warp == 0 && lane < 8) {
        int w = ws[lane];
        #pragma unroll
        for (int o = 1; o < 8; o <<= 1) {
            int u = __shfl_up_sync(0xffu, w, o);
            if (lane >= o) w += u;
        }
        ws[lane] = w;
    }
    __syncthreads();
    if (warp > 0) v += ws[warp - 1];
    return v;
}
__global__ void scan_part() {
    __shared__ int ws[8];
    int idx = blockIdx.x * 256 + threadIdx.x;
    int v = (idx < Nn) ? g_counts[idx] : 0;
    int incl = block_incl_scan(v, ws);
    if (idx < Nn) g_rowptr[idx + 1] = incl;
    if (threadIdx.x == 255) g_bsum[blockIdx.x] = incl;
}
__global__ void scan_top() {
    __shared__ int ws[8];
    int t = threadIdx.x;
    int v = (t < NB) ? g_bsum[t] : 0;
    int incl = block_incl_scan(v, ws);
    if (t < NB) g_boff[t] = incl - v;
    if (t == 0) g_rowptr[0] = 0;
}
__global__ void scan_add() {
    int idx = blockIdx.x * 256 + threadIdx.x;
    if (idx < Nn) g_rowptr[idx + 1] += g_boff[blockIdx.x];
}
__global__ void fill_kernel(const int* __restrict__ ei) {
    const int Q = Ee / 4;
    int i = blockIdx.x * blockDim.x + threadIdx.x;
    if (i < Q) {
        int4 s = ((const int4*)ei)[i];
        int4 d = ((const int4*)(ei + Ee))[i];
        int p;
        p = g_rowptr[d.x] + atomicAdd(&g_fill[d.x], 1); g_srcl[p] = s.x;
        p = g_rowptr[d.y] + atomicAdd(&g_fill[d.y], 1); g_srcl[p] = s.y;
        p = g_rowptr[d.z] + atomicAdd(&g_fill[d.z], 1); g_srcl[p] = s.z;
        p = g_rowptr[d.w] + atomicAdd(&g_fill[d.w], 1); g_srcl[p] = s.w;
    } else {
        int n = i - Q;
        if (n < Nn) {
            int p = g_rowptr[n] + atomicAdd(&g_fill[n], 1);
            g_srcl[p] = n;
        }
    }
}

// ---------------- merged weight convert ---------------------------------------
__global__ void convert_w(const float* __restrict__ W1, const float* __restrict__ W2) {
    int t = blockIdx.x * blockDim.x + threadIdx.x;
    if (t < INC * HC) {
        int k = t >> 8, n = t & 255;
        float v = W1[t];
        __nv_bfloat16 h = __float2bfloat16(v);
        g_w1h[n * INC + k] = h;
        g_w1l[n * INC + k] = __float2bfloat16(v - __bfloat162float(h));
    } else if (t < INC * HC + 64 * INC) {
        int u = t - INC * HC;
        int n = u >> 8, k = u & 255;
        float v = (n < OC) ? W2[k * OC + n] : 0.f;
        __nv_bfloat16 h = __float2bfloat16(v);
        g_w2h[n * INC + k] = h;
        g_w2l[n * INC + k] = __float2bfloat16(v - __bfloat162float(h));
    }
}

// ---------------- GEMM common ---------------------------------------------------
#define LDW 36
#define LDB 144
#define ATILE (128 * LDB)

__device__ __forceinline__ void mma_bf16(float* c, const uint32_t* a, const uint32_t* b) {
    asm volatile(
        "mma.sync.aligned.m16n8k16.row.col.f32.bf16.bf16.f32 "
        "{%0,%1,%2,%3}, {%4,%5,%6,%7}, {%8,%9}, {%0,%1,%2,%3};"
        : "+f"(c[0]), "+f"(c[1]), "+f"(c[2]), "+f"(c[3])
        : "r"(a[0]), "r"(a[1]), "r"(a[2]), "r"(a[3]), "r"(b[0]), "r"(b[1]));
}

// ---------------- GEMM1: h1 = x @ W1, fused attn coef epilogue ----------------
#define G1_BUF (4 * ATILE)
#define G1_SMEM (2 * G1_BUF)

__global__ void __launch_bounds__(256, 1)
gemm1_mma(const float* __restrict__ X,
          const float* __restrict__ a_src, const float* __restrict__ a_dst) {
    extern __shared__ char smem[];
    __shared__ float sAs[256], sAd[256];
    __shared__ float red[2][2][2][64];

    const int tid = threadIdx.x;
    const int wid = tid >> 5;
    const int lane = tid & 31;
    const int wm = wid >> 2;
    const int wn = wid & 3;
    const int g = lane >> 2;
    const int t = lane & 3;
    const int hl = wn >> 1;

    const int bm = (blockIdx.x >> 1) * MT;
    const int bn = (blockIdx.x & 1) * 128;

    const uint32_t sb = smem_u32(smem);

    if (tid < 128) { sAs[tid] = a_src[bn + tid]; sAd[tid] = a_dst[bn + tid]; }
    else { sAs[tid] = 0.f; sAd[tid] = 0.f; }
    {
        float* rp = &red[0][0][0][0];
        #pragma unroll
        for (int i = 0; i < 4; i++) rp[i * 256 + tid] = 0.f;
    }

    float acc[4][4][4] = {};
    float4 aregs[8];

    auto loadA = [&](int c) {
        #pragma unroll
        for (int i = 0; i < 8; i++) {
            int idx = i * 256 + tid;
            int row = idx >> 4;
            int col4 = (idx & 15) * 4;
            int grow = bm + row;
            aregs[i] = (grow < Nn)
                ? *(const float4*)(X + (size_t)grow * INC + c * 64 + col4)
                : make_float4(0.f, 0.f, 0.f, 0.f);
        }
    };
    auto storeA = [&](int buf) {
        char* sAh = smem + buf * G1_BUF;
        char* sAl = sAh + ATILE;
        #pragma unroll
        for (int i = 0; i < 8; i++) {
            int idx = i * 256 + tid;
            int row = idx >> 4;
            int col4 = (idx & 15) * 4;
            uint2 hh, ll;
            split4(aregs[i], hh, ll);
            int so = row * LDB + col4 * 2;
            *(uint2*)(sAh + so) = hh;
            *(uint2*)(sAl + so) = ll;
        }
    };
    auto cpB = [&](int c, int buf) {
        uint32_t dBh = sb + buf * G1_BUF + 2 * ATILE;
        uint32_t dBl = dBh + ATILE;
        #pragma unroll
        for (int i = 0; i < 4; i++) {
            int idx = i * 256 + tid;
            int row = idx >> 3;
            int col8 = (idx & 7) * 8;
            size_t gb = (size_t)(bn + row) * INC + c * 64 + col8;
            uint32_t so = row * LDB + col8 * 2;
            cp16(dBh + so, g_w1h + gb);
            cp16(dBl + so, g_w1l + gb);
        }
    };
    auto compute = [&](int buf) {
        const uint32_t* Ahw = (const uint32_t*)(smem + buf * G1_BUF);
        const uint32_t* Alw = (const uint32_t*)(smem + buf * G1_BUF + ATILE);
        const uint32_t* Bhw = (const uint32_t*)(smem + buf * G1_BUF + 2 * ATILE);
        const uint32_t* Blw = (const uint32_t*)(smem + buf * G1_BUF + 3 * ATILE);
        #pragma unroll
        for (int kk = 0; kk < 4; kk++) {
            const int kw = kk * 8;
            uint32_t bh[4][2], bl[4][2];
            #pragma unroll
            for (int nt = 0; nt < 4; nt++) {
                int w0 = (wn * 32 + nt * 8 + g) * LDW + kw + t;
                bh[nt][0] = Bhw[w0]; bh[nt][1] = Bhw[w0 + 4];
                bl[nt][0] = Blw[w0]; bl[nt][1] = Blw[w0 + 4];
            }
            #pragma unroll
            for (int mt = 0; mt < 4; mt++) {
                int w0 = (wm * 64 + mt * 16 + g) * LDW + kw + t;
                uint32_t ah[4], al[4];
                ah[0] = Ahw[w0]; ah[1] = Ahw[w0 + 8 * LDW];
                ah[2] = Ahw[w0 + 4]; ah[3] = Ahw[w0 + 8 * LDW + 4];
                al[0] = Alw[w0]; al[1] = Alw[w0 + 8 * LDW];
                al[2] = Alw[w0 + 4]; al[3] = Alw[w0 + 8 * LDW + 4];
                #pragma unroll
                for (int nt = 0; nt < 4; nt++) {
                    mma_bf16(acc[mt][nt], ah, bh[nt]);
                    mma_bf16(acc[mt][nt], ah, bl[nt]);
                    mma_bf16(acc[mt][nt], al, bh[nt]);
                }
            }
        }
    };

    loadA(0); cpB(0, 0); CP_COMMIT(); storeA(0);
    CP_WAIT0(); __syncthreads();
    #pragma unroll
    for (int c = 0; c < 4; c++) {
        int buf = c & 1;
        if (c < 3) { loadA(c + 1); cpB(c + 1, buf ^ 1); CP_COMMIT(); }
        compute(buf);
        if (c < 3) { storeA(buf ^ 1); CP_WAIT0(); __syncthreads(); }
    }

    #pragma unroll
    for (int mt = 0; mt < 4; mt++) {
        int row0 = bm + wm * 64 + mt * 16 + g;
        int row1 = row0 + 8;
        float s0 = 0.f, s1 = 0.f, d0 = 0.f, d1 = 0.f;
        #pragma unroll
        for (int nt = 0; nt < 4; nt++) {
            int lcol = wn * 32 + nt * 8 + 2 * t;
            int col = bn + lcol;
            float as0 = sAs[lcol], as1 = sAs[lcol + 1];
            float ad0 = sAd[lcol], ad1 = sAd[lcol + 1];
            s0 += acc[mt][nt][0] * as0 + acc[mt][nt][1] * as1;
            s1 += acc[mt][nt][2] * as0 + acc[mt][nt][3] * as1;
            d0 += acc[mt][nt][0] * ad0 + acc[mt][nt][1] * ad1;
            d1 += acc[mt][nt][2] * ad0 + acc[mt][nt][3] * ad1;
            if (row0 < Nn)
                *(float2*)(g_h1 + (size_t)row0 * HC + col) = make_float2(acc[mt][nt][0], acc[mt][nt][1]);
            if (row1 < Nn)
                *(float2*)(g_h1 + (size_t)row1 * HC + col) = make_float2(acc[mt][nt][2], acc[mt][nt][3]);
        }
        s0 += __shfl_down_sync(0xffffffffu, s0, 2); s0 += __shfl_down_sync(0xffffffffu, s0, 1);
        s1 += __shfl_down_sync(0xffffffffu, s1, 2); s1 += __shfl_down_sync(0xffffffffu, s1, 1);
        d0 += __shfl_down_sync(0xffffffffu, d0, 2); d0 += __shfl_down_sync(0xffffffffu, d0, 1);
        d1 += __shfl_down_sync(0xffffffffu, d1, 2); d1 += __shfl_down_sync(0xffffffffu, d1, 1);
        if (t == 0) {
            int r0 = mt * 16 + g, r1 = r0 + 8;
            atomicAdd(&red[wm][hl][0][r0], s0);
            atomicAdd(&red[wm][hl][0][r1], s1);
            atomicAdd(&red[wm][hl][1][r0], d0);
            atomicAdd(&red[wm][hl][1][r1], d1);
        }
    }
    __syncthreads();
    if (tid < 128) {
        int n = bm + tid;
        if (n < Nn) {
            int w = tid >> 6, r = tid & 63;
            #pragma unroll
            for (int h = 0; h < 2; h++) {
                int head = (bn >> 6) + h;
                g_als1[n * NH + head] = red[w][h][0][r];
                g_ald1[n * NH + head] = red[w][h][1][r];
            }
        }
    }
}

// ---------------- GEMM2: h2 = agg1 @ W2, fused attn coef epilogue -------------
#define BTILE2 (64 * LDB)
#define G2_BUF (2 * ATILE + 2 * BTILE2)
#define G2_SMEM (2 * G2_BUF)

__global__ void __launch_bounds__(256, 1)
gemm2_mma(const float* __restrict__ a_src, const float* __restrict__ a_dst) {
    extern __shared__ char smem[];
    __shared__ float sAs[64], sAd[64];
    __shared__ float red2[2][128];

    const int tid = threadIdx.x;
    const int wid = tid >> 5;
    const int lane = tid & 31;
    const int wm = wid >> 1;
    const int wn = wid & 1;
    const int g = lane >> 2;
    const int t = lane & 3;

    const int bm = blockIdx.x * MT;
    const uint32_t sb = smem_u32(smem);

    if (tid < 64) { sAs[tid] = (tid < OC) ? a_src[tid] : 0.f;
                    sAd[tid] = (tid < OC) ? a_dst[tid] : 0.f; }
    if (tid < 128) { red2[0][tid] = 0.f; red2[1][tid] = 0.f; }

    float acc[2][4][4] = {};

    auto stage = [&](int c, int buf) {
        uint32_t dAh = sb + buf * G2_BUF;
        uint32_t dAl = dAh + ATILE;
        uint32_t dBh = dAl + ATILE;
        uint32_t dBl = dBh + BTILE2;
        #pragma unroll
        for (int i = 0; i < 4; i++) {
            int idx = i * 256 + tid;
            int row = idx >> 3;
            int col8 = (idx & 7) * 8;
            size_t ga = (size_t)(bm + row) * HC + c * 64 + col8;
            uint32_t so = row * LDB + col8 * 2;
            cp16(dAh + so, g_a1h + ga);
            cp16(dAl + so, g_a1l + ga);
        }
        #pragma unroll
        for (int i = 0; i < 2; i++) {
            int idx = i * 256 + tid;
            int row = idx >> 3;
            int col8 = (idx & 7) * 8;
            size_t gb = (size_t)row * INC + c * 64 + col8;
            uint32_t so = row * LDB + col8 * 2;
            cp16(dBh + so, g_w2h + gb);
            cp16(dBl + so, g_w2l + gb);
        }
    };
    auto compute = [&](int buf) {
        const uint32_t* Ahw = (const uint32_t*)(smem + buf * G2_BUF);
        const uint32_t* Alw = (const uint32_t*)(smem + buf * G2_BUF + ATILE);
        const uint32_t* Bhw = (const uint32_t*)(smem + buf * G2_BUF + 2 * ATILE);
        const uint32_t* Blw = (const uint32_t*)(smem + buf * G2_BUF + 2 * ATILE + BTILE2);
        #pragma unroll
        for (int kk = 0; kk < 4; kk++) {
            const int kw = kk * 8;
            uint32_t bh[4][2], bl[4][2];
            #pragma unroll
            for (int nt = 0; nt < 4; nt++) {
                int w0 = (wn * 32 + nt * 8 + g) * LDW + kw + t;
                bh[nt][0] = Bhw[w0]; bh[nt][1] = Bhw[w0 + 4];
                bl[nt][0] = Blw[w0]; bl[nt][1] = Blw[w0 + 4];
            }
            #pragma unroll
            for (int mt = 0; mt < 2; mt++) {
                int w0 = (wm * 32 + mt * 16 + g) * LDW + kw + t;
                uint32_t ah[4], al[4];
                ah[0] = Ahw[w0]; ah[1] = Ahw[w0 + 8 * LDW];
                ah[2] = Ahw[w0 + 4]; ah[3] = Ahw[w0 + 8 * LDW + 4];
                al[0] = Alw[w0]; al[1] = Alw[w0 + 8 * LDW];
                al[2] = Alw[w0 + 4]; al[3] = Alw[w0 + 8 * LDW + 4];
                #pragma unroll
                for (int nt = 0; nt < 4; nt++) {
                    mma_bf16(acc[mt][nt], ah, bh[nt]);
                    mma_bf16(acc[mt][nt], ah, bl[nt]);
                    mma_bf16(acc[mt][nt], al, bh[nt]);
                }
            }
        }
    };

    stage(0, 0); CP_COMMIT();
    CP_WAIT0(); __syncthreads();
    #pragma unroll
    for (int c = 0; c < 4; c++) {
        int buf = c & 1;
        if (c < 3) { stage(c + 1, buf ^ 1); CP_COMMIT(); }
        compute(buf);
        if (c < 3) { CP_WAIT0(); __syncthreads(); }
    }

    #pragma unroll
    for (int mt = 0; mt < 2; mt++) {
        int row0 = bm + wm * 32 + mt * 16 + g;
        int row1 = row0 + 8;
        float s0 = 0.f, s1 = 0.f, d0 = 0.f, d1 = 0.f;
        #pragma unroll
        for (int nt = 0; nt < 4; nt++) {
            int lcol = wn * 32 + nt * 8 + 2 * t;
            float as0 = sAs[lcol], as1 = sAs[lcol + 1];
            float ad0 = sAd[lcol], ad1 = sAd[lcol + 1];
            s0 += acc[mt][nt][0] * as0 + acc[mt][nt][1] * as1;
            s1 += acc[mt][nt][2] * as0 + acc[mt][nt][3] * as1;
            d0 += acc[mt][nt][0] * ad0 + acc[mt][nt][1] * ad1;
            d1 += acc[mt][nt][2] * ad0 + acc[mt][nt][3] * ad1;
            if (lcol < OC) {
                if (row0 < Nn)
                    *(float2*)(g_h2 + (size_t)row0 * OC + lcol) = make_float2(acc[mt][nt][0], acc[mt][nt][1]);
                if (row1 < Nn)
                    *(float2*)(g_h2 + (size_t)row1 * OC + lcol) = make_float2(acc[mt][nt][2], acc[mt][nt][3]);
            }
        }
        s0 += __shfl_down_sync(0xffffffffu, s0, 2); s0 += __shfl_down_sync(0xffffffffu, s0, 1);
        s1 += __shfl_down_sync(0xffffffffu, s1, 2); s1 += __shfl_down_sync(0xffffffffu, s1, 1);
        d0 += __shfl_down_sync(0xffffffffu, d0, 2); d0 += __shfl_down_sync(0xffffffffu, d0, 1);
        d1 += __shfl_down_sync(0xffffffffu, d1, 2); d1 += __shfl_down_sync(0xffffffffu, d1, 1);
        if (t == 0) {
            int r0 = wm * 32 + mt * 16 + g, r1 = r0 + 8;
            atomicAdd(&red2[0][r0], s0);
            atomicAdd(&red2[0][r1], s1);
            atomicAdd(&red2[1][r0], d0);
            atomicAdd(&red2[1][r1], d1);
        }
    }
    __syncthreads();
    if (tid < 128) {
        int n = bm + tid;
        if (n < Nn) {
            g_als2[n] = red2[0][tid];
            g_ald2[n] = red2[1][tid];
        }
    }
}

// ---------------- layer 1 single-pass softmax+agg+bias+relu+split -------------
__global__ __launch_bounds__(256) void agg1_kernel(const float* __restrict__ b1) {
    int d = blockIdx.x;
    int start = g_rowptr[d], end = g_rowptr[d + 1];
    int tid = threadIdx.x;
    __shared__ float sden[NH];
    __shared__ int ssrc[128];
    __shared__ float salpha[128 * NH];
    __shared__ float4 sacc[4 * 64];

    if (tid < NH) sden[tid] = 1e-16f;
    float4 aldv = *(const float4*)&g_ald1[d * NH];

    const int ch4 = tid & 63;
    const int slot = tid >> 6;
    const int head = ch4 >> 4;
    float4 acc = make_float4(0.f, 0.f, 0.f, 0.f);
    float p0 = 0.f, p1 = 0.f, p2 = 0.f, p3 = 0.f;

    for (int base = start; base < end; base += 128) {
        int cnt = min(128, end - base);
        __syncthreads();
        if (tid < cnt) {
            int s = g_srcl[base + tid];
            ssrc[tid] = s;
            float4 als = *(const float4*)&g_als1[s * NH];
            float e0 = __expf(lrelu(als.x + aldv.x));
            float e1 = __expf(lrelu(als.y + aldv.y));
            float e2 = __expf(lrelu(als.z + aldv.z));
            float e3 = __expf(lrelu(als.w + aldv.w));
            salpha[tid * 4 + 0] = e0; salpha[tid * 4 + 1] = e1;
            salpha[tid * 4 + 2] = e2; salpha[tid * 4 + 3] = e3;
            p0 += e0; p1 += e1; p2 += e2; p3 += e3;
        }
        __syncthreads();
        int j = slot;
        for (; j + 4 < cnt; j += 8) {
            float a0 = salpha[j * 4 + head];
            float a1 = salpha[(j + 4) * 4 + head];
            int s0 = ssrc[j], s1 = ssrc[j + 4];
            float4 h0 = *((const float4*)(g_h1 + (size_t)s0 * HC) + ch4);
            float4 h1 = *((const float4*)(g_h1 + (size_t)s1 * HC) + ch4);
            acc.x = fmaf(a0, h0.x, acc.x); acc.y = fmaf(a0, h0.y, acc.y);
            acc.z = fmaf(a0, h0.z, acc.z); acc.w = fmaf(a0, h0.w, acc.w);
            acc.x = fmaf(a1, h1.x, acc.x); acc.y = fmaf(a1, h1.y, acc.y);
            acc.z = fmaf(a1, h1.z, acc.z); acc.w = fmaf(a1, h1.w, acc.w);
        }
        for (; j < cnt; j += 4) {
            float a = salpha[j * 4 + head];
            int s = ssrc[j];
            float4 h = *((const float4*)(g_h1 + (size_t)s * HC) + ch4);
            acc.x = fmaf(a, h.x, acc.x);
            acc.y = fmaf(a, h.y, acc.y);
            acc.z = fmaf(a, h.z, acc.z);
            acc.w = fmaf(a, h.w, acc.w);
        }
    }
    #pragma unroll
    for (int off = 16; off; off >>= 1) {
        p0 += __shfl_down_sync(0xffffffffu, p0, off);
        p1 += __shfl_down_sync(0xffffffffu, p1, off);
        p2 += __shfl_down_sync(0xffffffffu, p2, off);
        p3 += __shfl_down_sync(0xffffffffu, p3, off);
    }
    if ((tid & 31) == 0) {
        atomicAdd(&sden[0], p0);
        atomicAdd(&sden[1], p1);
        atomicAdd(&sden[2], p2);
        atomicAdd(&sden[3], p3);
    }
    sacc[slot * 64 + ch4] = acc;
    __syncthreads();
    if (tid < 64) {
        float4 a0 = sacc[tid], a1 = sacc[64 + tid], a2 = sacc[128 + tid], a3 = sacc[192 + tid];
        float rd = 1.f / sden[tid >> 4];
        int ch = tid * 4;
        float4 bb = *(const float4*)(b1 + ch);
        float4 r;
        r.x = fmaxf((a0.x + a1.x + a2.x + a3.x) * rd + bb.x, 0.f);
        r.y = fmaxf((a0.y + a1.y + a2.y + a3.y) * rd + bb.y, 0.f);
        r.z = fmaxf((a0.z + a1.z + a2.z + a3.z) * rd + bb.z, 0.f);
        r.w = fmaxf((a0.w + a1.w + a2.w + a3.w) * rd + bb.w, 0.f);
        uint2 hh, ll;
        split4(r, hh, ll);
        *(uint2*)(g_a1h + (size_t)d * HC + ch) = hh;
        *(uint2*)(g_a1l + (size_t)d * HC + ch) = ll;
    }
}

// ---------------- layer 2 single-pass agg + log_softmax ----------------------
__global__ void agg2_final(const float* __restrict__ b2, float* __restrict__ out) {
    int n = blockIdx.x * 8 + (threadIdx.x >> 5);
    if (n >= Nn) return;
    int lane = threadIdx.x & 31;
    int start = g_rowptr[n], end = g_rowptr[n + 1];
    float ald = g_ald2[n];

    float den = 0.f, acc0 = 0.f, acc1 = 0.f;
    for (int base = start; base < end; base += 32) {
        int i = base + lane;
        int s = 0; float e = 0.f;
        if (i < end) {
            s = g_srcl[i];
            e = __expf(lrelu(g_als2[s] + ald));
        }
        den += e;
        int cnt = min(32, end - base);
        for (int j = 0; j < cnt; j++) {
            int   sj = __shfl_sync(0xffffffffu, s, j);
            float ej = __shfl_sync(0xffffffffu, e, j);
            acc0 = fmaf(ej, g_h2[sj * OC + lane], acc0);
            if (lane < 8) acc1 = fmaf(ej, g_h2[sj * OC + 32 + lane], acc1);
        }
    }
    #pragma unroll
    for (int off = 16; off; off >>= 1)
        den += __shfl_xor_sync(0xffffffffu, den, off);
    float rden = 1.f / (den + 1e-16f);

    float v0 = acc0 * rden + b2[lane];
    float v1 = (lane < 8) ? (acc1 * rden + b2[32 + lane]) : -3.402823466e38f;
    float mx = fmaxf(v0, v1);
    #pragma unroll
    for (int off = 16; off; off >>= 1)
        mx = fmaxf(mx, __shfl_xor_sync(0xffffffffu, mx, off));
    float se = expf(v0 - mx) + ((lane < 8) ? expf(v1 - mx) : 0.f);
    #pragma unroll
    for (int off = 16; off; off >>= 1)
        se += __shfl_xor_sync(0xffffffffu, se, off);
    float lse = mx + logf(se);
    out[n * OC + lane] = v0 - lse;
    if (lane < 8) out[n * OC + 32 + lane] = v1 - lse;
}

// ---------------- launch -----------------------------------------------------
extern "C" void kernel_launch(void* const* d_in, const int* in_sizes, int n_in,
                              void* d_out, int out_size) {
    const float* x      = (const float*)d_in[0];
    const int*   ei     = (const int*)d_in[1];
    const float* W1     = (const float*)d_in[2];
    const float* a_src1 = (const float*)d_in[3];
    const float* a_dst1 = (const float*)d_in[4];
    const float* b1     = (const float*)d_in[5];
    const float* W2     = (const float*)d_in[6];
    const float* a_src2 = (const float*)d_in[7];
    const float* a_dst2 = (const float*)d_in[8];
    const float* b2     = (const float*)d_in[9];
    float* out = (float*)d_out;

    cudaFuncSetAttribute(gemm1_mma, cudaFuncAttributeMaxDynamicSharedMemorySize, G1_SMEM);
    cudaFuncSetAttribute(gemm2_mma, cudaFuncAttributeMaxDynamicSharedMemorySize, G2_SMEM);

    // launch order puts gemm1_mma at slot 4 (the slot ncu profiles)
    convert_w<<<(INC * HC + 64 * INC + 255) / 256, 256>>>(W1, W2);   // 1
    init_kernel<<<NB, 256>>>();                                       // 2
    hist_kernel<<<(Ee / 4 + 255) / 256, 256>>>(ei);                   // 3
    gemm1_mma<<<MTILES * 2, 256, G1_SMEM>>>(x, a_src1, a_dst1);       // 4 <- profiled
    scan_part<<<NB, 256>>>();                                         // 5
    scan_top<<<1, 256>>>();                                           // 6
    scan_add<<<NB, 256>>>();                                          // 7
    fill_kernel<<<(Ee / 4 + Nn + 255) / 256, 256>>>(ei);              // 8
    agg1_kernel<<<Nn, 256>>>(b1);                                     // 9
    gemm2_mma<<<MTILES, 256, G2_SMEM>>>(a_src2, a_dst2);              // 10
    agg2_final<<<(Nn + 7) / 8, 256>>>(b2, out);                       // 11
}

// round 8
// speedup vs baseline: 4.6654x; 1.0651x over previous
#include <cuda_runtime.h>
#include <cuda_bf16.h>
#include <cstdint>

#define Nn 50000
#define Ee 800000
#define ET (Ee + Nn)
#define INC 256
#define HC 256
#define NH 4
#define OC 40
#define NB ((Nn + 255) / 256)

#define MT 128
#define MTILES ((Nn + MT - 1) / MT)
#define PADN (MTILES * MT)

// ---------------- scratch ----------------------------------------------------
__device__ float g_h1[(size_t)Nn * HC];
__device__ float g_als1[Nn * NH];
__device__ float g_ald1[Nn * NH];
__device__ float g_h2[Nn * OC];
__device__ float g_als2[Nn];
__device__ float g_ald2[Nn];
__device__ int g_counts[Nn];
__device__ int g_fill[Nn];
__device__ int g_rowptr[Nn + 1];
__device__ int g_srcl[ET];
__device__ int g_bsum[NB];
__device__ int g_boff[NB];
__device__ __align__(16) __nv_bfloat16 g_w1h[INC * HC];
__device__ __align__(16) __nv_bfloat16 g_w1l[INC * HC];
__device__ __align__(16) __nv_bfloat16 g_w2h[64 * INC];
__device__ __align__(16) __nv_bfloat16 g_w2l[64 * INC];
__device__ __align__(16) __nv_bfloat16 g_a1h[(size_t)PADN * HC];
__device__ __align__(16) __nv_bfloat16 g_a1l[(size_t)PADN * HC];

// ---------------- helpers ----------------------------------------------------
__device__ __forceinline__ float lrelu(float v) { return (v > 0.f) ? v : 0.2f * v; }
__device__ __forceinline__ uint32_t pack2(__nv_bfloat16 a, __nv_bfloat16 b) {
    __nv_bfloat162 t; t.x = a; t.y = b;
    return *reinterpret_cast<uint32_t*>(&t);
}
__device__ __forceinline__ void split4(float4 v, uint2& hh, uint2& ll) {
    __nv_bfloat16 h0 = __float2bfloat16(v.x), h1 = __float2bfloat16(v.y);
    __nv_bfloat16 h2 = __float2bfloat16(v.z), h3 = __float2bfloat16(v.w);
    __nv_bfloat16 l0 = __float2bfloat16(v.x - __bfloat162float(h0));
    __nv_bfloat16 l1 = __float2bfloat16(v.y - __bfloat162float(h1));
    __nv_bfloat16 l2 = __float2bfloat16(v.z - __bfloat162float(h2));
    __nv_bfloat16 l3 = __float2bfloat16(v.w - __bfloat162float(h3));
    hh.x = pack2(h0, h1); hh.y = pack2(h2, h3);
    ll.x = pack2(l0, l1); ll.y = pack2(l2, l3);
}
__device__ __forceinline__ uint32_t smem_u32(const void* p) {
    uint32_t a;
    asm("{ .reg .u64 t; cvta.to.shared.u64 t, %1; cvt.u32.u64 %0, t; }" : "=r"(a) : "l"(p));
    return a;
}
__device__ __forceinline__ void cp16(uint32_t dst, const void* src) {
    asm volatile("cp.async.ca.shared.global [%0], [%1], 16;" :: "r"(dst), "l"(src));
}
#define CP_COMMIT() asm volatile("cp.async.commit_group;" ::: "memory")
#define CP_WAIT0()  asm volatile("cp.async.wait_group 0;" ::: "memory")

// ---------------- init / CSR build -------------------------------------------
__global__ void init_kernel() {
    int i = blockIdx.x * blockDim.x + threadIdx.x;
    if (i < Nn) { g_counts[i] = 1; g_fill[i] = 0; }
}
__global__ void hist_kernel(const int* __restrict__ ei) {
    int i = blockIdx.x * blockDim.x + threadIdx.x;
    if (i >= Ee / 4) return;
    int4 d = ((const int4*)(ei + Ee))[i];
    atomicAdd(&g_counts[d.x], 1);
    atomicAdd(&g_counts[d.y], 1);
    atomicAdd(&g_counts[d.z], 1);
    atomicAdd(&g_counts[d.w], 1);
}
__device__ __forceinline__ int block_incl_scan(int v, int* ws) {
    int lane = threadIdx.x & 31, warp = threadIdx.x >> 5;
    #pragma unroll
    for (int o = 1; o < 32; o <<= 1) {
        int u = __shfl_up_sync(0xffffffffu, v, o);
        if (lane >= o) v += u;
    }
    if (lane == 31) ws[warp] = v;
    __syncthreads();
    if (warp == 0 && lane < 8) {
        int w = ws[lane];
        #pragma unroll
        for (int o = 1; o < 8; o <<= 1) {
            int u = __shfl_up_sync(0xffu, w, o);
            if (lane >= o) w += u;
        }
        ws[lane] = w;
    }
    __syncthreads();
    if (warp > 0) v += ws[warp - 1];
    return v;
}
__global__ void scan_part() {
    __shared__ int ws[8];
    int idx = blockIdx.x * 256 + threadIdx.x;
    int v = (idx < Nn) ? g_counts[idx] : 0;
    int incl = block_incl_scan(v, ws);
    if (idx < Nn) g_rowptr[idx + 1] = incl;
    if (threadIdx.x == 255) g_bsum[blockIdx.x] = incl;
}
__global__ void scan_top() {
    __shared__ int ws[8];
    int t = threadIdx.x;
    int v = (t < NB) ? g_bsum[t] : 0;
    int incl = block_incl_scan(v, ws);
    if (t < NB) g_boff[t] = incl - v;
    if (t == 0) g_rowptr[0] = 0;
}
__global__ void scan_add() {
    int idx = blockIdx.x * 256 + threadIdx.x;
    if (idx < Nn) g_rowptr[idx + 1] += g_boff[blockIdx.x];
}
__global__ void fill_kernel(const int* __restrict__ ei) {
    const int Q = Ee / 4;
    int i = blockIdx.x * blockDim.x + threadIdx.x;
    if (i < Q) {
        int4 s = ((const int4*)ei)[i];
        int4 d = ((const int4*)(ei + Ee))[i];
        int p;
        p = g_rowptr[d.x] + atomicAdd(&g_fill[d.x], 1); g_srcl[p] = s.x;
        p = g_rowptr[d.y] + atomicAdd(&g_fill[d.y], 1); g_srcl[p] = s.y;
        p = g_rowptr[d.z] + atomicAdd(&g_fill[d.z], 1); g_srcl[p] = s.z;
        p = g_rowptr[d.w] + atomicAdd(&g_fill[d.w], 1); g_srcl[p] = s.w;
    } else {
        int n = i - Q;
        if (n < Nn) {
            int p = g_rowptr[n] + atomicAdd(&g_fill[n], 1);
            g_srcl[p] = n;
        }
    }
}

// ---------------- merged weight convert ---------------------------------------
__global__ void convert_w(const float* __restrict__ W1, const float* __restrict__ W2) {
    int t = blockIdx.x * blockDim.x + threadIdx.x;
    if (t < INC * HC) {
        int k = t >> 8, n = t & 255;
        float v = W1[t];
        __nv_bfloat16 h = __float2bfloat16(v);
        g_w1h[n * INC + k] = h;
        g_w1l[n * INC + k] = __float2bfloat16(v - __bfloat162float(h));
    } else if (t < INC * HC + 64 * INC) {
        int u = t - INC * HC;
        int n = u >> 8, k = u & 255;
        float v = (n < OC) ? W2[k * OC + n] : 0.f;
        __nv_bfloat16 h = __float2bfloat16(v);
        g_w2h[n * INC + k] = h;
        g_w2l[n * INC + k] = __float2bfloat16(v - __bfloat162float(h));
    }
}

// ---------------- GEMM common ---------------------------------------------------
#define LDW 36
#define LDB 144
#define ATILE (128 * LDB)

__device__ __forceinline__ void mma_bf16(float* c, const uint32_t* a, const uint32_t* b) {
    asm volatile(
        "mma.sync.aligned.m16n8k16.row.col.f32.bf16.bf16.f32 "
        "{%0,%1,%2,%3}, {%4,%5,%6,%7}, {%8,%9}, {%0,%1,%2,%3};"
        : "+f"(c[0]), "+f"(c[1]), "+f"(c[2]), "+f"(c[3])
        : "r"(a[0]), "r"(a[1]), "r"(a[2]), "r"(a[3]), "r"(b[0]), "r"(b[1]));
}

// ---------------- GEMM1: h1 = x @ W1, fused attn coef epilogue ----------------
// 512 threads, 16 warps (4x4), warp tile 32x32, CTA 128x128, BK=64.
#define G1_BUF (4 * ATILE)
#define G1_SMEM (2 * G1_BUF)

__global__ void __launch_bounds__(512, 1)
gemm1_mma(const float* __restrict__ X,
          const float* __restrict__ a_src, const float* __restrict__ a_dst) {
    extern __shared__ char smem[];
    __shared__ float sAs[128], sAd[128];
    __shared__ float red[4][2][2][32];   // [wm][hl][s/d][row]

    const int tid = threadIdx.x;
    const int wid = tid >> 5;
    const int lane = tid & 31;
    const int wm = wid >> 2;       // 0..3, 32 rows each
    const int wn = wid & 3;        // 0..3, 32 cols each
    const int g = lane >> 2;
    const int t = lane & 3;
    const int hl = wn >> 1;

    const int bm = (blockIdx.x >> 1) * MT;
    const int bn = (blockIdx.x & 1) * 128;

    const uint32_t sb = smem_u32(smem);

    if (tid < 128) { sAs[tid] = a_src[bn + tid]; sAd[tid] = a_dst[bn + tid]; }
    ((float*)red)[tid] = 0.f;      // 512 floats, tid < 512

    float acc[2][4][4] = {};
    float4 aregs[4];

    auto loadA = [&](int c) {
        #pragma unroll
        for (int i = 0; i < 4; i++) {
            int idx = i * 512 + tid;
            int row = idx >> 4;
            int col4 = (idx & 15) * 4;
            int grow = bm + row;
            aregs[i] = (grow < Nn)
                ? *(const float4*)(X + (size_t)grow * INC + c * 64 + col4)
                : make_float4(0.f, 0.f, 0.f, 0.f);
        }
    };
    auto storeA = [&](int buf) {
        char* sAh = smem + buf * G1_BUF;
        char* sAl = sAh + ATILE;
        #pragma unroll
        for (int i = 0; i < 4; i++) {
            int idx = i * 512 + tid;
            int row = idx >> 4;
            int col4 = (idx & 15) * 4;
            uint2 hh, ll;
            split4(aregs[i], hh, ll);
            int so = row * LDB + col4 * 2;
            *(uint2*)(sAh + so) = hh;
            *(uint2*)(sAl + so) = ll;
        }
    };
    auto cpB = [&](int c, int buf) {
        uint32_t dBh = sb + buf * G1_BUF + 2 * ATILE;
        uint32_t dBl = dBh + ATILE;
        #pragma unroll
        for (int i = 0; i < 2; i++) {
            int idx = i * 512 + tid;
            int row = idx >> 3;
            int col8 = (idx & 7) * 8;
            size_t gb = (size_t)(bn + row) * INC + c * 64 + col8;
            uint32_t so = row * LDB + col8 * 2;
            cp16(dBh + so, g_w1h + gb);
            cp16(dBl + so, g_w1l + gb);
        }
    };
    auto compute = [&](int buf) {
        const uint32_t* Ahw = (const uint32_t*)(smem + buf * G1_BUF);
        const uint32_t* Alw = (const uint32_t*)(smem + buf * G1_BUF + ATILE);
        const uint32_t* Bhw = (const uint32_t*)(smem + buf * G1_BUF + 2 * ATILE);
        const uint32_t* Blw = (const uint32_t*)(smem + buf * G1_BUF + 3 * ATILE);
        #pragma unroll
        for (int kk = 0; kk < 4; kk++) {
            const int kw = kk * 8;
            uint32_t bh[4][2], bl[4][2];
            #pragma unroll
            for (int nt = 0; nt < 4; nt++) {
                int w0 = (wn * 32 + nt * 8 + g) * LDW + kw + t;
                bh[nt][0] = Bhw[w0]; bh[nt][1] = Bhw[w0 + 4];
                bl[nt][0] = Blw[w0]; bl[nt][1] = Blw[w0 + 4];
            }
            #pragma unroll
            for (int mt = 0; mt < 2; mt++) {
                int w0 = (wm * 32 + mt * 16 + g) * LDW + kw + t;
                uint32_t ah[4], al[4];
                ah[0] = Ahw[w0]; ah[1] = Ahw[w0 + 8 * LDW];
                ah[2] = Ahw[w0 + 4]; ah[3] = Ahw[w0 + 8 * LDW + 4];
                al[0] = Alw[w0]; al[1] = Alw[w0 + 8 * LDW];
                al[2] = Alw[w0 + 4]; al[3] = Alw[w0 + 8 * LDW + 4];
                #pragma unroll
                for (int nt = 0; nt < 4; nt++) {
                    mma_bf16(acc[mt][nt], ah, bh[nt]);
                    mma_bf16(acc[mt][nt], ah, bl[nt]);
                    mma_bf16(acc[mt][nt], al, bh[nt]);
                }
            }
        }
    };

    loadA(0); cpB(0, 0); CP_COMMIT(); storeA(0);
    CP_WAIT0(); __syncthreads();
    #pragma unroll
    for (int c = 0; c < 4; c++) {
        int buf = c & 1;
        if (c < 3) { loadA(c + 1); cpB(c + 1, buf ^ 1); CP_COMMIT(); }
        compute(buf);
        if (c < 3) { storeA(buf ^ 1); CP_WAIT0(); __syncthreads(); }
    }

    // ---- epilogue: h1 stores + attn dot-products ----
    #pragma unroll
    for (int mt = 0; mt < 2; mt++) {
        int row0 = bm + wm * 32 + mt * 16 + g;
        int row1 = row0 + 8;
        float s0 = 0.f, s1 = 0.f, d0 = 0.f, d1 = 0.f;
        #pragma unroll
        for (int nt = 0; nt < 4; nt++) {
            int lcol = wn * 32 + nt * 8 + 2 * t;
            int col = bn + lcol;
            float as0 = sAs[lcol], as1 = sAs[lcol + 1];
            float ad0 = sAd[lcol], ad1 = sAd[lcol + 1];
            s0 += acc[mt][nt][0] * as0 + acc[mt][nt][1] * as1;
            s1 += acc[mt][nt][2] * as0 + acc[mt][nt][3] * as1;
            d0 += acc[mt][nt][0] * ad0 + acc[mt][nt][1] * ad1;
            d1 += acc[mt][nt][2] * ad0 + acc[mt][nt][3] * ad1;
            if (row0 < Nn)
                *(float2*)(g_h1 + (size_t)row0 * HC + col) = make_float2(acc[mt][nt][0], acc[mt][nt][1]);
            if (row1 < Nn)
                *(float2*)(g_h1 + (size_t)row1 * HC + col) = make_float2(acc[mt][nt][2], acc[mt][nt][3]);
        }
        s0 += __shfl_down_sync(0xffffffffu, s0, 2); s0 += __shfl_down_sync(0xffffffffu, s0, 1);
        s1 += __shfl_down_sync(0xffffffffu, s1, 2); s1 += __shfl_down_sync(0xffffffffu, s1, 1);
        d0 += __shfl_down_sync(0xffffffffu, d0, 2); d0 += __shfl_down_sync(0xffffffffu, d0, 1);
        d1 += __shfl_down_sync(0xffffffffu, d1, 2); d1 += __shfl_down_sync(0xffffffffu, d1, 1);
        if (t == 0) {
            int r0 = mt * 16 + g, r1 = r0 + 8;
            atomicAdd(&red[wm][hl][0][r0], s0);
            atomicAdd(&red[wm][hl][0][r1], s1);
            atomicAdd(&red[wm][hl][1][r0], d0);
            atomicAdd(&red[wm][hl][1][r1], d1);
        }
    }
    __syncthreads();
    if (tid < 128) {
        int n = bm + tid;
        if (n < Nn) {
            int w = tid >> 5, r = tid & 31;
            #pragma unroll
            for (int h = 0; h < 2; h++) {
                int head = (bn >> 6) + h;
                g_als1[n * NH + head] = red[w][h][0][r];
                g_ald1[n * NH + head] = red[w][h][1][r];
            }
        }
    }
}

// ---------------- GEMM2: h2 = agg1 @ W2, fused attn coef epilogue -------------
// 512 threads, 16 warps (8x2), warp tile 16x32, CTA 128x64, BK=64.
#define BTILE2 (64 * LDB)
#define G2_BUF (2 * ATILE + 2 * BTILE2)
#define G2_SMEM (2 * G2_BUF)

__global__ void __launch_bounds__(512, 1)
gemm2_mma(const float* __restrict__ a_src, const float* __restrict__ a_dst) {
    extern __shared__ char smem[];
    __shared__ float sAs[64], sAd[64];
    __shared__ float red2[2][128];

    const int tid = threadIdx.x;
    const int wid = tid >> 5;
    const int lane = tid & 31;
    const int wm = wid >> 1;       // 0..7, 16 rows each
    const int wn = wid & 1;        // 0..1, 32 cols each
    const int g = lane >> 2;
    const int t = lane & 3;

    const int bm = blockIdx.x * MT;
    const uint32_t sb = smem_u32(smem);

    if (tid < 64) { sAs[tid] = (tid < OC) ? a_src[tid] : 0.f;
                    sAd[tid] = (tid < OC) ? a_dst[tid] : 0.f; }
    if (tid < 256) ((float*)red2)[tid] = 0.f;

    float acc[4][4] = {};

    auto stage = [&](int c, int buf) {
        uint32_t dAh = sb + buf * G2_BUF;
        uint32_t dAl = dAh + ATILE;
        uint32_t dBh = dAl + ATILE;
        uint32_t dBl = dBh + BTILE2;
        #pragma unroll
        for (int i = 0; i < 2; i++) {
            int idx = i * 512 + tid;
            int row = idx >> 3;
            int col8 = (idx & 7) * 8;
            size_t ga = (size_t)(bm + row) * HC + c * 64 + col8;
            uint32_t so = row * LDB + col8 * 2;
            cp16(dAh + so, g_a1h + ga);
            cp16(dAl + so, g_a1l + ga);
        }
        {
            int idx = tid;                 // 0..511 covers 64 rows
            int row = idx >> 3;
            int col8 = (idx & 7) * 8;
            size_t gb = (size_t)row * INC + c * 64 + col8;
            uint32_t so = row * LDB + col8 * 2;
            cp16(dBh + so, g_w2h + gb);
            cp16(dBl + so, g_w2l + gb);
        }
    };
    auto compute = [&](int buf) {
        const uint32_t* Ahw = (const uint32_t*)(smem + buf * G2_BUF);
        const uint32_t* Alw = (const uint32_t*)(smem + buf * G2_BUF + ATILE);
        const uint32_t* Bhw = (const uint32_t*)(smem + buf * G2_BUF + 2 * ATILE);
        const uint32_t* Blw = (const uint32_t*)(smem + buf * G2_BUF + 2 * ATILE + BTILE2);
        #pragma unroll
        for (int kk = 0; kk < 4; kk++) {
            const int kw = kk * 8;
            uint32_t bh[4][2], bl[4][2];
            #pragma unroll
            for (int nt = 0; nt < 4; nt++) {
                int w0 = (wn * 32 + nt * 8 + g) * LDW + kw + t;
                bh[nt][0] = Bhw[w0]; bh[nt][1] = Bhw[w0 + 4];
                bl[nt][0] = Blw[w0]; bl[nt][1] = Blw[w0 + 4];
            }
            {
                int w0 = (wm * 16 + g) * LDW + kw + t;
                uint32_t ah[4], al[4];
                ah[0] = Ahw[w0]; ah[1] = Ahw[w0 + 8 * LDW];
                ah[2] = Ahw[w0 + 4]; ah[3] = Ahw[w0 + 8 * LDW + 4];
                al[0] = Alw[w0]; al[1] = Alw[w0 + 8 * LDW];
                al[2] = Alw[w0 + 4]; al[3] = Alw[w0 + 8 * LDW + 4];
                #pragma unroll
                for (int nt = 0; nt < 4; nt++) {
                    mma_bf16(acc[nt], ah, bh[nt]);
                    mma_bf16(acc[nt], ah, bl[nt]);
                    mma_bf16(acc[nt], al, bh[nt]);
                }
            }
        }
    };

    stage(0, 0); CP_COMMIT();
    CP_WAIT0(); __syncthreads();
    #pragma unroll
    for (int c = 0; c < 4; c++) {
        int buf = c & 1;
        if (c < 3) { stage(c + 1, buf ^ 1); CP_COMMIT(); }
        compute(buf);
        if (c < 3) { CP_WAIT0(); __syncthreads(); }
    }

    {
        int row0 = bm + wm * 16 + g;
        int row1 = row0 + 8;
        float s0 = 0.f, s1 = 0.f, d0 = 0.f, d1 = 0.f;
        #pragma unroll
        for (int nt = 0; nt < 4; nt++) {
            int lcol = wn * 32 + nt * 8 + 2 * t;
            float as0 = sAs[lcol], as1 = sAs[lcol + 1];
            float ad0 = sAd[lcol], ad1 = sAd[lcol + 1];
            s0 += acc[nt][0] * as0 + acc[nt][1] * as1;
            s1 += acc[nt][2] * as0 + acc[nt][3] * as1;
            d0 += acc[nt][0] * ad0 + acc[nt][1] * ad1;
            d1 += acc[nt][2] * ad0 + acc[nt][3] * ad1;
            if (lcol < OC) {
                if (row0 < Nn)
                    *(float2*)(g_h2 + (size_t)row0 * OC + lcol) = make_float2(acc[nt][0], acc[nt][1]);
                if (row1 < Nn)
                    *(float2*)(g_h2 + (size_t)row1 * OC + lcol) = make_float2(acc[nt][2], acc[nt][3]);
            }
        }
        s0 += __shfl_down_sync(0xffffffffu, s0, 2); s0 += __shfl_down_sync(0xffffffffu, s0, 1);
        s1 += __shfl_down_sync(0xffffffffu, s1, 2); s1 += __shfl_down_sync(0xffffffffu, s1, 1);
        d0 += __shfl_down_sync(0xffffffffu, d0, 2); d0 += __shfl_down_sync(0xffffffffu, d0, 1);
        d1 += __shfl_down_sync(0xffffffffu, d1, 2); d1 += __shfl_down_sync(0xffffffffu, d1, 1);
        if (t == 0) {
            int r0 = wm * 16 + g, r1 = r0 + 8;
            atomicAdd(&red2[0][r0], s0);
            atomicAdd(&red2[0][r1], s1);
            atomicAdd(&red2[1][r0], d0);
            atomicAdd(&red2[1][r1], d1);
        }
    }
    __syncthreads();
    if (tid < 128) {
        int n = bm + tid;
        if (n < Nn) {
            g_als2[n] = red2[0][tid];
            g_ald2[n] = red2[1][tid];
        }
    }
}

// ---------------- layer 1 single-pass softmax+agg+bias+relu+split -------------
__global__ __launch_bounds__(256) void agg1_kernel(const float* __restrict__ b1) {
    int d = blockIdx.x;
    int start = g_rowptr[d], end = g_rowptr[d + 1];
    int tid = threadIdx.x;
    __shared__ float sden[NH];
    __shared__ int ssrc[128];
    __shared__ float salpha[128 * NH];
    __shared__ float4 sacc[4 * 64];

    if (tid < NH) sden[tid] = 1e-16f;
    float4 aldv = *(const float4*)&g_ald1[d * NH];

    const int ch4 = tid & 63;
    const int slot = tid >> 6;
    const int head = ch4 >> 4;
    float4 acc = make_float4(0.f, 0.f, 0.f, 0.f);
    float p0 = 0.f, p1 = 0.f, p2 = 0.f, p3 = 0.f;

    for (int base = start; base < end; base += 128) {
        int cnt = min(128, end - base);
        __syncthreads();
        if (tid < cnt) {
            int s = g_srcl[base + tid];
            ssrc[tid] = s;
            float4 als = *(const float4*)&g_als1[s * NH];
            float e0 = __expf(lrelu(als.x + aldv.x));
            float e1 = __expf(lrelu(als.y + aldv.y));
            float e2 = __expf(lrelu(als.z + aldv.z));
            float e3 = __expf(lrelu(als.w + aldv.w));
            salpha[tid * 4 + 0] = e0; salpha[tid * 4 + 1] = e1;
            salpha[tid * 4 + 2] = e2; salpha[tid * 4 + 3] = e3;
            p0 += e0; p1 += e1; p2 += e2; p3 += e3;
        }
        __syncthreads();
        int j = slot;
        for (; j + 4 < cnt; j += 8) {
            float a0 = salpha[j * 4 + head];
            float a1 = salpha[(j + 4) * 4 + head];
            int s0 = ssrc[j], s1 = ssrc[j + 4];
            float4 h0 = *((const float4*)(g_h1 + (size_t)s0 * HC) + ch4);
            float4 h1 = *((const float4*)(g_h1 + (size_t)s1 * HC) + ch4);
            acc.x = fmaf(a0, h0.x, acc.x); acc.y = fmaf(a0, h0.y, acc.y);
            acc.z = fmaf(a0, h0.z, acc.z); acc.w = fmaf(a0, h0.w, acc.w);
            acc.x = fmaf(a1, h1.x, acc.x); acc.y = fmaf(a1, h1.y, acc.y);
            acc.z = fmaf(a1, h1.z, acc.z); acc.w = fmaf(a1, h1.w, acc.w);
        }
        for (; j < cnt; j += 4) {
            float a = salpha[j * 4 + head];
            int s = ssrc[j];
            float4 h = *((const float4*)(g_h1 + (size_t)s * HC) + ch4);
            acc.x = fmaf(a, h.x, acc.x);
            acc.y = fmaf(a, h.y, acc.y);
            acc.z = fmaf(a, h.z, acc.z);
            acc.w = fmaf(a, h.w, acc.w);
        }
    }
    #pragma unroll
    for (int off = 16; off; off >>= 1) {
        p0 += __shfl_down_sync(0xffffffffu, p0, off);
        p1 += __shfl_down_sync(0xffffffffu, p1, off);
        p2 += __shfl_down_sync(0xffffffffu, p2, off);
        p3 += __shfl_down_sync(0xffffffffu, p3, off);
    }
    if ((tid & 31) == 0) {
        atomicAdd(&sden[0], p0);
        atomicAdd(&sden[1], p1);
        atomicAdd(&sden[2], p2);
        atomicAdd(&sden[3], p3);
    }
    sacc[slot * 64 + ch4] = acc;
    __syncthreads();
    if (tid < 64) {
        float4 a0 = sacc[tid], a1 = sacc[64 + tid], a2 = sacc[128 + tid], a3 = sacc[192 + tid];
        float rd = 1.f / sden[tid >> 4];
        int ch = tid * 4;
        float4 bb = *(const float4*)(b1 + ch);
        float4 r;
        r.x = fmaxf((a0.x + a1.x + a2.x + a3.x) * rd + bb.x, 0.f);
        r.y = fmaxf((a0.y + a1.y + a2.y + a3.y) * rd + bb.y, 0.f);
        r.z = fmaxf((a0.z + a1.z + a2.z + a3.z) * rd + bb.z, 0.f);
        r.w = fmaxf((a0.w + a1.w + a2.w + a3.w) * rd + bb.w, 0.f);
        uint2 hh, ll;
        split4(r, hh, ll);
        *(uint2*)(g_a1h + (size_t)d * HC + ch) = hh;
        *(uint2*)(g_a1l + (size_t)d * HC + ch) = ll;
    }
}

// ---------------- layer 2 single-pass agg + log_softmax ----------------------
__global__ void agg2_final(const float* __restrict__ b2, float* __restrict__ out) {
    int n = blockIdx.x * 8 + (threadIdx.x >> 5);
    if (n >= Nn) return;
    int lane = threadIdx.x & 31;
    int start = g_rowptr[n], end = g_rowptr[n + 1];
    float ald = g_ald2[n];

    float den = 0.f, acc0 = 0.f, acc1 = 0.f;
    for (int base = start; base < end; base += 32) {
        int i = base + lane;
        int s = 0; float e = 0.f;
        if (i < end) {
            s = g_srcl[i];
            e = __expf(lrelu(g_als2[s] + ald));
        }
        den += e;
        int cnt = min(32, end - base);
        for (int j = 0; j < cnt; j++) {
            int   sj = __shfl_sync(0xffffffffu, s, j);
            float ej = __shfl_sync(0xffffffffu, e, j);
            acc0 = fmaf(ej, g_h2[sj * OC + lane], acc0);
            if (lane < 8) acc1 = fmaf(ej, g_h2[sj * OC + 32 + lane], acc1);
        }
    }
    #pragma unroll
    for (int off = 16; off; off >>= 1)
        den += __shfl_xor_sync(0xffffffffu, den, off);
    float rden = 1.f / (den + 1e-16f);

    float v0 = acc0 * rden + b2[lane];
    float v1 = (lane < 8) ? (acc1 * rden + b2[32 + lane]) : -3.402823466e38f;
    float mx = fmaxf(v0, v1);
    #pragma unroll
    for (int off = 16; off; off >>= 1)
        mx = fmaxf(mx, __shfl_xor_sync(0xffffffffu, mx, off));
    float se = expf(v0 - mx) + ((lane < 8) ? expf(v1 - mx) : 0.f);
    #pragma unroll
    for (int off = 16; off; off >>= 1)
        se += __shfl_xor_sync(0xffffffffu, se, off);
    float lse = mx + logf(se);
    out[n * OC + lane] = v0 - lse;
    if (lane < 8) out[n * OC + 32 + lane] = v1 - lse;
}

// ---------------- launch -----------------------------------------------------
extern "C" void kernel_launch(void* const* d_in, const int* in_sizes, int n_in,
                              void* d_out, int out_size) {
    const float* x      = (const float*)d_in[0];
    const int*   ei     = (const int*)d_in[1];
    const float* W1     = (const float*)d_in[2];
    const float* a_src1 = (const float*)d_in[3];
    const float* a_dst1 = (const float*)d_in[4];
    const float* b1     = (const float*)d_in[5];
    const float* W2     = (const float*)d_in[6];
    const float* a_src2 = (const float*)d_in[7];
    const float* a_dst2 = (const float*)d_in[8];
    const float* b2     = (const float*)d_in[9];
    float* out = (float*)d_out;

    cudaFuncSetAttribute(gemm1_mma, cudaFuncAttributeMaxDynamicSharedMemorySize, G1_SMEM);
    cudaFuncSetAttribute(gemm2_mma, cudaFuncAttributeMaxDynamicSharedMemorySize, G2_SMEM);

    convert_w<<<(INC * HC + 64 * INC + 255) / 256, 256>>>(W1, W2);   // 1
    init_kernel<<<NB, 256>>>();                                       // 2
    hist_kernel<<<(Ee / 4 + 255) / 256, 256>>>(ei);                   // 3
    gemm1_mma<<<MTILES * 2, 512, G1_SMEM>>>(x, a_src1, a_dst1);       // 4 <- profiled
    scan_part<<<NB, 256>>>();                                         // 5
    scan_top<<<1, 256>>>();                                           // 6
    scan_add<<<NB, 256>>>();                                          // 7
    fill_kernel<<<(Ee / 4 + Nn + 255) / 256, 256>>>(ei);              // 8
    agg1_kernel<<<Nn, 256>>>(b1);                                     // 9
    gemm2_mma<<<MTILES, 512, G2_SMEM>>>(a_src2, a_dst2);              // 10
    agg2_final<<<(Nn + 7) / 8, 256>>>(b2, out);                       // 11
}

// round 9
// speedup vs baseline: 4.8542x; 1.0405x over previous
#include <cuda_runtime.h>
#include <cuda_bf16.h>
#include <cstdint>

#define Nn 50000
#define Ee 800000
#define ET (Ee + Nn)
#define INC 256
#define HC 256
#define NH 4
#define OC 40
#define NB ((Nn + 255) / 256)

#define MT 128
#define MTILES ((Nn + MT - 1) / MT)
#define PADN (MTILES * MT)
#define HBLK 391                      // hist blocks appended to gemm1 grid

// ---------------- scratch ----------------------------------------------------
__device__ float g_h1[(size_t)Nn * HC];
__device__ float g_als1[Nn * NH];
__device__ float g_ald1[Nn * NH];
__device__ float g_h2[Nn * OC];
__device__ float g_als2[Nn];
__device__ float g_ald2[Nn];
__device__ int g_counts[Nn];
__device__ int g_fill[Nn];
__device__ int g_rowptr[Nn + 1];
__device__ int g_srcl[ET];
__device__ int g_bsum[NB];
__device__ __align__(16) __nv_bfloat16 g_w1h[INC * HC];
__device__ __align__(16) __nv_bfloat16 g_w1l[INC * HC];
__device__ __align__(16) __nv_bfloat16 g_w2h[64 * INC];
__device__ __align__(16) __nv_bfloat16 g_w2l[64 * INC];
__device__ __align__(16) __nv_bfloat16 g_a1h[(size_t)PADN * HC];
__device__ __align__(16) __nv_bfloat16 g_a1l[(size_t)PADN * HC];

// ---------------- helpers ----------------------------------------------------
__device__ __forceinline__ float lrelu(float v) { return (v > 0.f) ? v : 0.2f * v; }
__device__ __forceinline__ uint32_t pack2(__nv_bfloat16 a, __nv_bfloat16 b) {
    __nv_bfloat162 t; t.x = a; t.y = b;
    return *reinterpret_cast<uint32_t*>(&t);
}
__device__ __forceinline__ void split4(float4 v, uint2& hh, uint2& ll) {
    __nv_bfloat16 h0 = __float2bfloat16(v.x), h1 = __float2bfloat16(v.y);
    __nv_bfloat16 h2 = __float2bfloat16(v.z), h3 = __float2bfloat16(v.w);
    __nv_bfloat16 l0 = __float2bfloat16(v.x - __bfloat162float(h0));
    __nv_bfloat16 l1 = __float2bfloat16(v.y - __bfloat162float(h1));
    __nv_bfloat16 l2 = __float2bfloat16(v.z - __bfloat162float(h2));
    __nv_bfloat16 l3 = __float2bfloat16(v.w - __bfloat162float(h3));
    hh.x = pack2(h0, h1); hh.y = pack2(h2, h3);
    ll.x = pack2(l0, l1); ll.y = pack2(l2, l3);
}
__device__ __forceinline__ uint32_t smem_u32(const void* p) {
    uint32_t a;
    asm("{ .reg .u64 t; cvta.to.shared.u64 t, %1; cvt.u32.u64 %0, t; }" : "=r"(a) : "l"(p));
    return a;
}
__device__ __forceinline__ void cp16(uint32_t dst, const void* src) {
    asm volatile("cp.async.ca.shared.global [%0], [%1], 16;" :: "r"(dst), "l"(src));
}
#define CP_COMMIT() asm volatile("cp.async.commit_group;" ::: "memory")
#define CP_WAIT0()  asm volatile("cp.async.wait_group 0;" ::: "memory")

// ---------------- convert_w + init (fused) -------------------------------------
__global__ void convert_w(const float* __restrict__ W1, const float* __restrict__ W2) {
    int t = blockIdx.x * blockDim.x + threadIdx.x;
    if (t < INC * HC) {
        int k = t >> 8, n = t & 255;
        float v = W1[t];
        __nv_bfloat16 h = __float2bfloat16(v);
        g_w1h[n * INC + k] = h;
        g_w1l[n * INC + k] = __float2bfloat16(v - __bfloat162float(h));
    } else if (t < INC * HC + 64 * INC) {
        int u = t - INC * HC;
        int n = u >> 8, k = u & 255;
        float v = (n < OC) ? W2[k * OC + n] : 0.f;
        __nv_bfloat16 h = __float2bfloat16(v);
        g_w2h[n * INC + k] = h;
        g_w2l[n * INC + k] = __float2bfloat16(v - __bfloat162float(h));
    }
    if (t < Nn) { g_counts[t] = 1; g_fill[t] = 0; }   // self loop baked in
}

// ---------------- scan (2 kernels) ---------------------------------------------
__device__ __forceinline__ int block_incl_scan(int v, int* ws) {
    int lane = threadIdx.x & 31, warp = threadIdx.x >> 5;
    #pragma unroll
    for (int o = 1; o < 32; o <<= 1) {
        int u = __shfl_up_sync(0xffffffffu, v, o);
        if (lane >= o) v += u;
    }
    if (lane == 31) ws[warp] = v;
    __syncthreads();
    if (warp == 0 && lane < 8) {
        int w = ws[lane];
        #pragma unroll
        for (int o = 1; o < 8; o <<= 1) {
            int u = __shfl_up_sync(0xffu, w, o);
            if (lane >= o) w += u;
        }
        ws[lane] = w;
    }
    __syncthreads();
    if (warp > 0) v += ws[warp - 1];
    return v;
}
__global__ void scan_part() {
    __shared__ int ws[8];
    int idx = blockIdx.x * 256 + threadIdx.x;
    int v = (idx < Nn) ? g_counts[idx] : 0;
    int incl = block_incl_scan(v, ws);
    if (idx < Nn) g_rowptr[idx + 1] = incl;
    if (threadIdx.x == 255) g_bsum[blockIdx.x] = incl;
}
// block j adds sum(bsum[0..j-1]) to its chunk (redundant reduce, no serial chain)
__global__ void scan_add2() {
    __shared__ int ws[8];
    int j = blockIdx.x;
    int tid = threadIdx.x;
    int lane = tid & 31, warp = tid >> 5;
    int v = (tid < j) ? g_bsum[tid] : 0;
    #pragma unroll
    for (int o = 16; o; o >>= 1) v += __shfl_down_sync(0xffffffffu, v, o);
    if (lane == 0) ws[warp] = v;
    __syncthreads();
    if (warp == 0) {
        int w = (lane < 8) ? ws[lane] : 0;
        #pragma unroll
        for (int o = 4; o; o >>= 1) w += __shfl_down_sync(0xffffffffu, w, o);
        if (lane == 0) ws[0] = w;
    }
    __syncthreads();
    int offset = ws[0];
    int idx = j * 256 + tid;
    if (idx < Nn) g_rowptr[idx + 1] += offset;
    if (j == 0 && tid == 0) g_rowptr[0] = 0;
}
__global__ void fill_kernel(const int* __restrict__ ei) {
    const int Q = Ee / 4;
    int i = blockIdx.x * blockDim.x + threadIdx.x;
    if (i < Q) {
        int4 s = ((const int4*)ei)[i];
        int4 d = ((const int4*)(ei + Ee))[i];
        int p;
        p = g_rowptr[d.x] + atomicAdd(&g_fill[d.x], 1); g_srcl[p] = s.x;
        p = g_rowptr[d.y] + atomicAdd(&g_fill[d.y], 1); g_srcl[p] = s.y;
        p = g_rowptr[d.z] + atomicAdd(&g_fill[d.z], 1); g_srcl[p] = s.z;
        p = g_rowptr[d.w] + atomicAdd(&g_fill[d.w], 1); g_srcl[p] = s.w;
    } else {
        int n = i - Q;
        if (n < Nn) {
            int p = g_rowptr[n] + atomicAdd(&g_fill[n], 1);
            g_srcl[p] = n;
        }
    }
}

// ---------------- GEMM common ---------------------------------------------------
#define LDW 36
#define LDB 144
#define ATILE (128 * LDB)

__device__ __forceinline__ void mma_bf16(float* c, const uint32_t* a, const uint32_t* b) {
    asm volatile(
        "mma.sync.aligned.m16n8k16.row.col.f32.bf16.bf16.f32 "
        "{%0,%1,%2,%3}, {%4,%5,%6,%7}, {%8,%9}, {%0,%1,%2,%3};"
        : "+f"(c[0]), "+f"(c[1]), "+f"(c[2]), "+f"(c[3])
        : "r"(a[0]), "r"(a[1]), "r"(a[2]), "r"(a[3]), "r"(b[0]), "r"(b[1]));
}

// ---------------- GEMM1 (+ hist blocks): h1 = x @ W1, fused attn coef ----------
#define G1_BUF (4 * ATILE)
#define G1_SMEM (2 * G1_BUF)

__global__ void __launch_bounds__(512, 1)
gemm1_mma(const float* __restrict__ X, const int* __restrict__ ei,
          const float* __restrict__ a_src, const float* __restrict__ a_dst) {
    // ---- histogram blocks (appended to grid, backfill SM tail) ----
    if (blockIdx.x >= MTILES * 2) {
        int i = (blockIdx.x - MTILES * 2) * 512 + threadIdx.x;
        if (i < Ee / 4) {
            int4 d = ((const int4*)(ei + Ee))[i];
            atomicAdd(&g_counts[d.x], 1);
            atomicAdd(&g_counts[d.y], 1);
            atomicAdd(&g_counts[d.z], 1);
            atomicAdd(&g_counts[d.w], 1);
        }
        return;
    }

    extern __shared__ char smem[];
    __shared__ float sAs[128], sAd[128];
    __shared__ float red[4][2][2][32];   // [wm][hl][s/d][row]

    const int tid = threadIdx.x;
    const int wid = tid >> 5;
    const int lane = tid & 31;
    const int wm = wid >> 2;
    const int wn = wid & 3;
    const int g = lane >> 2;
    const int t = lane & 3;
    const int hl = wn >> 1;

    const int bm = (blockIdx.x >> 1) * MT;
    const int bn = (blockIdx.x & 1) * 128;

    const uint32_t sb = smem_u32(smem);

    if (tid < 128) { sAs[tid] = a_src[bn + tid]; sAd[tid] = a_dst[bn + tid]; }
    ((float*)red)[tid] = 0.f;

    float acc[2][4][4] = {};
    float4 aregs[4];

    auto loadA = [&](int c) {
        #pragma unroll
        for (int i = 0; i < 4; i++) {
            int idx = i * 512 + tid;
            int row = idx >> 4;
            int col4 = (idx & 15) * 4;
            int grow = bm + row;
            aregs[i] = (grow < Nn)
                ? *(const float4*)(X + (size_t)grow * INC + c * 64 + col4)
                : make_float4(0.f, 0.f, 0.f, 0.f);
        }
    };
    auto storeA = [&](int buf) {
        char* sAh = smem + buf * G1_BUF;
        char* sAl = sAh + ATILE;
        #pragma unroll
        for (int i = 0; i < 4; i++) {
            int idx = i * 512 + tid;
            int row = idx >> 4;
            int col4 = (idx & 15) * 4;
            uint2 hh, ll;
            split4(aregs[i], hh, ll);
            int so = row * LDB + col4 * 2;
            *(uint2*)(sAh + so) = hh;
            *(uint2*)(sAl + so) = ll;
        }
    };
    auto cpB = [&](int c, int buf) {
        uint32_t dBh = sb + buf * G1_BUF + 2 * ATILE;
        uint32_t dBl = dBh + ATILE;
        #pragma unroll
        for (int i = 0; i < 2; i++) {
            int idx = i * 512 + tid;
            int row = idx >> 3;
            int col8 = (idx & 7) * 8;
            size_t gb = (size_t)(bn + row) * INC + c * 64 + col8;
            uint32_t so = row * LDB + col8 * 2;
            cp16(dBh + so, g_w1h + gb);
            cp16(dBl + so, g_w1l + gb);
        }
    };
    auto compute = [&](int buf) {
        const uint32_t* Ahw = (const uint32_t*)(smem + buf * G1_BUF);
        const uint32_t* Alw = (const uint32_t*)(smem + buf * G1_BUF + ATILE);
        const uint32_t* Bhw = (const uint32_t*)(smem + buf * G1_BUF + 2 * ATILE);
        const uint32_t* Blw = (const uint32_t*)(smem + buf * G1_BUF + 3 * ATILE);
        #pragma unroll
        for (int kk = 0; kk < 4; kk++) {
            const int kw = kk * 8;
            uint32_t bh[4][2], bl[4][2];
            #pragma unroll
            for (int nt = 0; nt < 4; nt++) {
                int w0 = (wn * 32 + nt * 8 + g) * LDW + kw + t;
                bh[nt][0] = Bhw[w0]; bh[nt][1] = Bhw[w0 + 4];
                bl[nt][0] = Blw[w0]; bl[nt][1] = Blw[w0 + 4];
            }
            #pragma unroll
            for (int mt = 0; mt < 2; mt++) {
                int w0 = (wm * 32 + mt * 16 + g) * LDW + kw + t;
                uint32_t ah[4], al[4];
                ah[0] = Ahw[w0]; ah[1] = Ahw[w0 + 8 * LDW];
                ah[2] = Ahw[w0 + 4]; ah[3] = Ahw[w0 + 8 * LDW + 4];
                al[0] = Alw[w0]; al[1] = Alw[w0 + 8 * LDW];
                al[2] = Alw[w0 + 4]; al[3] = Alw[w0 + 8 * LDW + 4];
                #pragma unroll
                for (int nt = 0; nt < 4; nt++) {
                    mma_bf16(acc[mt][nt], ah, bh[nt]);
                    mma_bf16(acc[mt][nt], ah, bl[nt]);
                    mma_bf16(acc[mt][nt], al, bh[nt]);
                }
            }
        }
    };

    loadA(0); cpB(0, 0); CP_COMMIT(); storeA(0);
    CP_WAIT0(); __syncthreads();
    #pragma unroll
    for (int c = 0; c < 4; c++) {
        int buf = c & 1;
        if (c < 3) { loadA(c + 1); cpB(c + 1, buf ^ 1); CP_COMMIT(); }
        compute(buf);
        if (c < 3) { storeA(buf ^ 1); CP_WAIT0(); __syncthreads(); }
    }

    // ---- epilogue: h1 stores + attn dot-products ----
    #pragma unroll
    for (int mt = 0; mt < 2; mt++) {
        int row0 = bm + wm * 32 + mt * 16 + g;
        int row1 = row0 + 8;
        float s0 = 0.f, s1 = 0.f, d0 = 0.f, d1 = 0.f;
        #pragma unroll
        for (int nt = 0; nt < 4; nt++) {
            int lcol = wn * 32 + nt * 8 + 2 * t;
            int col = bn + lcol;
            float as0 = sAs[lcol], as1 = sAs[lcol + 1];
            float ad0 = sAd[lcol], ad1 = sAd[lcol + 1];
            s0 += acc[mt][nt][0] * as0 + acc[mt][nt][1] * as1;
            s1 += acc[mt][nt][2] * as0 + acc[mt][nt][3] * as1;
            d0 += acc[mt][nt][0] * ad0 + acc[mt][nt][1] * ad1;
            d1 += acc[mt][nt][2] * ad0 + acc[mt][nt][3] * ad1;
            if (row0 < Nn)
                *(float2*)(g_h1 + (size_t)row0 * HC + col) = make_float2(acc[mt][nt][0], acc[mt][nt][1]);
            if (row1 < Nn)
                *(float2*)(g_h1 + (size_t)row1 * HC + col) = make_float2(acc[mt][nt][2], acc[mt][nt][3]);
        }
        s0 += __shfl_down_sync(0xffffffffu, s0, 2); s0 += __shfl_down_sync(0xffffffffu, s0, 1);
        s1 += __shfl_down_sync(0xffffffffu, s1, 2); s1 += __shfl_down_sync(0xffffffffu, s1, 1);
        d0 += __shfl_down_sync(0xffffffffu, d0, 2); d0 += __shfl_down_sync(0xffffffffu, d0, 1);
        d1 += __shfl_down_sync(0xffffffffu, d1, 2); d1 += __shfl_down_sync(0xffffffffu, d1, 1);
        if (t == 0) {
            int r0 = mt * 16 + g, r1 = r0 + 8;
            atomicAdd(&red[wm][hl][0][r0], s0);
            atomicAdd(&red[wm][hl][0][r1], s1);
            atomicAdd(&red[wm][hl][1][r0], d0);
            atomicAdd(&red[wm][hl][1][r1], d1);
        }
    }
    __syncthreads();
    if (tid < 128) {
        int n = bm + tid;
        if (n < Nn) {
            int w = tid >> 5, r = tid & 31;
            #pragma unroll
            for (int h = 0; h < 2; h++) {
                int head = (bn >> 6) + h;
                g_als1[n * NH + head] = red[w][h][0][r];
                g_ald1[n * NH + head] = red[w][h][1][r];
            }
        }
    }
}

// ---------------- GEMM2: h2 = agg1 @ W2, fused attn coef epilogue -------------
#define BTILE2 (64 * LDB)
#define G2_BUF (2 * ATILE + 2 * BTILE2)
#define G2_SMEM (2 * G2_BUF)

__global__ void __launch_bounds__(512, 1)
gemm2_mma(const float* __restrict__ a_src, const float* __restrict__ a_dst) {
    extern __shared__ char smem[];
    __shared__ float sAs[64], sAd[64];
    __shared__ float red2[2][128];

    const int tid = threadIdx.x;
    const int wid = tid >> 5;
    const int lane = tid & 31;
    const int wm = wid >> 1;
    const int wn = wid & 1;
    const int g = lane >> 2;
    const int t = lane & 3;

    const int bm = blockIdx.x * MT;
    const uint32_t sb = smem_u32(smem);

    if (tid < 64) { sAs[tid] = (tid < OC) ? a_src[tid] : 0.f;
                    sAd[tid] = (tid < OC) ? a_dst[tid] : 0.f; }
    if (tid < 256) ((float*)red2)[tid] = 0.f;

    float acc[4][4] = {};

    auto stage = [&](int c, int buf) {
        uint32_t dAh = sb + buf * G2_BUF;
        uint32_t dAl = dAh + ATILE;
        uint32_t dBh = dAl + ATILE;
        uint32_t dBl = dBh + BTILE2;
        #pragma unroll
        for (int i = 0; i < 2; i++) {
            int idx = i * 512 + tid;
            int row = idx >> 3;
            int col8 = (idx & 7) * 8;
            size_t ga = (size_t)(bm + row) * HC + c * 64 + col8;
            uint32_t so = row * LDB + col8 * 2;
            cp16(dAh + so, g_a1h + ga);
            cp16(dAl + so, g_a1l + ga);
        }
        {
            int idx = tid;
            int row = idx >> 3;
            int col8 = (idx & 7) * 8;
            size_t gb = (size_t)row * INC + c * 64 + col8;
            uint32_t so = row * LDB + col8 * 2;
            cp16(dBh + so, g_w2h + gb);
            cp16(dBl + so, g_w2l + gb);
        }
    };
    auto compute = [&](int buf) {
        const uint32_t* Ahw = (const uint32_t*)(smem + buf * G2_BUF);
        const uint32_t* Alw = (const uint32_t*)(smem + buf * G2_BUF + ATILE);
        const uint32_t* Bhw = (const uint32_t*)(smem + buf * G2_BUF + 2 * ATILE);
        const uint32_t* Blw = (const uint32_t*)(smem + buf * G2_BUF + 2 * ATILE + BTILE2);
        #pragma unroll
        for (int kk = 0; kk < 4; kk++) {
            const int kw = kk * 8;
            uint32_t bh[4][2], bl[4][2];
            #pragma unroll
            for (int nt = 0; nt < 4; nt++) {
                int w0 = (wn * 32 + nt * 8 + g) * LDW + kw + t;
                bh[nt][0] = Bhw[w0]; bh[nt][1] = Bhw[w0 + 4];
                bl[nt][0] = Blw[w0]; bl[nt][1] = Blw[w0 + 4];
            }
            {
                int w0 = (wm * 16 + g) * LDW + kw + t;
                uint32_t ah[4], al[4];
                ah[0] = Ahw[w0]; ah[1] = Ahw[w0 + 8 * LDW];
                ah[2] = Ahw[w0 + 4]; ah[3] = Ahw[w0 + 8 * LDW + 4];
                al[0] = Alw[w0]; al[1] = Alw[w0 + 8 * LDW];
                al[2] = Alw[w0 + 4]; al[3] = Alw[w0 + 8 * LDW + 4];
                #pragma unroll
                for (int nt = 0; nt < 4; nt++) {
                    mma_bf16(acc[nt], ah, bh[nt]);
                    mma_bf16(acc[nt], ah, bl[nt]);
                    mma_bf16(acc[nt], al, bh[nt]);
                }
            }
        }
    };

    stage(0, 0); CP_COMMIT();
    CP_WAIT0(); __syncthreads();
    #pragma unroll
    for (int c = 0; c < 4; c++) {
        int buf = c & 1;
        if (c < 3) { stage(c + 1, buf ^ 1); CP_COMMIT(); }
        compute(buf);
        if (c < 3) { CP_WAIT0(); __syncthreads(); }
    }

    {
        int row0 = bm + wm * 16 + g;
        int row1 = row0 + 8;
        float s0 = 0.f, s1 = 0.f, d0 = 0.f, d1 = 0.f;
        #pragma unroll
        for (int nt = 0; nt < 4; nt++) {
            int lcol = wn * 32 + nt * 8 + 2 * t;
            float as0 = sAs[lcol], as1 = sAs[lcol + 1];
            float ad0 = sAd[lcol], ad1 = sAd[lcol + 1];
            s0 += acc[nt][0] * as0 + acc[nt][1] * as1;
            s1 += acc[nt][2] * as0 + acc[nt][3] * as1;
            d0 += acc[nt][0] * ad0 + acc[nt][1] * ad1;
            d1 += acc[nt][2] * ad0 + acc[nt][3] * ad1;
            if (lcol < OC) {
                if (row0 < Nn)
                    *(float2*)(g_h2 + (size_t)row0 * OC + lcol) = make_float2(acc[nt][0], acc[nt][1]);
                if (row1 < Nn)
                    *(float2*)(g_h2 + (size_t)row1 * OC + lcol) = make_float2(acc[nt][2], acc[nt][3]);
            }
        }
        s0 += __shfl_down_sync(0xffffffffu, s0, 2); s0 += __shfl_down_sync(0xffffffffu, s0, 1);
        s1 += __shfl_down_sync(0xffffffffu, s1, 2); s1 += __shfl_down_sync(0xffffffffu, s1, 1);
        d0 += __shfl_down_sync(0xffffffffu, d0, 2); d0 += __shfl_down_sync(0xffffffffu, d0, 1);
        d1 += __shfl_down_sync(0xffffffffu, d1, 2); d1 += __shfl_down_sync(0xffffffffu, d1, 1);
        if (t == 0) {
            int r0 = wm * 16 + g, r1 = r0 + 8;
            atomicAdd(&red2[0][r0], s0);
            atomicAdd(&red2[0][r1], s1);
            atomicAdd(&red2[1][r0], d0);
            atomicAdd(&red2[1][r1], d1);
        }
    }
    __syncthreads();
    if (tid < 128) {
        int n = bm + tid;
        if (n < Nn) {
            g_als2[n] = red2[0][tid];
            g_ald2[n] = red2[1][tid];
        }
    }
}

// ---------------- layer 1 single-pass softmax+agg+bias+relu+split -------------
__global__ __launch_bounds__(256) void agg1_kernel(const float* __restrict__ b1) {
    int d = blockIdx.x;
    int start = g_rowptr[d], end = g_rowptr[d + 1];
    int tid = threadIdx.x;
    __shared__ float sden[NH];
    __shared__ int ssrc[128];
    __shared__ float salpha[128 * NH];
    __shared__ float4 sacc[4 * 64];

    if (tid < NH) sden[tid] = 1e-16f;
    float4 aldv = *(const float4*)&g_ald1[d * NH];

    const int ch4 = tid & 63;
    const int slot = tid >> 6;
    const int head = ch4 >> 4;
    float4 acc = make_float4(0.f, 0.f, 0.f, 0.f);
    float p0 = 0.f, p1 = 0.f, p2 = 0.f, p3 = 0.f;

    for (int base = start; base < end; base += 128) {
        int cnt = min(128, end - base);
        __syncthreads();
        if (tid < cnt) {
            int s = g_srcl[base + tid];
            ssrc[tid] = s;
            float4 als = *(const float4*)&g_als1[s * NH];
            float e0 = __expf(lrelu(als.x + aldv.x));
            float e1 = __expf(lrelu(als.y + aldv.y));
            float e2 = __expf(lrelu(als.z + aldv.z));
            float e3 = __expf(lrelu(als.w + aldv.w));
            salpha[tid * 4 + 0] = e0; salpha[tid * 4 + 1] = e1;
            salpha[tid * 4 + 2] = e2; salpha[tid * 4 + 3] = e3;
            p0 += e0; p1 += e1; p2 += e2; p3 += e3;
        }
        __syncthreads();
        int j = slot;
        for (; j + 4 < cnt; j += 8) {
            float a0 = salpha[j * 4 + head];
            float a1 = salpha[(j + 4) * 4 + head];
            int s0 = ssrc[j], s1 = ssrc[j + 4];
            float4 h0 = *((const float4*)(g_h1 + (size_t)s0 * HC) + ch4);
            float4 h1 = *((const float4*)(g_h1 + (size_t)s1 * HC) + ch4);
            acc.x = fmaf(a0, h0.x, acc.x); acc.y = fmaf(a0, h0.y, acc.y);
            acc.z = fmaf(a0, h0.z, acc.z); acc.w = fmaf(a0, h0.w, acc.w);
            acc.x = fmaf(a1, h1.x, acc.x); acc.y = fmaf(a1, h1.y, acc.y);
            acc.z = fmaf(a1, h1.z, acc.z); acc.w = fmaf(a1, h1.w, acc.w);
        }
        for (; j < cnt; j += 4) {
            float a = salpha[j * 4 + head];
            int s = ssrc[j];
            float4 h = *((const float4*)(g_h1 + (size_t)s * HC) + ch4);
            acc.x = fmaf(a, h.x, acc.x);
            acc.y = fmaf(a, h.y, acc.y);
            acc.z = fmaf(a, h.z, acc.z);
            acc.w = fmaf(a, h.w, acc.w);
        }
    }
    #pragma unroll
    for (int off = 16; off; off >>= 1) {
        p0 += __shfl_down_sync(0xffffffffu, p0, off);
        p1 += __shfl_down_sync(0xffffffffu, p1, off);
        p2 += __shfl_down_sync(0xffffffffu, p2, off);
        p3 += __shfl_down_sync(0xffffffffu, p3, off);
    }
    if ((tid & 31) == 0) {
        atomicAdd(&sden[0], p0);
        atomicAdd(&sden[1], p1);
        atomicAdd(&sden[2], p2);
        atomicAdd(&sden[3], p3);
    }
    sacc[slot * 64 + ch4] = acc;
    __syncthreads();
    if (tid < 64) {
        float4 a0 = sacc[tid], a1 = sacc[64 + tid], a2 = sacc[128 + tid], a3 = sacc[192 + tid];
        float rd = 1.f / sden[tid >> 4];
        int ch = tid * 4;
        float4 bb = *(const float4*)(b1 + ch);
        float4 r;
        r.x = fmaxf((a0.x + a1.x + a2.x + a3.x) * rd + bb.x, 0.f);
        r.y = fmaxf((a0.y + a1.y + a2.y + a3.y) * rd + bb.y, 0.f);
        r.z = fmaxf((a0.z + a1.z + a2.z + a3.z) * rd + bb.z, 0.f);
        r.w = fmaxf((a0.w + a1.w + a2.w + a3.w) * rd + bb.w, 0.f);
        uint2 hh, ll;
        split4(r, hh, ll);
        *(uint2*)(g_a1h + (size_t)d * HC + ch) = hh;
        *(uint2*)(g_a1l + (size_t)d * HC + ch) = ll;
    }
}

// ---------------- layer 2 single-pass agg + log_softmax ----------------------
__global__ void agg2_final(const float* __restrict__ b2, float* __restrict__ out) {
    int n = blockIdx.x * 8 + (threadIdx.x >> 5);
    if (n >= Nn) return;
    int lane = threadIdx.x & 31;
    int start = g_rowptr[n], end = g_rowptr[n + 1];
    float ald = g_ald2[n];

    float den = 0.f, acc0 = 0.f, acc1 = 0.f;
    for (int base = start; base < end; base += 32) {
        int i = base + lane;
        int s = 0; float e = 0.f;
        if (i < end) {
            s = g_srcl[i];
            e = __expf(lrelu(g_als2[s] + ald));
        }
        den += e;
        int cnt = min(32, end - base);
        for (int j = 0; j < cnt; j++) {
            int   sj = __shfl_sync(0xffffffffu, s, j);
            float ej = __shfl_sync(0xffffffffu, e, j);
            acc0 = fmaf(ej, g_h2[sj * OC + lane], acc0);
            if (lane < 8) acc1 = fmaf(ej, g_h2[sj * OC + 32 + lane], acc1);
        }
    }
    #pragma unroll
    for (int off = 16; off; off >>= 1)
        den += __shfl_xor_sync(0xffffffffu, den, off);
    float rden = 1.f / (den + 1e-16f);

    float v0 = acc0 * rden + b2[lane];
    float v1 = (lane < 8) ? (acc1 * rden + b2[32 + lane]) : -3.402823466e38f;
    float mx = fmaxf(v0, v1);
    #pragma unroll
    for (int off = 16; off; off >>= 1)
        mx = fmaxf(mx, __shfl_xor_sync(0xffffffffu, mx, off));
    float se = expf(v0 - mx) + ((lane < 8) ? expf(v1 - mx) : 0.f);
    #pragma unroll
    for (int off = 16; off; off >>= 1)
        se += __shfl_xor_sync(0xffffffffu, se, off);
    float lse = mx + logf(se);
    out[n * OC + lane] = v0 - lse;
    if (lane < 8) out[n * OC + 32 + lane] = v1 - lse;
}

// ---------------- launch -----------------------------------------------------
extern "C" void kernel_launch(void* const* d_in, const int* in_sizes, int n_in,
                              void* d_out, int out_size) {
    const float* x      = (const float*)d_in[0];
    const int*   ei     = (const int*)d_in[1];
    const float* W1     = (const float*)d_in[2];
    const float* a_src1 = (const float*)d_in[3];
    const float* a_dst1 = (const float*)d_in[4];
    const float* b1     = (const float*)d_in[5];
    const float* W2     = (const float*)d_in[6];
    const float* a_src2 = (const float*)d_in[7];
    const float* a_dst2 = (const float*)d_in[8];
    const float* b2     = (const float*)d_in[9];
    float* out = (float*)d_out;

    cudaFuncSetAttribute(gemm1_mma, cudaFuncAttributeMaxDynamicSharedMemorySize, G1_SMEM);
    cudaFuncSetAttribute(gemm2_mma, cudaFuncAttributeMaxDynamicSharedMemorySize, G2_SMEM);

    convert_w<<<(INC * HC + 64 * INC + 255) / 256, 256>>>(W1, W2);        // 1 (+init)
    gemm1_mma<<<MTILES * 2 + HBLK, 512, G1_SMEM>>>(x, ei, a_src1, a_dst1); // 2 (+hist)
    scan_part<<<NB, 256>>>();                                              // 3
    scan_add2<<<NB, 256>>>();                                              // 4
    fill_kernel<<<(Ee / 4 + Nn + 255) / 256, 256>>>(ei);                   // 5
    agg1_kernel<<<Nn, 256>>>(b1);                                          // 6
    gemm2_mma<<<MTILES, 512, G2_SMEM>>>(a_src2, a_dst2);                   // 7
    agg2_final<<<(Nn + 7) / 8, 256>>>(b2, out);                            // 8
}